// round 1
// baseline (speedup 1.0000x reference)
#include <cuda_runtime.h>
#include <cuda_bf16.h>
#include <math.h>

// ---------------- problem constants (fixed by setup_inputs) ----------------
#define NN    12032      // total nodes
#define DMODEL 512
#define BGR   16         // graphs
#define SEQ   256        // conditioning length
#define NH    8
#define DH    64
#define LMAX  992
#define LATD  768
#define ROWS_Q  (BGR*LMAX)   // 15872
#define ROWS_KV (BGR*SEQ)    // 4096

// ---------------- scratch (static device allocations are allowed) ----------
__device__ float g_dense[ROWS_Q*DMODEL];
__device__ float g_qh   [ROWS_Q*DMODEL];
__device__ float g_ctx  [ROWS_Q*DMODEL];
__device__ float g_y    [ROWS_Q*DMODEL];
__device__ float g_x1   [ROWS_Q*DMODEL];
__device__ float g_h    [ROWS_Q*DMODEL];
__device__ float g_kh   [ROWS_KV*DMODEL];
__device__ float g_vh   [ROWS_KV*DMODEL];
__device__ float g_Wq2  [DMODEL*DMODEL];
__device__ float g_Wk2  [LATD*DMODEL];
__device__ float g_Wv2  [LATD*DMODEL];
__device__ float g_bq2  [DMODEL];
__device__ float g_bk2  [DMODEL];
__device__ float g_bv2  [DMODEL];
__device__ int   g_starts[BGR];

// ---------------- small helpers ----------------
__global__ void zero_kernel(float* p, int n) {
    int i = blockIdx.x*blockDim.x + threadIdx.x;
    int stride = gridDim.x*blockDim.x;
    for (; i < n; i += stride) p[i] = 0.f;
}

__global__ void find_starts(const int* __restrict__ gb, int* starts, int n) {
    int i = blockIdx.x*blockDim.x + threadIdx.x;
    if (i < n) {
        if (i == 0 || gb[i] != gb[i-1]) starts[gb[i]] = i;
    }
}

// one block per node, 128 threads * float4 = 512 floats
__global__ __launch_bounds__(128) void scatter_kernel(
    const float* __restrict__ nodes, const int* __restrict__ gb,
    const int* __restrict__ starts, float* __restrict__ dense)
{
    int i = blockIdx.x;
    int b = gb[i];
    int p = i - starts[b];
    const float4* src = (const float4*)(nodes + (size_t)i*DMODEL);
    float4* dst = (float4*)(dense + ((size_t)b*LMAX + p)*DMODEL);
    dst[threadIdx.x] = src[threadIdx.x];
}

__global__ __launch_bounds__(128) void gather_kernel(
    const float* __restrict__ x, const int* __restrict__ gb,
    const int* __restrict__ starts, float* __restrict__ out)
{
    int i = blockIdx.x;
    int b = gb[i];
    int p = i - starts[b];
    const float4* src = (const float4*)(x + ((size_t)b*LMAX + p)*DMODEL);
    float4* dst = (float4*)(out + (size_t)i*DMODEL);
    dst[threadIdx.x] = src[threadIdx.x];
}

// out[j] = add_b[j] + sum_i bin[i]*W[i*512+j]
__global__ void bias_combine(const float* __restrict__ bin,
                             const float* __restrict__ W,
                             const float* __restrict__ add_b,
                             float* __restrict__ out)
{
    int j = blockIdx.x*blockDim.x + threadIdx.x;
    if (j < DMODEL) {
        float a = add_b[j];
        for (int i = 0; i < DMODEL; i++) a += bin[i]*W[i*DMODEL + j];
        out[j] = a;
    }
}

// ---------------- SGEMM 128x128x8, 256 threads, 8x8 microtile ----------------
// MODE 0: C = A@B + bias            (bias may be null)
// MODE 1: C = A@B + bias + Dm
// MODE 2: C = leaky_relu(A@B+bias) + Dm
template<int MODE>
__global__ __launch_bounds__(256) void sgemm_ep(
    const float* __restrict__ A, const float* __restrict__ B,
    const float* __restrict__ bias, const float* __restrict__ Dm,
    float* __restrict__ C, int M, int N, int K)
{
    __shared__ float As[8][128];
    __shared__ float Bs[8][128];
    int tid = threadIdx.x;
    int tx = tid & 15, ty = tid >> 4;
    int row0 = blockIdx.y*128 + ty*8;
    int col0 = blockIdx.x*128 + tx*8;
    float acc[8][8] = {};
    int ar = tid >> 1;            // 0..127
    int ac = (tid & 1)*4;         // 0 or 4
    int br = tid >> 5;            // 0..7
    int bc = (tid & 31)*4;        // 0..124
    const float* Ag = A + ((size_t)blockIdx.y*128 + ar)*K + ac;
    const float* Bg = B + (size_t)br*N + blockIdx.x*128 + bc;
    for (int kt = 0; kt < K; kt += 8) {
        float4 av = *(const float4*)(Ag + kt);
        float4 bv = *(const float4*)(Bg + (size_t)kt*N);
        As[ac+0][ar] = av.x; As[ac+1][ar] = av.y;
        As[ac+2][ar] = av.z; As[ac+3][ar] = av.w;
        *(float4*)&Bs[br][bc] = bv;
        __syncthreads();
        #pragma unroll
        for (int k = 0; k < 8; k++) {
            float a[8], b[8];
            *(float4*)(a)   = *(const float4*)&As[k][ty*8];
            *(float4*)(a+4) = *(const float4*)&As[k][ty*8+4];
            *(float4*)(b)   = *(const float4*)&Bs[k][tx*8];
            *(float4*)(b+4) = *(const float4*)&Bs[k][tx*8+4];
            #pragma unroll
            for (int i = 0; i < 8; i++)
                #pragma unroll
                for (int j = 0; j < 8; j++)
                    acc[i][j] += a[i]*b[j];
        }
        __syncthreads();
    }
    #pragma unroll
    for (int i = 0; i < 8; i++) {
        int r = row0 + i;
        size_t base = (size_t)r*N + col0;
        #pragma unroll
        for (int j = 0; j < 8; j++) {
            float v = acc[i][j];
            if (bias) v += bias[col0 + j];
            if (MODE == 1) v += Dm[base + j];
            if (MODE == 2) {
                v = (v > 0.f) ? v : 0.01f*v;
                v += Dm[base + j];
            }
            C[base + j] = v;
        }
    }
}

// ---------------- attention: per (graph, 32-row tile), loop heads -----------
// smem layout (floats):
//  sK   [256*68]  (stride 68 for float4-aligned padded rows)
//  sV   [256*64]
//  sQ   [32*64]
//  sP   [32*256]
//  sAv  [32*256]
//  sMask[256] (int)
#define ATT_SMEM ((256*68 + 256*64 + 32*64 + 32*256 + 32*256)*4 + 256*4)

__global__ __launch_bounds__(1024, 1) void attn_kernel(
    const float* __restrict__ qh, const float* __restrict__ kh,
    const float* __restrict__ vh, const int* __restrict__ maskp,
    float* __restrict__ ctx, float* __restrict__ av_out)
{
    extern __shared__ float sm[];
    float* sK  = sm;
    float* sV  = sK + 256*68;
    float* sQ  = sV + 256*64;
    float* sP  = sQ + 32*64;
    float* sAv = sP + 32*256;
    int*   sMask = (int*)(sAv + 32*256);

    int b = blockIdx.y;
    int lt = blockIdx.x;
    int tid = threadIdx.x;
    int warp = tid >> 5, lane = tid & 31;
    int l = lt*32 + warp;                     // row within [0,992)

    for (int i = tid; i < 32*256; i += 1024) sAv[i] = 0.f;
    if (tid < 256) sMask[tid] = maskp[b*SEQ + tid];
    __syncthreads();

    for (int h = 0; h < NH; h++) {
        // load K,V head slices
        for (int idx = tid; idx < 256*64; idx += 1024) {
            int s = idx >> 6, d = idx & 63;
            size_t g = ((size_t)(b*SEQ + s))*DMODEL + h*DH + d;
            sK[s*68 + d] = kh[g];
            sV[s*64 + d] = vh[g];
        }
        // load Q rows (warp-per-row)
        {
            size_t g = ((size_t)(b*LMAX + l))*DMODEL + h*DH;
            sQ[warp*64 + lane]      = qh[g + lane];
            sQ[warp*64 + 32 + lane] = qh[g + 32 + lane];
        }
        __syncthreads();

        // scores: each lane handles 8 s-values (s = j*32 + lane)
        float sc[8];
        #pragma unroll
        for (int j = 0; j < 8; j++) sc[j] = 0.f;
        const float4* q4 = (const float4*)(sQ + warp*64);
        #pragma unroll 4
        for (int d4 = 0; d4 < 16; d4++) {
            float4 qv = q4[d4];
            #pragma unroll
            for (int j = 0; j < 8; j++) {
                int s = j*32 + lane;
                float4 kv = *(const float4*)(sK + s*68 + d4*4);
                sc[j] += qv.x*kv.x + qv.y*kv.y + qv.z*kv.z + qv.w*kv.w;
            }
        }
        float m = -INFINITY;
        #pragma unroll
        for (int j = 0; j < 8; j++) {
            int s = j*32 + lane;
            sc[j] = sMask[s] ? -INFINITY : sc[j]*0.125f;  // 1/sqrt(64)
            m = fmaxf(m, sc[j]);
        }
        #pragma unroll
        for (int o = 16; o > 0; o >>= 1) m = fmaxf(m, __shfl_xor_sync(0xffffffffu, m, o));
        float sum = 0.f;
        #pragma unroll
        for (int j = 0; j < 8; j++) { sc[j] = expf(sc[j] - m); sum += sc[j]; }
        #pragma unroll
        for (int o = 16; o > 0; o >>= 1) sum += __shfl_xor_sync(0xffffffffu, sum, o);
        float inv = 1.f/sum;
        #pragma unroll
        for (int j = 0; j < 8; j++) {
            int s = j*32 + lane;
            float p = sc[j]*inv;
            sP[warp*256 + s] = p;
            sAv[warp*256 + s] += p*(1.f/NH);
        }
        __syncwarp();

        // ctx: lane owns 2 dims (d = 2*lane, 2*lane+1)
        float2 acc = make_float2(0.f, 0.f);
        const float2* V2 = (const float2*)sV;
        const float4* P4 = (const float4*)(sP + warp*256);
        #pragma unroll 4
        for (int s4 = 0; s4 < 64; s4++) {
            float4 pv = P4[s4];
            int s = s4*4;
            float2 v0 = V2[(s+0)*32 + lane];
            float2 v1 = V2[(s+1)*32 + lane];
            float2 v2 = V2[(s+2)*32 + lane];
            float2 v3 = V2[(s+3)*32 + lane];
            acc.x += pv.x*v0.x + pv.y*v1.x + pv.z*v2.x + pv.w*v3.x;
            acc.y += pv.x*v0.y + pv.y*v1.y + pv.z*v2.y + pv.w*v3.y;
        }
        ((float2*)(ctx + ((size_t)(b*LMAX + l))*DMODEL + h*DH))[lane] = acc;
        __syncthreads();
    }

    // write head-averaged attention [B, LMAX, SEQ]
    for (int i = tid; i < 32*256; i += 1024) {
        int r = i >> 8, s = i & 255;
        av_out[((size_t)(b*LMAX) + lt*32 + r)*SEQ + s] = sAv[i];
    }
}

// ---------------- LayerNorm: block per row (512 cols, 128 threads) ----------
__global__ __launch_bounds__(128) void ln_kernel(
    const float* __restrict__ x, const float* __restrict__ g,
    const float* __restrict__ bb, float* __restrict__ y)
{
    __shared__ float ws[4], wss[4];
    int r = blockIdx.x;
    int tid = threadIdx.x;
    const float4* xr = (const float4*)(x + (size_t)r*DMODEL);
    float4 v = xr[tid];
    float s  = v.x + v.y + v.z + v.w;
    float ss = v.x*v.x + v.y*v.y + v.z*v.z + v.w*v.w;
    #pragma unroll
    for (int o = 16; o > 0; o >>= 1) {
        s  += __shfl_xor_sync(0xffffffffu, s,  o);
        ss += __shfl_xor_sync(0xffffffffu, ss, o);
    }
    int warp = tid >> 5, lane = tid & 31;
    if (lane == 0) { ws[warp] = s; wss[warp] = ss; }
    __syncthreads();
    float S  = ws[0] + ws[1] + ws[2] + ws[3];
    float SS = wss[0] + wss[1] + wss[2] + wss[3];
    float mean = S * (1.f/DMODEL);
    float var  = SS * (1.f/DMODEL) - mean*mean;
    float rstd = rsqrtf(var + 1e-5f);
    float4 gg = ((const float4*)g)[tid];
    float4 b4 = ((const float4*)bb)[tid];
    float4 o4;
    o4.x = (v.x - mean)*rstd*gg.x + b4.x;
    o4.y = (v.y - mean)*rstd*gg.y + b4.y;
    o4.z = (v.z - mean)*rstd*gg.z + b4.z;
    o4.w = (v.w - mean)*rstd*gg.w + b4.w;
    ((float4*)(y + (size_t)r*DMODEL))[tid] = o4;
}

// ---------------- launch ----------------
extern "C" void kernel_launch(void* const* d_in, const int* in_sizes, int n_in,
                              void* d_out, int out_size)
{
    // input mapping; handle harness with/without the two scalar inputs
    int off = (n_in >= 22) ? 0 : 2;
    const float* nodes  = (const float*)d_in[0];
    const int*   gb     = (const int*)  d_in[1];
    const float* cond   = (const float*)d_in[2];
    const int*   maskp  = (const int*)  d_in[3];   // nonzero test works for i32 & f32
    const float* Wq     = (const float*)d_in[6-off];
    const float* bq     = (const float*)d_in[7-off];
    const float* Wk     = (const float*)d_in[8-off];
    const float* bk     = (const float*)d_in[9-off];
    const float* Wv     = (const float*)d_in[10-off];
    const float* bv     = (const float*)d_in[11-off];
    const float* in_w   = (const float*)d_in[12-off];
    const float* in_b   = (const float*)d_in[13-off];
    const float* Wo     = (const float*)d_in[14-off];
    const float* bo     = (const float*)d_in[15-off];
    const float* ln1g   = (const float*)d_in[16-off];
    const float* ln1b   = (const float*)d_in[17-off];
    const float* W1     = (const float*)d_in[18-off];
    const float* b1     = (const float*)d_in[19-off];
    const float* ln2g   = (const float*)d_in[20-off];
    const float* ln2b   = (const float*)d_in[21-off];
    float* out = (float*)d_out;
    float* av_out = out + (size_t)NN*DMODEL;

    // resolve scratch symbol addresses
    float *p_dense, *p_qh, *p_kh, *p_vh, *p_ctx, *p_y, *p_x1, *p_h;
    float *p_Wq2, *p_Wk2, *p_Wv2, *p_bq2, *p_bk2, *p_bv2;
    int *p_starts;
    cudaGetSymbolAddress((void**)&p_dense, g_dense);
    cudaGetSymbolAddress((void**)&p_qh, g_qh);
    cudaGetSymbolAddress((void**)&p_kh, g_kh);
    cudaGetSymbolAddress((void**)&p_vh, g_vh);
    cudaGetSymbolAddress((void**)&p_ctx, g_ctx);
    cudaGetSymbolAddress((void**)&p_y, g_y);
    cudaGetSymbolAddress((void**)&p_x1, g_x1);
    cudaGetSymbolAddress((void**)&p_h, g_h);
    cudaGetSymbolAddress((void**)&p_Wq2, g_Wq2);
    cudaGetSymbolAddress((void**)&p_Wk2, g_Wk2);
    cudaGetSymbolAddress((void**)&p_Wv2, g_Wv2);
    cudaGetSymbolAddress((void**)&p_bq2, g_bq2);
    cudaGetSymbolAddress((void**)&p_bk2, g_bk2);
    cudaGetSymbolAddress((void**)&p_bv2, g_bv2);
    cudaGetSymbolAddress((void**)&p_starts, g_starts);

    const float* in_w0 = in_w;
    const float* in_w1 = in_w + DMODEL*DMODEL;
    const float* in_w2 = in_w + 2*DMODEL*DMODEL;
    const float* in_b0 = in_b;
    const float* in_b1 = in_b + DMODEL;
    const float* in_b2 = in_b + 2*DMODEL;

    // 1) ragged bookkeeping + dense padding
    find_starts<<<(NN+255)/256, 256>>>(gb, p_starts, NN);
    zero_kernel<<<1024, 256>>>(p_dense, ROWS_Q*DMODEL);
    scatter_kernel<<<NN, 128>>>(nodes, gb, p_starts, p_dense);

    // 2) fold projection pairs: W2 = W @ in_w, b2 = b @ in_w + in_b
    sgemm_ep<0><<<dim3(4,4), 256>>>(Wq, in_w0, nullptr, nullptr, p_Wq2, DMODEL, DMODEL, DMODEL);
    sgemm_ep<0><<<dim3(4,6), 256>>>(Wk, in_w1, nullptr, nullptr, p_Wk2, LATD, DMODEL, DMODEL);
    sgemm_ep<0><<<dim3(4,6), 256>>>(Wv, in_w2, nullptr, nullptr, p_Wv2, LATD, DMODEL, DMODEL);
    bias_combine<<<1, 512>>>(bq, in_w0, in_b0, p_bq2);
    bias_combine<<<1, 512>>>(bk, in_w1, in_b1, p_bk2);
    bias_combine<<<1, 512>>>(bv, in_w2, in_b2, p_bv2);

    // 3) projections
    sgemm_ep<0><<<dim3(4,124), 256>>>(p_dense, p_Wq2, p_bq2, nullptr, p_qh, ROWS_Q, DMODEL, DMODEL);
    sgemm_ep<0><<<dim3(4,32),  256>>>(cond,    p_Wk2, p_bk2, nullptr, p_kh, ROWS_KV, DMODEL, LATD);
    sgemm_ep<0><<<dim3(4,32),  256>>>(cond,    p_Wv2, p_bv2, nullptr, p_vh, ROWS_KV, DMODEL, LATD);

    // 4) attention (writes ctx and head-averaged attn)
    cudaFuncSetAttribute(attn_kernel, cudaFuncAttributeMaxDynamicSharedMemorySize, ATT_SMEM);
    attn_kernel<<<dim3(LMAX/32, BGR), 1024, ATT_SMEM>>>(p_qh, p_kh, p_vh, maskp, p_ctx, av_out);

    // 5) out proj + residual, LN1, FFN (+leaky_relu + residual), LN2
    sgemm_ep<1><<<dim3(4,124), 256>>>(p_ctx, Wo, bo, p_dense, p_y, ROWS_Q, DMODEL, DMODEL);
    ln_kernel<<<ROWS_Q, 128>>>(p_y, ln1g, ln1b, p_x1);
    sgemm_ep<2><<<dim3(4,124), 256>>>(p_x1, W1, b1, p_x1, p_h, ROWS_Q, DMODEL, DMODEL);
    ln_kernel<<<ROWS_Q, 128>>>(p_h, ln2g, ln2b, p_y);

    // 6) ragged gather to node_out
    gather_kernel<<<NN, 128>>>(p_y, gb, p_starts, out);
}

// round 2
// speedup vs baseline: 1.5576x; 1.5576x over previous
#include <cuda_runtime.h>
#include <cuda_bf16.h>
#include <math.h>

// ---------------- problem constants (fixed by setup_inputs) ----------------
#define NN    12032      // total nodes
#define DMODEL 512
#define BGR   16         // graphs
#define SEQ   256        // conditioning length
#define NH    8
#define DH    64
#define LMAX  992
#define LATD  768
#define ROWS_Q  (BGR*LMAX)   // 15872
#define ROWS_KV (BGR*SEQ)    // 4096

// ---------------- scratch ----------
__device__ float g_dense[ROWS_Q*DMODEL];
__device__ float g_qh   [ROWS_Q*DMODEL];
__device__ float g_ctx  [ROWS_Q*DMODEL];
__device__ float g_y    [ROWS_Q*DMODEL];
__device__ float g_x1   [ROWS_Q*DMODEL];
__device__ float g_h    [ROWS_Q*DMODEL];
__device__ float g_kh   [ROWS_KV*DMODEL];
__device__ float g_vh   [ROWS_KV*DMODEL];
__device__ float g_Wq2  [DMODEL*DMODEL];
__device__ float g_Wk2  [LATD*DMODEL];
__device__ float g_Wv2  [LATD*DMODEL];
__device__ float g_bq2  [DMODEL];
__device__ float g_bk2  [DMODEL];
__device__ float g_bv2  [DMODEL];
__device__ int   g_starts[BGR];

// ---------------- small helpers ----------------
__global__ void zero_kernel(float* p, int n) {
    int i = blockIdx.x*blockDim.x + threadIdx.x;
    int stride = gridDim.x*blockDim.x;
    for (; i < n; i += stride) p[i] = 0.f;
}

__global__ void find_starts(const int* __restrict__ gb, int* starts, int n) {
    int i = blockIdx.x*blockDim.x + threadIdx.x;
    if (i < n) {
        if (i == 0 || gb[i] != gb[i-1]) starts[gb[i]] = i;
    }
}

__global__ __launch_bounds__(128) void scatter_kernel(
    const float* __restrict__ nodes, const int* __restrict__ gb,
    const int* __restrict__ starts, float* __restrict__ dense)
{
    int i = blockIdx.x;
    int b = gb[i];
    int p = i - starts[b];
    const float4* src = (const float4*)(nodes + (size_t)i*DMODEL);
    float4* dst = (float4*)(dense + ((size_t)b*LMAX + p)*DMODEL);
    dst[threadIdx.x] = src[threadIdx.x];
}

__global__ __launch_bounds__(128) void gather_kernel(
    const float* __restrict__ x, const int* __restrict__ gb,
    const int* __restrict__ starts, float* __restrict__ out)
{
    int i = blockIdx.x;
    int b = gb[i];
    int p = i - starts[b];
    const float4* src = (const float4*)(x + ((size_t)b*LMAX + p)*DMODEL);
    float4* dst = (float4*)(out + (size_t)i*DMODEL);
    dst[threadIdx.x] = src[threadIdx.x];
}

// out[j] = add_b[j] + sum_i bin[i]*W[i*512+j]   (tiny, fp32 exact)
__global__ void bias_combine(const float* __restrict__ bin,
                             const float* __restrict__ W,
                             const float* __restrict__ add_b,
                             float* __restrict__ out)
{
    int j = blockIdx.x*blockDim.x + threadIdx.x;
    if (j < DMODEL) {
        float a = add_b[j];
        for (int i = 0; i < DMODEL; i++) a += bin[i]*W[i*DMODEL + j];
        out[j] = a;
    }
}

// ---------------- TF32 tensor-core GEMM ----------------
// 128x128 block tile, BK=16, 256 threads = 8 warps (4 over M x 2 over N),
// warp tile 32x64 = 2x8 grid of m16n8k8 mma.
// MODE 0: C = A@B + bias (bias may be null)
// MODE 1: C = A@B + bias + Dm
// MODE 2: C = leaky_relu(A@B+bias) + Dm

__device__ __forceinline__ unsigned f2tf32(float x) {
    unsigned y;
    asm("cvt.rna.tf32.f32 %0, %1;" : "=r"(y) : "f"(x));
    return y;
}

__device__ __forceinline__ void mma_tf32(float c[4],
    unsigned a0, unsigned a1, unsigned a2, unsigned a3,
    unsigned b0, unsigned b1)
{
    asm volatile(
        "mma.sync.aligned.m16n8k8.row.col.f32.tf32.tf32.f32 "
        "{%0,%1,%2,%3}, {%4,%5,%6,%7}, {%8,%9}, {%0,%1,%2,%3};"
        : "+f"(c[0]), "+f"(c[1]), "+f"(c[2]), "+f"(c[3])
        : "r"(a0), "r"(a1), "r"(a2), "r"(a3), "r"(b0), "r"(b1));
}

#define SMP 132   // padded row stride

template<int MODE>
__global__ __launch_bounds__(256) void gemm_tf32(
    const float* __restrict__ A, const float* __restrict__ B,
    const float* __restrict__ bias, const float* __restrict__ Dm,
    float* __restrict__ C, int M, int N, int K)
{
    __shared__ unsigned As[16][SMP];   // [k][m]
    __shared__ unsigned Bs[16][SMP];   // [k][n]

    int tid = threadIdx.x;
    int warp = tid >> 5, lane = tid & 31;
    int warp_m = warp & 3, warp_n = warp >> 2;
    int p = lane >> 2, q = lane & 3;
    int blockM = blockIdx.y * 128;
    int blockN = blockIdx.x * 128;

    // global load indices (2 float4 each for A and B per thread)
    int ia0 = tid*2, ia1 = tid*2 + 1;
    int arow0 = ia0 >> 2, akq0 = ia0 & 3;
    int arow1 = ia1 >> 2, akq1 = ia1 & 3;
    int bk0 = ia0 >> 5, bn0 = ia0 & 31;
    int bk1 = ia1 >> 5, bn1 = ia1 & 31;

    const float* Ap0 = A + (size_t)(blockM + arow0)*K + akq0*4;
    const float* Ap1 = A + (size_t)(blockM + arow1)*K + akq1*4;
    const float* Bp0 = B + (size_t)bk0*N + blockN + bn0*4;
    const float* Bp1 = B + (size_t)bk1*N + blockN + bn1*4;

    float acc[2][8][4];
    #pragma unroll
    for (int mt = 0; mt < 2; mt++)
        #pragma unroll
        for (int nt = 0; nt < 8; nt++)
            #pragma unroll
            for (int i = 0; i < 4; i++) acc[mt][nt][i] = 0.f;

    // prologue: load tile 0
    float4 av0 = *(const float4*)(Ap0);
    float4 av1 = *(const float4*)(Ap1);
    float4 bv0 = *(const float4*)(Bp0);
    float4 bv1 = *(const float4*)(Bp1);

    for (int kt = 16; kt <= K; kt += 16) {
        // store current tile to smem
        As[akq0*4+0][arow0] = f2tf32(av0.x);
        As[akq0*4+1][arow0] = f2tf32(av0.y);
        As[akq0*4+2][arow0] = f2tf32(av0.z);
        As[akq0*4+3][arow0] = f2tf32(av0.w);
        As[akq1*4+0][arow1] = f2tf32(av1.x);
        As[akq1*4+1][arow1] = f2tf32(av1.y);
        As[akq1*4+2][arow1] = f2tf32(av1.z);
        As[akq1*4+3][arow1] = f2tf32(av1.w);
        {
            uint4 t0, t1;
            t0.x = f2tf32(bv0.x); t0.y = f2tf32(bv0.y);
            t0.z = f2tf32(bv0.z); t0.w = f2tf32(bv0.w);
            t1.x = f2tf32(bv1.x); t1.y = f2tf32(bv1.y);
            t1.z = f2tf32(bv1.z); t1.w = f2tf32(bv1.w);
            *(uint4*)&Bs[bk0][bn0*4] = t0;
            *(uint4*)&Bs[bk1][bn1*4] = t1;
        }
        __syncthreads();

        // prefetch next tile
        if (kt < K) {
            av0 = *(const float4*)(Ap0 + kt);
            av1 = *(const float4*)(Ap1 + kt);
            bv0 = *(const float4*)(Bp0 + (size_t)kt*N);
            bv1 = *(const float4*)(Bp1 + (size_t)kt*N);
        }

        // compute on current smem tile
        #pragma unroll
        for (int kk = 0; kk < 16; kk += 8) {
            unsigned afr[2][4];
            #pragma unroll
            for (int mt = 0; mt < 2; mt++) {
                int mb = warp_m*32 + mt*16;
                afr[mt][0] = As[kk+q  ][mb + p];
                afr[mt][1] = As[kk+q  ][mb + p + 8];
                afr[mt][2] = As[kk+q+4][mb + p];
                afr[mt][3] = As[kk+q+4][mb + p + 8];
            }
            unsigned bfr[8][2];
            #pragma unroll
            for (int nt = 0; nt < 8; nt++) {
                int nb = warp_n*64 + nt*8;
                bfr[nt][0] = Bs[kk+q  ][nb + p];
                bfr[nt][1] = Bs[kk+q+4][nb + p];
            }
            #pragma unroll
            for (int mt = 0; mt < 2; mt++)
                #pragma unroll
                for (int nt = 0; nt < 8; nt++)
                    mma_tf32(acc[mt][nt], afr[mt][0], afr[mt][1], afr[mt][2], afr[mt][3],
                             bfr[nt][0], bfr[nt][1]);
        }
        __syncthreads();
    }

    // epilogue
    #pragma unroll
    for (int mt = 0; mt < 2; mt++) {
        int r0 = blockM + warp_m*32 + mt*16 + p;
        #pragma unroll
        for (int nt = 0; nt < 8; nt++) {
            int c0 = blockN + warp_n*64 + nt*8 + 2*q;
            float b0 = 0.f, b1 = 0.f;
            if (bias) { b0 = bias[c0]; b1 = bias[c0+1]; }
            float v0 = acc[mt][nt][0] + b0;
            float v1 = acc[mt][nt][1] + b1;
            float v2 = acc[mt][nt][2] + b0;
            float v3 = acc[mt][nt][3] + b1;
            size_t o0 = (size_t)r0*N + c0;
            size_t o1 = (size_t)(r0+8)*N + c0;
            if (MODE == 1) {
                float2 d0 = *(const float2*)(Dm + o0);
                float2 d1 = *(const float2*)(Dm + o1);
                v0 += d0.x; v1 += d0.y; v2 += d1.x; v3 += d1.y;
            }
            if (MODE == 2) {
                v0 = (v0 > 0.f) ? v0 : 0.01f*v0;
                v1 = (v1 > 0.f) ? v1 : 0.01f*v1;
                v2 = (v2 > 0.f) ? v2 : 0.01f*v2;
                v3 = (v3 > 0.f) ? v3 : 0.01f*v3;
                float2 d0 = *(const float2*)(Dm + o0);
                float2 d1 = *(const float2*)(Dm + o1);
                v0 += d0.x; v1 += d0.y; v2 += d1.x; v3 += d1.y;
            }
            *(float2*)(C + o0) = make_float2(v0, v1);
            *(float2*)(C + o1) = make_float2(v2, v3);
        }
    }
}

// ---------------- attention: per (graph, 32-row tile), loop heads -----------
#define ATT_SMEM ((256*68 + 256*64 + 32*64 + 32*256 + 32*256)*4 + 256*4)

__global__ __launch_bounds__(1024, 1) void attn_kernel(
    const float* __restrict__ qh, const float* __restrict__ kh,
    const float* __restrict__ vh, const int* __restrict__ maskp,
    float* __restrict__ ctx, float* __restrict__ av_out)
{
    extern __shared__ float sm[];
    float* sK  = sm;
    float* sV  = sK + 256*68;
    float* sQ  = sV + 256*64;
    float* sP  = sQ + 32*64;
    float* sAv = sP + 32*256;
    int*   sMask = (int*)(sAv + 32*256);

    int b = blockIdx.y;
    int lt = blockIdx.x;
    int tid = threadIdx.x;
    int warp = tid >> 5, lane = tid & 31;
    int l = lt*32 + warp;

    for (int i = tid; i < 32*256; i += 1024) sAv[i] = 0.f;
    if (tid < 256) sMask[tid] = maskp[b*SEQ + tid];
    __syncthreads();

    for (int h = 0; h < NH; h++) {
        for (int idx = tid; idx < 256*64; idx += 1024) {
            int s = idx >> 6, d = idx & 63;
            size_t g = ((size_t)(b*SEQ + s))*DMODEL + h*DH + d;
            sK[s*68 + d] = kh[g];
            sV[s*64 + d] = vh[g];
        }
        {
            size_t g = ((size_t)(b*LMAX + l))*DMODEL + h*DH;
            sQ[warp*64 + lane]      = qh[g + lane];
            sQ[warp*64 + 32 + lane] = qh[g + 32 + lane];
        }
        __syncthreads();

        float sc[8];
        #pragma unroll
        for (int j = 0; j < 8; j++) sc[j] = 0.f;
        const float4* q4 = (const float4*)(sQ + warp*64);
        #pragma unroll 4
        for (int d4 = 0; d4 < 16; d4++) {
            float4 qv = q4[d4];
            #pragma unroll
            for (int j = 0; j < 8; j++) {
                int s = j*32 + lane;
                float4 kv = *(const float4*)(sK + s*68 + d4*4);
                sc[j] += qv.x*kv.x + qv.y*kv.y + qv.z*kv.z + qv.w*kv.w;
            }
        }
        float m = -INFINITY;
        #pragma unroll
        for (int j = 0; j < 8; j++) {
            int s = j*32 + lane;
            sc[j] = sMask[s] ? -INFINITY : sc[j]*0.125f;
            m = fmaxf(m, sc[j]);
        }
        #pragma unroll
        for (int o = 16; o > 0; o >>= 1) m = fmaxf(m, __shfl_xor_sync(0xffffffffu, m, o));
        float sum = 0.f;
        #pragma unroll
        for (int j = 0; j < 8; j++) { sc[j] = expf(sc[j] - m); sum += sc[j]; }
        #pragma unroll
        for (int o = 16; o > 0; o >>= 1) sum += __shfl_xor_sync(0xffffffffu, sum, o);
        float inv = 1.f/sum;
        #pragma unroll
        for (int j = 0; j < 8; j++) {
            int s = j*32 + lane;
            float p = sc[j]*inv;
            sP[warp*256 + s] = p;
            sAv[warp*256 + s] += p*(1.f/NH);
        }
        __syncwarp();

        float2 acc2 = make_float2(0.f, 0.f);
        const float2* V2 = (const float2*)sV;
        const float4* P4 = (const float4*)(sP + warp*256);
        #pragma unroll 4
        for (int s4 = 0; s4 < 64; s4++) {
            float4 pv = P4[s4];
            int s = s4*4;
            float2 v0 = V2[(s+0)*32 + lane];
            float2 v1 = V2[(s+1)*32 + lane];
            float2 v2 = V2[(s+2)*32 + lane];
            float2 v3 = V2[(s+3)*32 + lane];
            acc2.x += pv.x*v0.x + pv.y*v1.x + pv.z*v2.x + pv.w*v3.x;
            acc2.y += pv.x*v0.y + pv.y*v1.y + pv.z*v2.y + pv.w*v3.y;
        }
        ((float2*)(ctx + ((size_t)(b*LMAX + l))*DMODEL + h*DH))[lane] = acc2;
        __syncthreads();
    }

    for (int i = tid; i < 32*256; i += 1024) {
        int r = i >> 8, s = i & 255;
        av_out[((size_t)(b*LMAX) + lt*32 + r)*SEQ + s] = sAv[i];
    }
}

// ---------------- LayerNorm ----------
__global__ __launch_bounds__(128) void ln_kernel(
    const float* __restrict__ x, const float* __restrict__ g,
    const float* __restrict__ bb, float* __restrict__ y)
{
    __shared__ float ws[4], wss[4];
    int r = blockIdx.x;
    int tid = threadIdx.x;
    const float4* xr = (const float4*)(x + (size_t)r*DMODEL);
    float4 v = xr[tid];
    float s  = v.x + v.y + v.z + v.w;
    float ss = v.x*v.x + v.y*v.y + v.z*v.z + v.w*v.w;
    #pragma unroll
    for (int o = 16; o > 0; o >>= 1) {
        s  += __shfl_xor_sync(0xffffffffu, s,  o);
        ss += __shfl_xor_sync(0xffffffffu, ss, o);
    }
    int warp = tid >> 5, lane = tid & 31;
    if (lane == 0) { ws[warp] = s; wss[warp] = ss; }
    __syncthreads();
    float S  = ws[0] + ws[1] + ws[2] + ws[3];
    float SS = wss[0] + wss[1] + wss[2] + wss[3];
    float mean = S * (1.f/DMODEL);
    float var  = SS * (1.f/DMODEL) - mean*mean;
    float rstd = rsqrtf(var + 1e-5f);
    float4 gg = ((const float4*)g)[tid];
    float4 b4 = ((const float4*)bb)[tid];
    float4 o4;
    o4.x = (v.x - mean)*rstd*gg.x + b4.x;
    o4.y = (v.y - mean)*rstd*gg.y + b4.y;
    o4.z = (v.z - mean)*rstd*gg.z + b4.z;
    o4.w = (v.w - mean)*rstd*gg.w + b4.w;
    ((float4*)(y + (size_t)r*DMODEL))[tid] = o4;
}

// ---------------- launch ----------------
extern "C" void kernel_launch(void* const* d_in, const int* in_sizes, int n_in,
                              void* d_out, int out_size)
{
    int off = (n_in >= 22) ? 0 : 2;
    const float* nodes  = (const float*)d_in[0];
    const int*   gb     = (const int*)  d_in[1];
    const float* cond   = (const float*)d_in[2];
    const int*   maskp  = (const int*)  d_in[3];
    const float* Wq     = (const float*)d_in[6-off];
    const float* bq     = (const float*)d_in[7-off];
    const float* Wk     = (const float*)d_in[8-off];
    const float* bk     = (const float*)d_in[9-off];
    const float* Wv     = (const float*)d_in[10-off];
    const float* bv     = (const float*)d_in[11-off];
    const float* in_w   = (const float*)d_in[12-off];
    const float* in_b   = (const float*)d_in[13-off];
    const float* Wo     = (const float*)d_in[14-off];
    const float* bo     = (const float*)d_in[15-off];
    const float* ln1g   = (const float*)d_in[16-off];
    const float* ln1b   = (const float*)d_in[17-off];
    const float* W1     = (const float*)d_in[18-off];
    const float* b1     = (const float*)d_in[19-off];
    const float* ln2g   = (const float*)d_in[20-off];
    const float* ln2b   = (const float*)d_in[21-off];
    float* out = (float*)d_out;
    float* av_out = out + (size_t)NN*DMODEL;

    float *p_dense, *p_qh, *p_kh, *p_vh, *p_ctx, *p_y, *p_x1, *p_h;
    float *p_Wq2, *p_Wk2, *p_Wv2, *p_bq2, *p_bk2, *p_bv2;
    int *p_starts;
    cudaGetSymbolAddress((void**)&p_dense, g_dense);
    cudaGetSymbolAddress((void**)&p_qh, g_qh);
    cudaGetSymbolAddress((void**)&p_kh, g_kh);
    cudaGetSymbolAddress((void**)&p_vh, g_vh);
    cudaGetSymbolAddress((void**)&p_ctx, g_ctx);
    cudaGetSymbolAddress((void**)&p_y, g_y);
    cudaGetSymbolAddress((void**)&p_x1, g_x1);
    cudaGetSymbolAddress((void**)&p_h, g_h);
    cudaGetSymbolAddress((void**)&p_Wq2, g_Wq2);
    cudaGetSymbolAddress((void**)&p_Wk2, g_Wk2);
    cudaGetSymbolAddress((void**)&p_Wv2, g_Wv2);
    cudaGetSymbolAddress((void**)&p_bq2, g_bq2);
    cudaGetSymbolAddress((void**)&p_bk2, g_bk2);
    cudaGetSymbolAddress((void**)&p_bv2, g_bv2);
    cudaGetSymbolAddress((void**)&p_starts, g_starts);

    const float* in_w0 = in_w;
    const float* in_w1 = in_w + DMODEL*DMODEL;
    const float* in_w2 = in_w + 2*DMODEL*DMODEL;
    const float* in_b0 = in_b;
    const float* in_b1 = in_b + DMODEL;
    const float* in_b2 = in_b + 2*DMODEL;

    // 1) ragged bookkeeping + dense padding
    find_starts<<<(NN+255)/256, 256>>>(gb, p_starts, NN);
    zero_kernel<<<1024, 256>>>(p_dense, ROWS_Q*DMODEL);
    scatter_kernel<<<NN, 128>>>(nodes, gb, p_starts, p_dense);

    // 2) fold projection pairs: W2 = W @ in_w, b2 = b @ in_w + in_b
    gemm_tf32<0><<<dim3(4,4), 256>>>(Wq, in_w0, nullptr, nullptr, p_Wq2, DMODEL, DMODEL, DMODEL);
    gemm_tf32<0><<<dim3(4,6), 256>>>(Wk, in_w1, nullptr, nullptr, p_Wk2, LATD, DMODEL, DMODEL);
    gemm_tf32<0><<<dim3(4,6), 256>>>(Wv, in_w2, nullptr, nullptr, p_Wv2, LATD, DMODEL, DMODEL);
    bias_combine<<<1, 512>>>(bq, in_w0, in_b0, p_bq2);
    bias_combine<<<1, 512>>>(bk, in_w1, in_b1, p_bk2);
    bias_combine<<<1, 512>>>(bv, in_w2, in_b2, p_bv2);

    // 3) projections
    gemm_tf32<0><<<dim3(4,124), 256>>>(p_dense, p_Wq2, p_bq2, nullptr, p_qh, ROWS_Q, DMODEL, DMODEL);
    gemm_tf32<0><<<dim3(4,32),  256>>>(cond,    p_Wk2, p_bk2, nullptr, p_kh, ROWS_KV, DMODEL, LATD);
    gemm_tf32<0><<<dim3(4,32),  256>>>(cond,    p_Wv2, p_bv2, nullptr, p_vh, ROWS_KV, DMODEL, LATD);

    // 4) attention
    cudaFuncSetAttribute(attn_kernel, cudaFuncAttributeMaxDynamicSharedMemorySize, ATT_SMEM);
    attn_kernel<<<dim3(LMAX/32, BGR), 1024, ATT_SMEM>>>(p_qh, p_kh, p_vh, maskp, p_ctx, av_out);

    // 5) out proj + residual, LN1, FFN, LN2
    gemm_tf32<1><<<dim3(4,124), 256>>>(p_ctx, Wo, bo, p_dense, p_y, ROWS_Q, DMODEL, DMODEL);
    ln_kernel<<<ROWS_Q, 128>>>(p_y, ln1g, ln1b, p_x1);
    gemm_tf32<2><<<dim3(4,124), 256>>>(p_x1, W1, b1, p_x1, p_h, ROWS_Q, DMODEL, DMODEL);
    ln_kernel<<<ROWS_Q, 128>>>(p_h, ln2g, ln2b, p_y);

    // 6) ragged gather
    gather_kernel<<<NN, 128>>>(p_y, gb, p_starts, out);
}

// round 3
// speedup vs baseline: 3.2608x; 2.0936x over previous
#include <cuda_runtime.h>
#include <cuda_bf16.h>
#include <math.h>

// ---------------- problem constants ----------------
#define NN    12032
#define DMODEL 512
#define BGR   16
#define SEQ   256
#define NH    8
#define DH    64
#define LMAX  992
#define LATD  768
#define ROWS_Q  (BGR*LMAX)   // 15872
#define ROWS_KV (BGR*SEQ)    // 4096

// ---------------- scratch ----------
__device__ float g_dense[ROWS_Q*DMODEL];
__device__ float g_qh   [ROWS_Q*DMODEL];
__device__ float g_ctx  [ROWS_Q*DMODEL];
__device__ float g_y    [ROWS_Q*DMODEL];
__device__ float g_x1   [ROWS_Q*DMODEL];
__device__ float g_h    [ROWS_Q*DMODEL];
__device__ float g_kh   [ROWS_KV*DMODEL];
__device__ float g_vh   [ROWS_KV*DMODEL];
__device__ float g_Wq2  [DMODEL*DMODEL];
__device__ float g_Wk2  [LATD*DMODEL];
__device__ float g_Wv2  [LATD*DMODEL];
__device__ float g_Wo2  [DMODEL*DMODEL];
__device__ float g_W12  [DMODEL*DMODEL];
__device__ float g_cond [BGR*SEQ*LATD];
__device__ float g_bq2  [DMODEL];
__device__ float g_bk2  [DMODEL];
__device__ float g_bv2  [DMODEL];
__device__ int   g_starts[BGR];

// ---------------- helpers ----------------
__device__ __forceinline__ unsigned f2tf32(float x) {
    unsigned y;
    asm("cvt.rna.tf32.f32 %0, %1;" : "=r"(y) : "f"(x));
    return y;
}
__device__ __forceinline__ float rtf(float x) { return __uint_as_float(f2tf32(x)); }

__device__ __forceinline__ void mma_tf32(float c[4],
    unsigned a0, unsigned a1, unsigned a2, unsigned a3,
    unsigned b0, unsigned b1)
{
    asm volatile(
        "mma.sync.aligned.m16n8k8.row.col.f32.tf32.tf32.f32 "
        "{%0,%1,%2,%3}, {%4,%5,%6,%7}, {%8,%9}, {%0,%1,%2,%3};"
        : "+f"(c[0]), "+f"(c[1]), "+f"(c[2]), "+f"(c[3])
        : "r"(a0), "r"(a1), "r"(a2), "r"(a3), "r"(b0), "r"(b1));
}

#define CP16(dst, src) asm volatile("cp.async.cg.shared.global [%0], [%1], 16;" :: "r"(dst), "l"(src))

__global__ void zero_kernel(float* p, int n) {
    int i = blockIdx.x*blockDim.x + threadIdx.x;
    int stride = gridDim.x*blockDim.x;
    for (; i < n; i += stride) p[i] = 0.f;
}

__global__ void round_copy(const float* __restrict__ src, float* __restrict__ dst, int n4) {
    int i = blockIdx.x*blockDim.x + threadIdx.x;
    int stride = gridDim.x*blockDim.x;
    for (; i < n4; i += stride) {
        float4 v = ((const float4*)src)[i];
        v.x = rtf(v.x); v.y = rtf(v.y); v.z = rtf(v.z); v.w = rtf(v.w);
        ((float4*)dst)[i] = v;
    }
}

__global__ void find_starts(const int* __restrict__ gb, int* starts, int n) {
    int i = blockIdx.x*blockDim.x + threadIdx.x;
    if (i < n) {
        if (i == 0 || gb[i] != gb[i-1]) starts[gb[i]] = i;
    }
}

// scatter with tf32 rounding (dense feeds GEMM A + residual)
__global__ __launch_bounds__(128) void scatter_kernel(
    const float* __restrict__ nodes, const int* __restrict__ gb,
    const int* __restrict__ starts, float* __restrict__ dense)
{
    int i = blockIdx.x;
    int b = gb[i];
    int p = i - starts[b];
    float4 v = ((const float4*)(nodes + (size_t)i*DMODEL))[threadIdx.x];
    v.x = rtf(v.x); v.y = rtf(v.y); v.z = rtf(v.z); v.w = rtf(v.w);
    ((float4*)(dense + ((size_t)b*LMAX + p)*DMODEL))[threadIdx.x] = v;
}

__global__ __launch_bounds__(128) void gather_kernel(
    const float* __restrict__ x, const int* __restrict__ gb,
    const int* __restrict__ starts, float* __restrict__ out)
{
    int i = blockIdx.x;
    int b = gb[i];
    int p = i - starts[b];
    const float4* src = (const float4*)(x + ((size_t)b*LMAX + p)*DMODEL);
    float4* dst = (float4*)(out + (size_t)i*DMODEL);
    dst[threadIdx.x] = src[threadIdx.x];
}

// batched bias combine: out_z[j] = in_b[z][j] + sum_i b_z[i]*in_w[z][i*512+j]
__global__ void bias3(const float* __restrict__ bq, const float* __restrict__ bk,
                      const float* __restrict__ bv, const float* __restrict__ inw,
                      const float* __restrict__ inb,
                      float* __restrict__ oq, float* __restrict__ ok, float* __restrict__ ov)
{
    int z = blockIdx.y;
    const float* bin = (z==0) ? bq : (z==1) ? bk : bv;
    const float* W = inw + (size_t)z*DMODEL*DMODEL;
    const float* ab = inb + z*DMODEL;
    float* out = (z==0) ? oq : (z==1) ? ok : ov;
    int j = threadIdx.x;
    if (j < DMODEL) {
        float a = ab[j];
        for (int i = 0; i < DMODEL; i++) a += bin[i]*W[i*DMODEL + j];
        out[j] = a;
    }
}

// ---------------- fold3: three small weight GEMMs in one launch -------------
// z=0: Wq2 = Wq @ in_w0 (M=512); z=1: Wk2 = Wk @ in_w1 (M=768); z=2: Wv2.
// Register-prefetch path with rna cvt (inputs are raw fp32). Output rounded.
#define SMP 132

__global__ __launch_bounds__(256) void fold3_gemm(
    const float* __restrict__ Wq, const float* __restrict__ Wk,
    const float* __restrict__ Wv, const float* __restrict__ inw,
    float* __restrict__ Cq, float* __restrict__ Ck, float* __restrict__ Cv)
{
    int z = blockIdx.z;
    int M = (z == 0) ? DMODEL : LATD;
    if ((int)blockIdx.y*128 >= M) return;
    const float* A = (z==0) ? Wq : (z==1) ? Wk : Wv;
    const float* B = inw + (size_t)z*DMODEL*DMODEL;
    float* C = (z==0) ? Cq : (z==1) ? Ck : Cv;
    const int N = DMODEL, K = DMODEL;

    __shared__ unsigned As[16][SMP];
    __shared__ unsigned Bs[16][SMP];
    int tid = threadIdx.x;
    int warp = tid >> 5, lane = tid & 31;
    int warp_m = warp & 3, warp_n = warp >> 2;
    int p = lane >> 2, q = lane & 3;
    int blockM = blockIdx.y * 128;
    int blockN = blockIdx.x * 128;

    int ia0 = tid*2, ia1 = tid*2 + 1;
    int arow0 = ia0 >> 2, akq0 = ia0 & 3;
    int arow1 = ia1 >> 2, akq1 = ia1 & 3;
    int bk0 = ia0 >> 5, bn0 = ia0 & 31;
    int bk1 = ia1 >> 5, bn1 = ia1 & 31;

    const float* Ap0 = A + (size_t)(blockM + arow0)*K + akq0*4;
    const float* Ap1 = A + (size_t)(blockM + arow1)*K + akq1*4;
    const float* Bp0 = B + (size_t)bk0*N + blockN + bn0*4;
    const float* Bp1 = B + (size_t)bk1*N + blockN + bn1*4;

    float acc[2][8][4];
    #pragma unroll
    for (int mt = 0; mt < 2; mt++)
        #pragma unroll
        for (int nt = 0; nt < 8; nt++)
            #pragma unroll
            for (int i = 0; i < 4; i++) acc[mt][nt][i] = 0.f;

    float4 av0 = *(const float4*)(Ap0);
    float4 av1 = *(const float4*)(Ap1);
    float4 bv0 = *(const float4*)(Bp0);
    float4 bv1 = *(const float4*)(Bp1);

    for (int kt = 16; kt <= K; kt += 16) {
        As[akq0*4+0][arow0] = f2tf32(av0.x);
        As[akq0*4+1][arow0] = f2tf32(av0.y);
        As[akq0*4+2][arow0] = f2tf32(av0.z);
        As[akq0*4+3][arow0] = f2tf32(av0.w);
        As[akq1*4+0][arow1] = f2tf32(av1.x);
        As[akq1*4+1][arow1] = f2tf32(av1.y);
        As[akq1*4+2][arow1] = f2tf32(av1.z);
        As[akq1*4+3][arow1] = f2tf32(av1.w);
        {
            uint4 t0, t1;
            t0.x = f2tf32(bv0.x); t0.y = f2tf32(bv0.y);
            t0.z = f2tf32(bv0.z); t0.w = f2tf32(bv0.w);
            t1.x = f2tf32(bv1.x); t1.y = f2tf32(bv1.y);
            t1.z = f2tf32(bv1.z); t1.w = f2tf32(bv1.w);
            *(uint4*)&Bs[bk0][bn0*4] = t0;
            *(uint4*)&Bs[bk1][bn1*4] = t1;
        }
        __syncthreads();
        if (kt < K) {
            av0 = *(const float4*)(Ap0 + kt);
            av1 = *(const float4*)(Ap1 + kt);
            bv0 = *(const float4*)(Bp0 + (size_t)kt*N);
            bv1 = *(const float4*)(Bp1 + (size_t)kt*N);
        }
        #pragma unroll
        for (int kk = 0; kk < 16; kk += 8) {
            unsigned afr[2][4];
            #pragma unroll
            for (int mt = 0; mt < 2; mt++) {
                int mb = warp_m*32 + mt*16;
                afr[mt][0] = As[kk+q  ][mb + p];
                afr[mt][1] = As[kk+q  ][mb + p + 8];
                afr[mt][2] = As[kk+q+4][mb + p];
                afr[mt][3] = As[kk+q+4][mb + p + 8];
            }
            unsigned bfr[8][2];
            #pragma unroll
            for (int nt = 0; nt < 8; nt++) {
                int nb = warp_n*64 + nt*8;
                bfr[nt][0] = Bs[kk+q  ][nb + p];
                bfr[nt][1] = Bs[kk+q+4][nb + p];
            }
            #pragma unroll
            for (int mt = 0; mt < 2; mt++)
                #pragma unroll
                for (int nt = 0; nt < 8; nt++)
                    mma_tf32(acc[mt][nt], afr[mt][0], afr[mt][1], afr[mt][2], afr[mt][3],
                             bfr[nt][0], bfr[nt][1]);
        }
        __syncthreads();
    }

    #pragma unroll
    for (int mt = 0; mt < 2; mt++) {
        int r0 = blockM + warp_m*32 + mt*16 + p;
        #pragma unroll
        for (int nt = 0; nt < 8; nt++) {
            int c0 = blockN + warp_n*64 + nt*8 + 2*q;
            size_t o0 = (size_t)r0*N + c0;
            size_t o1 = (size_t)(r0+8)*N + c0;
            *(float2*)(C + o0) = make_float2(rtf(acc[mt][nt][0]), rtf(acc[mt][nt][1]));
            *(float2*)(C + o1) = make_float2(rtf(acc[mt][nt][2]), rtf(acc[mt][nt][3]));
        }
    }
}

// ---------------- cp.async double-buffered TF32 GEMM ----------------
// Operands must be pre-rounded to tf32 (raw bits fed to mma).
// MODE 0: C = A@B + bias ; MODE 1: += Dm ; MODE 2: leaky_relu then += Dm
#define AS_STRIDE 20
#define BS_STRIDE 136

template<int MODE, bool RND>
__global__ __launch_bounds__(256, 2) void gemm_ca(
    const float* __restrict__ A, const float* __restrict__ B,
    const float* __restrict__ bias, const float* __restrict__ Dm,
    float* __restrict__ C, int M, int N, int K)
{
    __shared__ float As[2][128*AS_STRIDE];
    __shared__ float Bs[2][16*BS_STRIDE];
    int tid = threadIdx.x;
    int warp = tid >> 5, lane = tid & 31;
    int warp_m = warp & 3, warp_n = warp >> 2;
    int p = lane >> 2, q = lane & 3;
    int blockM = blockIdx.y * 128;
    int blockN = blockIdx.x * 128;

    int c0 = tid*2, c1 = c0 + 1;
    int ar0 = c0 >> 2, ak0 = (c0 & 3)*4;
    int ar1 = c1 >> 2, ak1 = (c1 & 3)*4;
    int bk0 = c0 >> 5, bn0 = (c0 & 31)*4;
    int bk1 = c1 >> 5, bn1 = (c1 & 31)*4;

    const float* gA0 = A + (size_t)(blockM + ar0)*K + ak0;
    const float* gA1 = A + (size_t)(blockM + ar1)*K + ak1;
    const float* gB0 = B + (size_t)bk0*N + blockN + bn0;
    const float* gB1 = B + (size_t)bk1*N + blockN + bn1;

    unsigned sa = (unsigned)__cvta_generic_to_shared(&As[0][0]);
    unsigned sb = (unsigned)__cvta_generic_to_shared(&Bs[0][0]);
    unsigned dA0[2], dA1[2], dB0[2], dB1[2];
    #pragma unroll
    for (int s = 0; s < 2; s++) {
        dA0[s] = sa + (s*128*AS_STRIDE + ar0*AS_STRIDE + ak0)*4;
        dA1[s] = sa + (s*128*AS_STRIDE + ar1*AS_STRIDE + ak1)*4;
        dB0[s] = sb + (s*16*BS_STRIDE + bk0*BS_STRIDE + bn0)*4;
        dB1[s] = sb + (s*16*BS_STRIDE + bk1*BS_STRIDE + bn1)*4;
    }

    float acc[2][8][4];
    #pragma unroll
    for (int mt = 0; mt < 2; mt++)
        #pragma unroll
        for (int nt = 0; nt < 8; nt++)
            #pragma unroll
            for (int i = 0; i < 4; i++) acc[mt][nt][i] = 0.f;

    // prologue: stage 0
    CP16(dA0[0], gA0); CP16(dA1[0], gA1);
    CP16(dB0[0], gB0); CP16(dB1[0], gB1);
    asm volatile("cp.async.commit_group;");

    int nk = K >> 4;
    for (int t = 0; t < nk; t++) {
        if (t + 1 < nk) {
            int kt = (t + 1) << 4;
            int s = (t + 1) & 1;
            CP16(dA0[s], gA0 + kt); CP16(dA1[s], gA1 + kt);
            CP16(dB0[s], gB0 + (size_t)kt*N); CP16(dB1[s], gB1 + (size_t)kt*N);
            asm volatile("cp.async.commit_group;");
            asm volatile("cp.async.wait_group 1;");
        } else {
            asm volatile("cp.async.wait_group 0;");
        }
        __syncthreads();
        const float* as = As[t & 1];
        const float* bs = Bs[t & 1];
        #pragma unroll
        for (int kk = 0; kk < 16; kk += 8) {
            unsigned afr[2][4];
            #pragma unroll
            for (int mt = 0; mt < 2; mt++) {
                int mb = warp_m*32 + mt*16;
                afr[mt][0] = __float_as_uint(as[(mb+p  )*AS_STRIDE + kk+q  ]);
                afr[mt][1] = __float_as_uint(as[(mb+p+8)*AS_STRIDE + kk+q  ]);
                afr[mt][2] = __float_as_uint(as[(mb+p  )*AS_STRIDE + kk+q+4]);
                afr[mt][3] = __float_as_uint(as[(mb+p+8)*AS_STRIDE + kk+q+4]);
            }
            unsigned bfr[8][2];
            #pragma unroll
            for (int nt = 0; nt < 8; nt++) {
                int nb = warp_n*64 + nt*8;
                bfr[nt][0] = __float_as_uint(bs[(kk+q  )*BS_STRIDE + nb+p]);
                bfr[nt][1] = __float_as_uint(bs[(kk+q+4)*BS_STRIDE + nb+p]);
            }
            #pragma unroll
            for (int mt = 0; mt < 2; mt++)
                #pragma unroll
                for (int nt = 0; nt < 8; nt++)
                    mma_tf32(acc[mt][nt], afr[mt][0], afr[mt][1], afr[mt][2], afr[mt][3],
                             bfr[nt][0], bfr[nt][1]);
        }
        __syncthreads();
    }

    #pragma unroll
    for (int mt = 0; mt < 2; mt++) {
        int r0 = blockM + warp_m*32 + mt*16 + p;
        #pragma unroll
        for (int nt = 0; nt < 8; nt++) {
            int c0c = blockN + warp_n*64 + nt*8 + 2*q;
            float b0 = 0.f, b1 = 0.f;
            if (bias) { b0 = bias[c0c]; b1 = bias[c0c+1]; }
            float v0 = acc[mt][nt][0] + b0;
            float v1 = acc[mt][nt][1] + b1;
            float v2 = acc[mt][nt][2] + b0;
            float v3 = acc[mt][nt][3] + b1;
            size_t o0 = (size_t)r0*N + c0c;
            size_t o1 = (size_t)(r0+8)*N + c0c;
            if (MODE == 1) {
                float2 d0 = *(const float2*)(Dm + o0);
                float2 d1 = *(const float2*)(Dm + o1);
                v0 += d0.x; v1 += d0.y; v2 += d1.x; v3 += d1.y;
            }
            if (MODE == 2) {
                v0 = (v0 > 0.f) ? v0 : 0.01f*v0;
                v1 = (v1 > 0.f) ? v1 : 0.01f*v1;
                v2 = (v2 > 0.f) ? v2 : 0.01f*v2;
                v3 = (v3 > 0.f) ? v3 : 0.01f*v3;
                float2 d0 = *(const float2*)(Dm + o0);
                float2 d1 = *(const float2*)(Dm + o1);
                v0 += d0.x; v1 += d0.y; v2 += d1.x; v3 += d1.y;
            }
            if (RND) { v0 = rtf(v0); v1 = rtf(v1); v2 = rtf(v2); v3 = rtf(v3); }
            *(float2*)(C + o0) = make_float2(v0, v1);
            *(float2*)(C + o1) = make_float2(v2, v3);
        }
    }
}

// ---------------- tensor-core attention ----------------
// grid (16 tiles of 64 rows, 16 graphs), 512 threads = 16 warps.
// smem strides chosen for conflict-free mma fragment access:
#define TB   64
#define KSTR 68
#define VSTR 72
#define PSTR 260
#define ATT_SMEM ((SEQ*KSTR + SEQ*VSTR + TB*PSTR)*4 + SEQ*4)

__global__ __launch_bounds__(512, 1) void attn_mma(
    const float* __restrict__ qh, const float* __restrict__ kh,
    const float* __restrict__ vh, const int* __restrict__ maskp,
    float* __restrict__ ctx, float* __restrict__ av_out)
{
    extern __shared__ float sm[];
    float* sK = sm;                    // [256][68]
    float* sV = sK + SEQ*KSTR;         // [256][72]
    float* sU = sV + SEQ*VSTR;         // Q as [64][68] / P as [64][260]
    int* sMask = (int*)(sU + TB*PSTR);

    int b = blockIdx.y, lt = blockIdx.x;
    int tid = threadIdx.x;
    int w = tid >> 5, lane = tid & 31;
    int p = lane >> 2, q = lane & 3;

    if (tid < SEQ) sMask[tid] = maskp[b*SEQ + tid];

    float avacc[2][4][4];
    #pragma unroll
    for (int j = 0; j < 2; j++)
        #pragma unroll
        for (int mt = 0; mt < 4; mt++)
            #pragma unroll
            for (int i = 0; i < 4; i++) avacc[j][mt][i] = 0.f;

    for (int h = 0; h < NH; h++) {
        __syncthreads();   // smem reuse barrier (also covers sMask at h=0)
        // load K,V head slice (already tf32-rounded at producer)
        for (int idx = tid; idx < SEQ*DH; idx += 512) {
            int s = idx >> 6, d = idx & 63;
            size_t g = ((size_t)(b*SEQ + s))*DMODEL + h*DH + d;
            sK[s*KSTR + d] = kh[g];
            sV[s*VSTR + d] = vh[g];
        }
        // load Q tile (clamp padded rows)
        for (int idx = tid; idx < TB*DH; idx += 512) {
            int r = idx >> 6, d = idx & 63;
            int l = lt*TB + r; if (l > LMAX-1) l = LMAX-1;
            sU[r*KSTR + d] = qh[((size_t)(b*LMAX) + l)*DMODEL + h*DH + d];
        }
        __syncthreads();

        // ---- scores: warp w owns columns [16w, 16w+16) as 2 n-tiles ----
        float csc[2][4][4];
        #pragma unroll
        for (int j = 0; j < 2; j++)
            #pragma unroll
            for (int mt = 0; mt < 4; mt++)
                #pragma unroll
                for (int i = 0; i < 4; i++) csc[j][mt][i] = 0.f;
        #pragma unroll
        for (int k = 0; k < 8; k++) {
            int kc = k*8 + q;
            unsigned bf0[2], bf1[2];
            #pragma unroll
            for (int j = 0; j < 2; j++) {
                int sc = (2*w + j)*8 + p;
                bf0[j] = __float_as_uint(sK[sc*KSTR + kc]);
                bf1[j] = __float_as_uint(sK[sc*KSTR + kc + 4]);
            }
            #pragma unroll
            for (int mt = 0; mt < 4; mt++) {
                int r0 = mt*16 + p;
                unsigned a0 = __float_as_uint(sU[r0*KSTR + kc]);
                unsigned a1 = __float_as_uint(sU[(r0+8)*KSTR + kc]);
                unsigned a2 = __float_as_uint(sU[r0*KSTR + kc + 4]);
                unsigned a3 = __float_as_uint(sU[(r0+8)*KSTR + kc + 4]);
                mma_tf32(csc[0][mt], a0, a1, a2, a3, bf0[0], bf1[0]);
                mma_tf32(csc[1][mt], a0, a1, a2, a3, bf0[1], bf1[1]);
            }
        }
        __syncthreads();   // done reading sU as Q
        // write raw scores into P region
        #pragma unroll
        for (int j = 0; j < 2; j++)
            #pragma unroll
            for (int mt = 0; mt < 4; mt++) {
                int row = mt*16 + p;
                int col = (2*w + j)*8 + 2*q;
                *(float2*)&sU[row*PSTR + col]     = make_float2(csc[j][mt][0], csc[j][mt][1]);
                *(float2*)&sU[(row+8)*PSTR + col] = make_float2(csc[j][mt][2], csc[j][mt][3]);
            }
        __syncthreads();
        // ---- softmax: warp w owns rows [4w, 4w+4) ----
        #pragma unroll
        for (int rr = 0; rr < 4; rr++) {
            int row = 4*w + rr;
            float v[8];
            float m = -1e30f;
            #pragma unroll
            for (int jj = 0; jj < 8; jj++) {
                int s = lane + 32*jj;
                float x = sMask[s] ? -1e30f : sU[row*PSTR + s]*0.125f;
                v[jj] = x;
                m = fmaxf(m, x);
            }
            #pragma unroll
            for (int o = 16; o > 0; o >>= 1) m = fmaxf(m, __shfl_xor_sync(0xffffffffu, m, o));
            float sum = 0.f;
            #pragma unroll
            for (int jj = 0; jj < 8; jj++) { v[jj] = __expf(v[jj] - m); sum += v[jj]; }
            #pragma unroll
            for (int o = 16; o > 0; o >>= 1) sum += __shfl_xor_sync(0xffffffffu, sum, o);
            float inv = 1.f/sum;
            #pragma unroll
            for (int jj = 0; jj < 8; jj++)
                sU[row*PSTR + lane + 32*jj] = rtf(v[jj]*inv);
        }
        __syncthreads();
        // ---- av accumulate (same fragment ownership as scores) ----
        #pragma unroll
        for (int j = 0; j < 2; j++)
            #pragma unroll
            for (int mt = 0; mt < 4; mt++) {
                int row = mt*16 + p;
                int col = (2*w + j)*8 + 2*q;
                avacc[j][mt][0] += sU[row*PSTR + col];
                avacc[j][mt][1] += sU[row*PSTR + col + 1];
                avacc[j][mt][2] += sU[(row+8)*PSTR + col];
                avacc[j][mt][3] += sU[(row+8)*PSTR + col + 1];
            }
        // ---- P@V: warp w -> (mt = w&3, nt = w>>2 and +4) ----
        int mtw = w & 3, nt0 = w >> 2;
        float cct[2][4];
        #pragma unroll
        for (int j = 0; j < 2; j++)
            #pragma unroll
            for (int i = 0; i < 4; i++) cct[j][i] = 0.f;
        #pragma unroll 8
        for (int k = 0; k < 32; k++) {
            int sc = k*8 + q;
            int r0 = mtw*16 + p;
            unsigned a0 = __float_as_uint(sU[r0*PSTR + sc]);
            unsigned a1 = __float_as_uint(sU[(r0+8)*PSTR + sc]);
            unsigned a2 = __float_as_uint(sU[r0*PSTR + sc + 4]);
            unsigned a3 = __float_as_uint(sU[(r0+8)*PSTR + sc + 4]);
            #pragma unroll
            for (int j = 0; j < 2; j++) {
                int dc = (nt0 + 4*j)*8 + p;
                unsigned b0 = __float_as_uint(sV[sc*VSTR + dc]);
                unsigned b1 = __float_as_uint(sV[(sc+4)*VSTR + dc]);
                mma_tf32(cct[j], a0, a1, a2, a3, b0, b1);
            }
        }
        // store ctx slice (rounded: feeds Wo GEMM)
        #pragma unroll
        for (int j = 0; j < 2; j++) {
            int dc = h*DH + (nt0 + 4*j)*8 + 2*q;
            int l0 = lt*TB + mtw*16 + p;
            if (l0 < LMAX)
                *(float2*)&ctx[((size_t)(b*LMAX) + l0)*DMODEL + dc] =
                    make_float2(rtf(cct[j][0]), rtf(cct[j][1]));
            int l1 = l0 + 8;
            if (l1 < LMAX)
                *(float2*)&ctx[((size_t)(b*LMAX) + l1)*DMODEL + dc] =
                    make_float2(rtf(cct[j][2]), rtf(cct[j][3]));
        }
    }

    // ---- store head-averaged attention ----
    #pragma unroll
    for (int j = 0; j < 2; j++)
        #pragma unroll
        for (int mt = 0; mt < 4; mt++) {
            int col = (2*w + j)*8 + 2*q;
            int l0 = lt*TB + mt*16 + p;
            if (l0 < LMAX)
                *(float2*)&av_out[((size_t)(b*LMAX) + l0)*SEQ + col] =
                    make_float2(avacc[j][mt][0]*0.125f, avacc[j][mt][1]*0.125f);
            int l1 = l0 + 8;
            if (l1 < LMAX)
                *(float2*)&av_out[((size_t)(b*LMAX) + l1)*SEQ + col] =
                    make_float2(avacc[j][mt][2]*0.125f, avacc[j][mt][3]*0.125f);
        }
}

// ---------------- LayerNorm ----------
template<bool RND>
__global__ __launch_bounds__(128) void ln_kernel(
    const float* __restrict__ x, const float* __restrict__ g,
    const float* __restrict__ bb, float* __restrict__ y)
{
    __shared__ float ws[4], wss[4];
    int r = blockIdx.x;
    int tid = threadIdx.x;
    const float4* xr = (const float4*)(x + (size_t)r*DMODEL);
    float4 v = xr[tid];
    float s  = v.x + v.y + v.z + v.w;
    float ss = v.x*v.x + v.y*v.y + v.z*v.z + v.w*v.w;
    #pragma unroll
    for (int o = 16; o > 0; o >>= 1) {
        s  += __shfl_xor_sync(0xffffffffu, s,  o);
        ss += __shfl_xor_sync(0xffffffffu, ss, o);
    }
    int warp = tid >> 5, lane = tid & 31;
    if (lane == 0) { ws[warp] = s; wss[warp] = ss; }
    __syncthreads();
    float S  = ws[0] + ws[1] + ws[2] + ws[3];
    float SS = wss[0] + wss[1] + wss[2] + wss[3];
    float mean = S * (1.f/DMODEL);
    float var  = SS * (1.f/DMODEL) - mean*mean;
    float rstd = rsqrtf(var + 1e-5f);
    float4 gg = ((const float4*)g)[tid];
    float4 b4 = ((const float4*)bb)[tid];
    float4 o4;
    o4.x = (v.x - mean)*rstd*gg.x + b4.x;
    o4.y = (v.y - mean)*rstd*gg.y + b4.y;
    o4.z = (v.z - mean)*rstd*gg.z + b4.z;
    o4.w = (v.w - mean)*rstd*gg.w + b4.w;
    if (RND) { o4.x = rtf(o4.x); o4.y = rtf(o4.y); o4.z = rtf(o4.z); o4.w = rtf(o4.w); }
    ((float4*)(y + (size_t)r*DMODEL))[tid] = o4;
}

// ---------------- launch ----------------
extern "C" void kernel_launch(void* const* d_in, const int* in_sizes, int n_in,
                              void* d_out, int out_size)
{
    int off = (n_in >= 22) ? 0 : 2;
    const float* nodes  = (const float*)d_in[0];
    const int*   gb     = (const int*)  d_in[1];
    const float* cond   = (const float*)d_in[2];
    const int*   maskp  = (const int*)  d_in[3];
    const float* Wq     = (const float*)d_in[6-off];
    const float* bq     = (const float*)d_in[7-off];
    const float* Wk     = (const float*)d_in[8-off];
    const float* bk     = (const float*)d_in[9-off];
    const float* Wv     = (const float*)d_in[10-off];
    const float* bv     = (const float*)d_in[11-off];
    const float* in_w   = (const float*)d_in[12-off];
    const float* in_b   = (const float*)d_in[13-off];
    const float* Wo     = (const float*)d_in[14-off];
    const float* bo     = (const float*)d_in[15-off];
    const float* ln1g   = (const float*)d_in[16-off];
    const float* ln1b   = (const float*)d_in[17-off];
    const float* W1     = (const float*)d_in[18-off];
    const float* b1     = (const float*)d_in[19-off];
    const float* ln2g   = (const float*)d_in[20-off];
    const float* ln2b   = (const float*)d_in[21-off];
    float* out = (float*)d_out;
    float* av_out = out + (size_t)NN*DMODEL;

    float *p_dense, *p_qh, *p_kh, *p_vh, *p_ctx, *p_y, *p_x1, *p_h;
    float *p_Wq2, *p_Wk2, *p_Wv2, *p_Wo2, *p_W12, *p_cond;
    float *p_bq2, *p_bk2, *p_bv2;
    int *p_starts;
    cudaGetSymbolAddress((void**)&p_dense, g_dense);
    cudaGetSymbolAddress((void**)&p_qh, g_qh);
    cudaGetSymbolAddress((void**)&p_kh, g_kh);
    cudaGetSymbolAddress((void**)&p_vh, g_vh);
    cudaGetSymbolAddress((void**)&p_ctx, g_ctx);
    cudaGetSymbolAddress((void**)&p_y, g_y);
    cudaGetSymbolAddress((void**)&p_x1, g_x1);
    cudaGetSymbolAddress((void**)&p_h, g_h);
    cudaGetSymbolAddress((void**)&p_Wq2, g_Wq2);
    cudaGetSymbolAddress((void**)&p_Wk2, g_Wk2);
    cudaGetSymbolAddress((void**)&p_Wv2, g_Wv2);
    cudaGetSymbolAddress((void**)&p_Wo2, g_Wo2);
    cudaGetSymbolAddress((void**)&p_W12, g_W12);
    cudaGetSymbolAddress((void**)&p_cond, g_cond);
    cudaGetSymbolAddress((void**)&p_bq2, g_bq2);
    cudaGetSymbolAddress((void**)&p_bk2, g_bk2);
    cudaGetSymbolAddress((void**)&p_bv2, g_bv2);
    cudaGetSymbolAddress((void**)&p_starts, g_starts);

    // 1) ragged bookkeeping + dense padding (rounded)
    find_starts<<<(NN+255)/256, 256>>>(gb, p_starts, NN);
    zero_kernel<<<1024, 256>>>(p_dense, ROWS_Q*DMODEL);
    scatter_kernel<<<NN, 128>>>(nodes, gb, p_starts, p_dense);

    // 2) fold projections (one z-batched launch) + bias combines
    fold3_gemm<<<dim3(4,6,3), 256>>>(Wq, Wk, Wv, in_w, p_Wq2, p_Wk2, p_Wv2);
    bias3<<<dim3(1,3), 512>>>(bq, bk, bv, in_w, in_b, p_bq2, p_bk2, p_bv2);

    // 3) pre-round remaining GEMM operands
    round_copy<<<512, 256>>>(cond, p_cond, BGR*SEQ*LATD/4);
    round_copy<<<128, 256>>>(Wo, p_Wo2, DMODEL*DMODEL/4);
    round_copy<<<128, 256>>>(W1, p_W12, DMODEL*DMODEL/4);

    // 4) projections (outputs rounded for attention mma)
    gemm_ca<0,true><<<dim3(4,124), 256>>>(p_dense, p_Wq2, p_bq2, nullptr, p_qh, ROWS_Q, DMODEL, DMODEL);
    gemm_ca<0,true><<<dim3(4,32),  256>>>(p_cond,  p_Wk2, p_bk2, nullptr, p_kh, ROWS_KV, DMODEL, LATD);
    gemm_ca<0,true><<<dim3(4,32),  256>>>(p_cond,  p_Wv2, p_bv2, nullptr, p_vh, ROWS_KV, DMODEL, LATD);

    // 5) tensor-core attention
    cudaFuncSetAttribute(attn_mma, cudaFuncAttributeMaxDynamicSharedMemorySize, ATT_SMEM);
    attn_mma<<<dim3(16, BGR), 512, ATT_SMEM>>>(p_qh, p_kh, p_vh, maskp, p_ctx, av_out);

    // 6) out proj + residual, LN1, FFN, LN2
    gemm_ca<1,false><<<dim3(4,124), 256>>>(p_ctx, p_Wo2, bo, p_dense, p_y, ROWS_Q, DMODEL, DMODEL);
    ln_kernel<true><<<ROWS_Q, 128>>>(p_y, ln1g, ln1b, p_x1);
    gemm_ca<2,false><<<dim3(4,124), 256>>>(p_x1, p_W12, b1, p_x1, p_h, ROWS_Q, DMODEL, DMODEL);
    ln_kernel<false><<<ROWS_Q, 128>>>(p_h, ln2g, ln2b, p_y);

    // 7) ragged gather
    gather_kernel<<<NN, 128>>>(p_y, gb, p_starts, out);
}

// round 4
// speedup vs baseline: 3.3761x; 1.0354x over previous
#include <cuda_runtime.h>
#include <cuda_bf16.h>
#include <math.h>

// ---------------- problem constants ----------------
#define NN    12032
#define DMODEL 512
#define BGR   16
#define SEQ   256
#define NH    8
#define DH    64
#define LMAX  992
#define LATD  768
#define ROWS_Q  (BGR*LMAX)   // 15872
#define ROWS_KV (BGR*SEQ)    // 4096

// ---------------- scratch ----------
__device__ float g_dense[ROWS_Q*DMODEL];
__device__ float g_qh   [ROWS_Q*DMODEL];
__device__ float g_ctx  [ROWS_Q*DMODEL];
__device__ float g_y    [ROWS_Q*DMODEL];
__device__ float g_x1   [ROWS_Q*DMODEL];
__device__ float g_h    [ROWS_Q*DMODEL];
__device__ float g_kh   [ROWS_KV*DMODEL];
__device__ float g_vh   [ROWS_KV*DMODEL];
__device__ float g_Wq2  [DMODEL*DMODEL];
__device__ float g_Wk2  [LATD*DMODEL];
__device__ float g_Wv2  [LATD*DMODEL];
__device__ float g_Wo2  [DMODEL*DMODEL];
__device__ float g_W12  [DMODEL*DMODEL];
__device__ float g_cond [BGR*SEQ*LATD];
__device__ float g_bq2  [DMODEL];
__device__ float g_bk2  [DMODEL];
__device__ float g_bv2  [DMODEL];
__device__ int   g_starts[BGR];

// ---------------- helpers ----------------
__device__ __forceinline__ unsigned f2tf32(float x) {
    unsigned y;
    asm("cvt.rna.tf32.f32 %0, %1;" : "=r"(y) : "f"(x));
    return y;
}
__device__ __forceinline__ float rtf(float x) { return __uint_as_float(f2tf32(x)); }

__device__ __forceinline__ void mma_tf32(float c[4],
    unsigned a0, unsigned a1, unsigned a2, unsigned a3,
    unsigned b0, unsigned b1)
{
    asm volatile(
        "mma.sync.aligned.m16n8k8.row.col.f32.tf32.tf32.f32 "
        "{%0,%1,%2,%3}, {%4,%5,%6,%7}, {%8,%9}, {%0,%1,%2,%3};"
        : "+f"(c[0]), "+f"(c[1]), "+f"(c[2]), "+f"(c[3])
        : "r"(a0), "r"(a1), "r"(a2), "r"(a3), "r"(b0), "r"(b1));
}

#define CP16(dst, src) asm volatile("cp.async.cg.shared.global [%0], [%1], 16;" :: "r"(dst), "l"(src))

__global__ void find_starts(const int* __restrict__ gb, int* starts, int n) {
    int i = blockIdx.x*blockDim.x + threadIdx.x;
    if (i < n) {
        if (i == 0 || gb[i] != gb[i-1]) starts[gb[i]] = i;
    }
}

// one block per dense row: copy rounded node or write zeros (fuses zero+scatter)
__global__ __launch_bounds__(128) void pad_kernel(
    const float* __restrict__ nodes, const int* __restrict__ starts,
    float* __restrict__ dense)
{
    int r = blockIdx.x;
    int b = r / LMAX, pp = r - b*LMAX;
    int s = starts[b];
    int e = (b == BGR-1) ? NN : starts[b+1];
    int i = s + pp;
    float4 v = make_float4(0.f, 0.f, 0.f, 0.f);
    if (i < e) {
        v = ((const float4*)(nodes + (size_t)i*DMODEL))[threadIdx.x];
        v.x = rtf(v.x); v.y = rtf(v.y); v.z = rtf(v.z); v.w = rtf(v.w);
    }
    ((float4*)(dense + (size_t)r*DMODEL))[threadIdx.x] = v;
}

__global__ __launch_bounds__(128) void gather_kernel(
    const float* __restrict__ x, const int* __restrict__ gb,
    const int* __restrict__ starts, float* __restrict__ out)
{
    int i = blockIdx.x;
    int b = gb[i];
    int p = i - starts[b];
    const float4* src = (const float4*)(x + ((size_t)b*LMAX + p)*DMODEL);
    float4* dst = (float4*)(out + (size_t)i*DMODEL);
    dst[threadIdx.x] = src[threadIdx.x];
}

// batched tf32 round-copy of the three remaining raw operands
__global__ void round3(const float* __restrict__ cond, const float* __restrict__ Wo,
                       const float* __restrict__ W1,
                       float* __restrict__ dc, float* __restrict__ dwo, float* __restrict__ dw1)
{
    int z = blockIdx.y;
    const float* s = (z==0) ? cond : (z==1) ? Wo : W1;
    float* d = (z==0) ? dc : (z==1) ? dwo : dw1;
    int n4 = ((z==0) ? BGR*SEQ*LATD : DMODEL*DMODEL) >> 2;
    int i = blockIdx.x*blockDim.x + threadIdx.x;
    int stride = gridDim.x*blockDim.x;
    for (; i < n4; i += stride) {
        float4 v = ((const float4*)s)[i];
        v.x = rtf(v.x); v.y = rtf(v.y); v.z = rtf(v.z); v.w = rtf(v.w);
        ((float4*)d)[i] = v;
    }
}

// batched bias combine
__global__ void bias3(const float* __restrict__ bq, const float* __restrict__ bk,
                      const float* __restrict__ bv, const float* __restrict__ inw,
                      const float* __restrict__ inb,
                      float* __restrict__ oq, float* __restrict__ ok, float* __restrict__ ov)
{
    int z = blockIdx.y;
    const float* bin = (z==0) ? bq : (z==1) ? bk : bv;
    const float* W = inw + (size_t)z*DMODEL*DMODEL;
    const float* ab = inb + z*DMODEL;
    float* out = (z==0) ? oq : (z==1) ? ok : ov;
    int j = threadIdx.x;
    if (j < DMODEL) {
        float a = ab[j];
        for (int i = 0; i < DMODEL; i++) a += bin[i]*W[i*DMODEL + j];
        out[j] = a;
    }
}

// ---------------- fold3: three small weight GEMMs in one launch -------------
#define SMP 132

__global__ __launch_bounds__(256) void fold3_gemm(
    const float* __restrict__ Wq, const float* __restrict__ Wk,
    const float* __restrict__ Wv, const float* __restrict__ inw,
    float* __restrict__ Cq, float* __restrict__ Ck, float* __restrict__ Cv)
{
    int z = blockIdx.z;
    int M = (z == 0) ? DMODEL : LATD;
    if ((int)blockIdx.y*128 >= M) return;
    const float* A = (z==0) ? Wq : (z==1) ? Wk : Wv;
    const float* B = inw + (size_t)z*DMODEL*DMODEL;
    float* C = (z==0) ? Cq : (z==1) ? Ck : Cv;
    const int N = DMODEL, K = DMODEL;

    __shared__ unsigned As[16][SMP];
    __shared__ unsigned Bs[16][SMP];
    int tid = threadIdx.x;
    int warp = tid >> 5, lane = tid & 31;
    int warp_m = warp & 3, warp_n = warp >> 2;
    int p = lane >> 2, q = lane & 3;
    int blockM = blockIdx.y * 128;
    int blockN = blockIdx.x * 128;

    int ia0 = tid*2, ia1 = tid*2 + 1;
    int arow0 = ia0 >> 2, akq0 = ia0 & 3;
    int arow1 = ia1 >> 2, akq1 = ia1 & 3;
    int bk0 = ia0 >> 5, bn0 = ia0 & 31;
    int bk1 = ia1 >> 5, bn1 = ia1 & 31;

    const float* Ap0 = A + (size_t)(blockM + arow0)*K + akq0*4;
    const float* Ap1 = A + (size_t)(blockM + arow1)*K + akq1*4;
    const float* Bp0 = B + (size_t)bk0*N + blockN + bn0*4;
    const float* Bp1 = B + (size_t)bk1*N + blockN + bn1*4;

    float acc[2][8][4];
    #pragma unroll
    for (int mt = 0; mt < 2; mt++)
        #pragma unroll
        for (int nt = 0; nt < 8; nt++)
            #pragma unroll
            for (int i = 0; i < 4; i++) acc[mt][nt][i] = 0.f;

    float4 av0 = *(const float4*)(Ap0);
    float4 av1 = *(const float4*)(Ap1);
    float4 bv0 = *(const float4*)(Bp0);
    float4 bv1 = *(const float4*)(Bp1);

    for (int kt = 16; kt <= K; kt += 16) {
        As[akq0*4+0][arow0] = f2tf32(av0.x);
        As[akq0*4+1][arow0] = f2tf32(av0.y);
        As[akq0*4+2][arow0] = f2tf32(av0.z);
        As[akq0*4+3][arow0] = f2tf32(av0.w);
        As[akq1*4+0][arow1] = f2tf32(av1.x);
        As[akq1*4+1][arow1] = f2tf32(av1.y);
        As[akq1*4+2][arow1] = f2tf32(av1.z);
        As[akq1*4+3][arow1] = f2tf32(av1.w);
        {
            uint4 t0, t1;
            t0.x = f2tf32(bv0.x); t0.y = f2tf32(bv0.y);
            t0.z = f2tf32(bv0.z); t0.w = f2tf32(bv0.w);
            t1.x = f2tf32(bv1.x); t1.y = f2tf32(bv1.y);
            t1.z = f2tf32(bv1.z); t1.w = f2tf32(bv1.w);
            *(uint4*)&Bs[bk0][bn0*4] = t0;
            *(uint4*)&Bs[bk1][bn1*4] = t1;
        }
        __syncthreads();
        if (kt < K) {
            av0 = *(const float4*)(Ap0 + kt);
            av1 = *(const float4*)(Ap1 + kt);
            bv0 = *(const float4*)(Bp0 + (size_t)kt*N);
            bv1 = *(const float4*)(Bp1 + (size_t)kt*N);
        }
        #pragma unroll
        for (int kk = 0; kk < 16; kk += 8) {
            unsigned afr[2][4];
            #pragma unroll
            for (int mt = 0; mt < 2; mt++) {
                int mb = warp_m*32 + mt*16;
                afr[mt][0] = As[kk+q  ][mb + p];
                afr[mt][1] = As[kk+q  ][mb + p + 8];
                afr[mt][2] = As[kk+q+4][mb + p];
                afr[mt][3] = As[kk+q+4][mb + p + 8];
            }
            unsigned bfr[8][2];
            #pragma unroll
            for (int nt = 0; nt < 8; nt++) {
                int nb = warp_n*64 + nt*8;
                bfr[nt][0] = Bs[kk+q  ][nb + p];
                bfr[nt][1] = Bs[kk+q+4][nb + p];
            }
            #pragma unroll
            for (int mt = 0; mt < 2; mt++)
                #pragma unroll
                for (int nt = 0; nt < 8; nt++)
                    mma_tf32(acc[mt][nt], afr[mt][0], afr[mt][1], afr[mt][2], afr[mt][3],
                             bfr[nt][0], bfr[nt][1]);
        }
        __syncthreads();
    }

    #pragma unroll
    for (int mt = 0; mt < 2; mt++) {
        int r0 = blockM + warp_m*32 + mt*16 + p;
        #pragma unroll
        for (int nt = 0; nt < 8; nt++) {
            int c0 = blockN + warp_n*64 + nt*8 + 2*q;
            size_t o0 = (size_t)r0*N + c0;
            size_t o1 = (size_t)(r0+8)*N + c0;
            *(float2*)(C + o0) = make_float2(rtf(acc[mt][nt][0]), rtf(acc[mt][nt][1]));
            *(float2*)(C + o1) = make_float2(rtf(acc[mt][nt][2]), rtf(acc[mt][nt][3]));
        }
    }
}

// ---------------- 3-stage cp.async TF32 GEMM (single sync per tile) --------
// Operands must be pre-rounded to tf32.
#define AS_STRIDE 20
#define BS_STRIDE 136
#define GEMM_SMEM ((3*128*AS_STRIDE + 3*16*BS_STRIDE)*4)

template<int MODE, bool RND>
__device__ __forceinline__ void gemm_body(
    const float* __restrict__ A, const float* __restrict__ B,
    const float* __restrict__ bias, const float* __restrict__ Dm,
    float* __restrict__ C, int N, int K, float* smem)
{
    float* As = smem;
    float* Bs = smem + 3*128*AS_STRIDE;

    int tid = threadIdx.x;
    int warp = tid >> 5, lane = tid & 31;
    int warp_m = warp & 3, warp_n = warp >> 2;
    int p = lane >> 2, q = lane & 3;
    int blockM = blockIdx.y * 128;
    int blockN = blockIdx.x * 128;

    int c0 = tid*2, c1 = c0 + 1;
    int ar0 = c0 >> 2, ak0 = (c0 & 3)*4;
    int ar1 = c1 >> 2, ak1 = (c1 & 3)*4;
    int bk0 = c0 >> 5, bn0 = (c0 & 31)*4;
    int bk1 = c1 >> 5, bn1 = (c1 & 31)*4;

    const float* gA0 = A + (size_t)(blockM + ar0)*K + ak0;
    const float* gA1 = A + (size_t)(blockM + ar1)*K + ak1;
    const float* gB0 = B + (size_t)bk0*N + blockN + bn0;
    const float* gB1 = B + (size_t)bk1*N + blockN + bn1;

    unsigned sa = (unsigned)__cvta_generic_to_shared(As);
    unsigned sb = (unsigned)__cvta_generic_to_shared(Bs);
    unsigned dA0[3], dA1[3], dB0[3], dB1[3];
    #pragma unroll
    for (int s = 0; s < 3; s++) {
        dA0[s] = sa + (s*128*AS_STRIDE + ar0*AS_STRIDE + ak0)*4;
        dA1[s] = sa + (s*128*AS_STRIDE + ar1*AS_STRIDE + ak1)*4;
        dB0[s] = sb + (s*16*BS_STRIDE + bk0*BS_STRIDE + bn0)*4;
        dB1[s] = sb + (s*16*BS_STRIDE + bk1*BS_STRIDE + bn1)*4;
    }

    float acc[2][8][4];
    #pragma unroll
    for (int mt = 0; mt < 2; mt++)
        #pragma unroll
        for (int nt = 0; nt < 8; nt++)
            #pragma unroll
            for (int i = 0; i < 4; i++) acc[mt][nt][i] = 0.f;

    // prologue: stages 0,1
    CP16(dA0[0], gA0); CP16(dA1[0], gA1);
    CP16(dB0[0], gB0); CP16(dB1[0], gB1);
    asm volatile("cp.async.commit_group;");
    CP16(dA0[1], gA0 + 16); CP16(dA1[1], gA1 + 16);
    CP16(dB0[1], gB0 + (size_t)16*N); CP16(dB1[1], gB1 + (size_t)16*N);
    asm volatile("cp.async.commit_group;");

    int nk = K >> 4;
    int sc = 0, sp = 2;
    for (int t = 0; t < nk; t++) {
        asm volatile("cp.async.wait_group 1;");
        __syncthreads();
        if (t + 2 < nk) {
            int kt = (t + 2) << 4;
            CP16(dA0[sp], gA0 + kt); CP16(dA1[sp], gA1 + kt);
            CP16(dB0[sp], gB0 + (size_t)kt*N); CP16(dB1[sp], gB1 + (size_t)kt*N);
        }
        asm volatile("cp.async.commit_group;");
        const float* as = As + sc*128*AS_STRIDE;
        const float* bs = Bs + sc*16*BS_STRIDE;
        #pragma unroll
        for (int kk = 0; kk < 16; kk += 8) {
            unsigned afr[2][4];
            #pragma unroll
            for (int mt = 0; mt < 2; mt++) {
                int mb = warp_m*32 + mt*16;
                afr[mt][0] = __float_as_uint(as[(mb+p  )*AS_STRIDE + kk+q  ]);
                afr[mt][1] = __float_as_uint(as[(mb+p+8)*AS_STRIDE + kk+q  ]);
                afr[mt][2] = __float_as_uint(as[(mb+p  )*AS_STRIDE + kk+q+4]);
                afr[mt][3] = __float_as_uint(as[(mb+p+8)*AS_STRIDE + kk+q+4]);
            }
            unsigned bfr[8][2];
            #pragma unroll
            for (int nt = 0; nt < 8; nt++) {
                int nb = warp_n*64 + nt*8;
                bfr[nt][0] = __float_as_uint(bs[(kk+q  )*BS_STRIDE + nb+p]);
                bfr[nt][1] = __float_as_uint(bs[(kk+q+4)*BS_STRIDE + nb+p]);
            }
            #pragma unroll
            for (int mt = 0; mt < 2; mt++)
                #pragma unroll
                for (int nt = 0; nt < 8; nt++)
                    mma_tf32(acc[mt][nt], afr[mt][0], afr[mt][1], afr[mt][2], afr[mt][3],
                             bfr[nt][0], bfr[nt][1]);
        }
        sc++; if (sc == 3) sc = 0;
        sp++; if (sp == 3) sp = 0;
    }

    #pragma unroll
    for (int mt = 0; mt < 2; mt++) {
        int r0 = blockM + warp_m*32 + mt*16 + p;
        #pragma unroll
        for (int nt = 0; nt < 8; nt++) {
            int c0c = blockN + warp_n*64 + nt*8 + 2*q;
            float b0 = 0.f, b1 = 0.f;
            if (bias) { b0 = bias[c0c]; b1 = bias[c0c+1]; }
            float v0 = acc[mt][nt][0] + b0;
            float v1 = acc[mt][nt][1] + b1;
            float v2 = acc[mt][nt][2] + b0;
            float v3 = acc[mt][nt][3] + b1;
            size_t o0 = (size_t)r0*N + c0c;
            size_t o1 = (size_t)(r0+8)*N + c0c;
            if (MODE == 1) {
                float2 d0 = *(const float2*)(Dm + o0);
                float2 d1 = *(const float2*)(Dm + o1);
                v0 += d0.x; v1 += d0.y; v2 += d1.x; v3 += d1.y;
            }
            if (MODE == 2) {
                v0 = (v0 > 0.f) ? v0 : 0.01f*v0;
                v1 = (v1 > 0.f) ? v1 : 0.01f*v1;
                v2 = (v2 > 0.f) ? v2 : 0.01f*v2;
                v3 = (v3 > 0.f) ? v3 : 0.01f*v3;
                float2 d0 = *(const float2*)(Dm + o0);
                float2 d1 = *(const float2*)(Dm + o1);
                v0 += d0.x; v1 += d0.y; v2 += d1.x; v3 += d1.y;
            }
            if (RND) { v0 = rtf(v0); v1 = rtf(v1); v2 = rtf(v2); v3 = rtf(v3); }
            *(float2*)(C + o0) = make_float2(v0, v1);
            *(float2*)(C + o1) = make_float2(v2, v3);
        }
    }
}

template<int MODE, bool RND>
__global__ __launch_bounds__(256, 2) void gemm_one(
    const float* __restrict__ A, const float* __restrict__ B,
    const float* __restrict__ bias, const float* __restrict__ Dm,
    float* __restrict__ C, int N, int K)
{
    extern __shared__ float smem[];
    gemm_body<MODE, RND>(A, B, bias, Dm, C, N, K, smem);
}

// K and V projections fused into one launch (z selects operand set)
__global__ __launch_bounds__(256, 2) void gemm_kv(
    const float* __restrict__ cond,
    const float* __restrict__ Wk2, const float* __restrict__ Wv2,
    const float* __restrict__ bk2, const float* __restrict__ bv2,
    float* __restrict__ kh, float* __restrict__ vh)
{
    extern __shared__ float smem[];
    const float* B = blockIdx.z ? Wv2 : Wk2;
    const float* bias = blockIdx.z ? bv2 : bk2;
    float* C = blockIdx.z ? vh : kh;
    gemm_body<0, true>(cond, B, bias, nullptr, C, DMODEL, LATD, smem);
}

// ---------------- tensor-core attention (unchanged from R3) ----------------
#define TB   64
#define KSTR 68
#define VSTR 72
#define PSTR 260
#define ATT_SMEM ((SEQ*KSTR + SEQ*VSTR + TB*PSTR)*4 + SEQ*4)

__global__ __launch_bounds__(512, 1) void attn_mma(
    const float* __restrict__ qh, const float* __restrict__ kh,
    const float* __restrict__ vh, const int* __restrict__ maskp,
    float* __restrict__ ctx, float* __restrict__ av_out)
{
    extern __shared__ float sm[];
    float* sK = sm;
    float* sV = sK + SEQ*KSTR;
    float* sU = sV + SEQ*VSTR;
    int* sMask = (int*)(sU + TB*PSTR);

    int b = blockIdx.y, lt = blockIdx.x;
    int tid = threadIdx.x;
    int w = tid >> 5, lane = tid & 31;
    int p = lane >> 2, q = lane & 3;

    if (tid < SEQ) sMask[tid] = maskp[b*SEQ + tid];

    float avacc[2][4][4];
    #pragma unroll
    for (int j = 0; j < 2; j++)
        #pragma unroll
        for (int mt = 0; mt < 4; mt++)
            #pragma unroll
            for (int i = 0; i < 4; i++) avacc[j][mt][i] = 0.f;

    for (int h = 0; h < NH; h++) {
        __syncthreads();
        for (int idx = tid; idx < SEQ*DH; idx += 512) {
            int s = idx >> 6, d = idx & 63;
            size_t g = ((size_t)(b*SEQ + s))*DMODEL + h*DH + d;
            sK[s*KSTR + d] = kh[g];
            sV[s*VSTR + d] = vh[g];
        }
        for (int idx = tid; idx < TB*DH; idx += 512) {
            int r = idx >> 6, d = idx & 63;
            int l = lt*TB + r; if (l > LMAX-1) l = LMAX-1;
            sU[r*KSTR + d] = qh[((size_t)(b*LMAX) + l)*DMODEL + h*DH + d];
        }
        __syncthreads();

        float csc[2][4][4];
        #pragma unroll
        for (int j = 0; j < 2; j++)
            #pragma unroll
            for (int mt = 0; mt < 4; mt++)
                #pragma unroll
                for (int i = 0; i < 4; i++) csc[j][mt][i] = 0.f;
        #pragma unroll
        for (int k = 0; k < 8; k++) {
            int kc = k*8 + q;
            unsigned bf0[2], bf1[2];
            #pragma unroll
            for (int j = 0; j < 2; j++) {
                int sc = (2*w + j)*8 + p;
                bf0[j] = __float_as_uint(sK[sc*KSTR + kc]);
                bf1[j] = __float_as_uint(sK[sc*KSTR + kc + 4]);
            }
            #pragma unroll
            for (int mt = 0; mt < 4; mt++) {
                int r0 = mt*16 + p;
                unsigned a0 = __float_as_uint(sU[r0*KSTR + kc]);
                unsigned a1 = __float_as_uint(sU[(r0+8)*KSTR + kc]);
                unsigned a2 = __float_as_uint(sU[r0*KSTR + kc + 4]);
                unsigned a3 = __float_as_uint(sU[(r0+8)*KSTR + kc + 4]);
                mma_tf32(csc[0][mt], a0, a1, a2, a3, bf0[0], bf1[0]);
                mma_tf32(csc[1][mt], a0, a1, a2, a3, bf0[1], bf1[1]);
            }
        }
        __syncthreads();
        #pragma unroll
        for (int j = 0; j < 2; j++)
            #pragma unroll
            for (int mt = 0; mt < 4; mt++) {
                int row = mt*16 + p;
                int col = (2*w + j)*8 + 2*q;
                *(float2*)&sU[row*PSTR + col]     = make_float2(csc[j][mt][0], csc[j][mt][1]);
                *(float2*)&sU[(row+8)*PSTR + col] = make_float2(csc[j][mt][2], csc[j][mt][3]);
            }
        __syncthreads();
        #pragma unroll
        for (int rr = 0; rr < 4; rr++) {
            int row = 4*w + rr;
            float v[8];
            float m = -1e30f;
            #pragma unroll
            for (int jj = 0; jj < 8; jj++) {
                int s = lane + 32*jj;
                float x = sMask[s] ? -1e30f : sU[row*PSTR + s]*0.125f;
                v[jj] = x;
                m = fmaxf(m, x);
            }
            #pragma unroll
            for (int o = 16; o > 0; o >>= 1) m = fmaxf(m, __shfl_xor_sync(0xffffffffu, m, o));
            float sum = 0.f;
            #pragma unroll
            for (int jj = 0; jj < 8; jj++) { v[jj] = __expf(v[jj] - m); sum += v[jj]; }
            #pragma unroll
            for (int o = 16; o > 0; o >>= 1) sum += __shfl_xor_sync(0xffffffffu, sum, o);
            float inv = 1.f/sum;
            #pragma unroll
            for (int jj = 0; jj < 8; jj++)
                sU[row*PSTR + lane + 32*jj] = rtf(v[jj]*inv);
        }
        __syncthreads();
        #pragma unroll
        for (int j = 0; j < 2; j++)
            #pragma unroll
            for (int mt = 0; mt < 4; mt++) {
                int row = mt*16 + p;
                int col = (2*w + j)*8 + 2*q;
                avacc[j][mt][0] += sU[row*PSTR + col];
                avacc[j][mt][1] += sU[row*PSTR + col + 1];
                avacc[j][mt][2] += sU[(row+8)*PSTR + col];
                avacc[j][mt][3] += sU[(row+8)*PSTR + col + 1];
            }
        int mtw = w & 3, nt0 = w >> 2;
        float cct[2][4];
        #pragma unroll
        for (int j = 0; j < 2; j++)
            #pragma unroll
            for (int i = 0; i < 4; i++) cct[j][i] = 0.f;
        #pragma unroll 8
        for (int k = 0; k < 32; k++) {
            int sc = k*8 + q;
            int r0 = mtw*16 + p;
            unsigned a0 = __float_as_uint(sU[r0*PSTR + sc]);
            unsigned a1 = __float_as_uint(sU[(r0+8)*PSTR + sc]);
            unsigned a2 = __float_as_uint(sU[r0*PSTR + sc + 4]);
            unsigned a3 = __float_as_uint(sU[(r0+8)*PSTR + sc + 4]);
            #pragma unroll
            for (int j = 0; j < 2; j++) {
                int dc = (nt0 + 4*j)*8 + p;
                unsigned b0 = __float_as_uint(sV[sc*VSTR + dc]);
                unsigned b1 = __float_as_uint(sV[(sc+4)*VSTR + dc]);
                mma_tf32(cct[j], a0, a1, a2, a3, b0, b1);
            }
        }
        #pragma unroll
        for (int j = 0; j < 2; j++) {
            int dc = h*DH + (nt0 + 4*j)*8 + 2*q;
            int l0 = lt*TB + mtw*16 + p;
            if (l0 < LMAX)
                *(float2*)&ctx[((size_t)(b*LMAX) + l0)*DMODEL + dc] =
                    make_float2(rtf(cct[j][0]), rtf(cct[j][1]));
            int l1 = l0 + 8;
            if (l1 < LMAX)
                *(float2*)&ctx[((size_t)(b*LMAX) + l1)*DMODEL + dc] =
                    make_float2(rtf(cct[j][2]), rtf(cct[j][3]));
        }
    }

    #pragma unroll
    for (int j = 0; j < 2; j++)
        #pragma unroll
        for (int mt = 0; mt < 4; mt++) {
            int col = (2*w + j)*8 + 2*q;
            int l0 = lt*TB + mt*16 + p;
            if (l0 < LMAX)
                *(float2*)&av_out[((size_t)(b*LMAX) + l0)*SEQ + col] =
                    make_float2(avacc[j][mt][0]*0.125f, avacc[j][mt][1]*0.125f);
            int l1 = l0 + 8;
            if (l1 < LMAX)
                *(float2*)&av_out[((size_t)(b*LMAX) + l1)*SEQ + col] =
                    make_float2(avacc[j][mt][2]*0.125f, avacc[j][mt][3]*0.125f);
        }
}

// ---------------- LayerNorm ----------
template<bool RND>
__global__ __launch_bounds__(128) void ln_kernel(
    const float* __restrict__ x, const float* __restrict__ g,
    const float* __restrict__ bb, float* __restrict__ y)
{
    __shared__ float ws[4], wss[4];
    int r = blockIdx.x;
    int tid = threadIdx.x;
    const float4* xr = (const float4*)(x + (size_t)r*DMODEL);
    float4 v = xr[tid];
    float s  = v.x + v.y + v.z + v.w;
    float ss = v.x*v.x + v.y*v.y + v.z*v.z + v.w*v.w;
    #pragma unroll
    for (int o = 16; o > 0; o >>= 1) {
        s  += __shfl_xor_sync(0xffffffffu, s,  o);
        ss += __shfl_xor_sync(0xffffffffu, ss, o);
    }
    int warp = tid >> 5, lane = tid & 31;
    if (lane == 0) { ws[warp] = s; wss[warp] = ss; }
    __syncthreads();
    float S  = ws[0] + ws[1] + ws[2] + ws[3];
    float SS = wss[0] + wss[1] + wss[2] + wss[3];
    float mean = S * (1.f/DMODEL);
    float var  = SS * (1.f/DMODEL) - mean*mean;
    float rstd = rsqrtf(var + 1e-5f);
    float4 gg = ((const float4*)g)[tid];
    float4 b4 = ((const float4*)bb)[tid];
    float4 o4;
    o4.x = (v.x - mean)*rstd*gg.x + b4.x;
    o4.y = (v.y - mean)*rstd*gg.y + b4.y;
    o4.z = (v.z - mean)*rstd*gg.z + b4.z;
    o4.w = (v.w - mean)*rstd*gg.w + b4.w;
    if (RND) { o4.x = rtf(o4.x); o4.y = rtf(o4.y); o4.z = rtf(o4.z); o4.w = rtf(o4.w); }
    ((float4*)(y + (size_t)r*DMODEL))[tid] = o4;
}

// ---------------- launch ----------------
extern "C" void kernel_launch(void* const* d_in, const int* in_sizes, int n_in,
                              void* d_out, int out_size)
{
    int off = (n_in >= 22) ? 0 : 2;
    const float* nodes  = (const float*)d_in[0];
    const int*   gb     = (const int*)  d_in[1];
    const float* cond   = (const float*)d_in[2];
    const int*   maskp  = (const int*)  d_in[3];
    const float* Wq     = (const float*)d_in[6-off];
    const float* bq     = (const float*)d_in[7-off];
    const float* Wk     = (const float*)d_in[8-off];
    const float* bk     = (const float*)d_in[9-off];
    const float* Wv     = (const float*)d_in[10-off];
    const float* bv     = (const float*)d_in[11-off];
    const float* in_w   = (const float*)d_in[12-off];
    const float* in_b   = (const float*)d_in[13-off];
    const float* Wo     = (const float*)d_in[14-off];
    const float* bo     = (const float*)d_in[15-off];
    const float* ln1g   = (const float*)d_in[16-off];
    const float* ln1b   = (const float*)d_in[17-off];
    const float* W1     = (const float*)d_in[18-off];
    const float* b1     = (const float*)d_in[19-off];
    const float* ln2g   = (const float*)d_in[20-off];
    const float* ln2b   = (const float*)d_in[21-off];
    float* out = (float*)d_out;
    float* av_out = out + (size_t)NN*DMODEL;

    float *p_dense, *p_qh, *p_kh, *p_vh, *p_ctx, *p_y, *p_x1, *p_h;
    float *p_Wq2, *p_Wk2, *p_Wv2, *p_Wo2, *p_W12, *p_cond;
    float *p_bq2, *p_bk2, *p_bv2;
    int *p_starts;
    cudaGetSymbolAddress((void**)&p_dense, g_dense);
    cudaGetSymbolAddress((void**)&p_qh, g_qh);
    cudaGetSymbolAddress((void**)&p_kh, g_kh);
    cudaGetSymbolAddress((void**)&p_vh, g_vh);
    cudaGetSymbolAddress((void**)&p_ctx, g_ctx);
    cudaGetSymbolAddress((void**)&p_y, g_y);
    cudaGetSymbolAddress((void**)&p_x1, g_x1);
    cudaGetSymbolAddress((void**)&p_h, g_h);
    cudaGetSymbolAddress((void**)&p_Wq2, g_Wq2);
    cudaGetSymbolAddress((void**)&p_Wk2, g_Wk2);
    cudaGetSymbolAddress((void**)&p_Wv2, g_Wv2);
    cudaGetSymbolAddress((void**)&p_Wo2, g_Wo2);
    cudaGetSymbolAddress((void**)&p_W12, g_W12);
    cudaGetSymbolAddress((void**)&p_cond, g_cond);
    cudaGetSymbolAddress((void**)&p_bq2, g_bq2);
    cudaGetSymbolAddress((void**)&p_bk2, g_bk2);
    cudaGetSymbolAddress((void**)&p_bv2, g_bv2);
    cudaGetSymbolAddress((void**)&p_starts, g_starts);

    // opt-in dynamic smem for gemms + attention
    cudaFuncSetAttribute(gemm_one<0,true>,  cudaFuncAttributeMaxDynamicSharedMemorySize, GEMM_SMEM);
    cudaFuncSetAttribute(gemm_one<1,false>, cudaFuncAttributeMaxDynamicSharedMemorySize, GEMM_SMEM);
    cudaFuncSetAttribute(gemm_one<2,false>, cudaFuncAttributeMaxDynamicSharedMemorySize, GEMM_SMEM);
    cudaFuncSetAttribute(gemm_kv,           cudaFuncAttributeMaxDynamicSharedMemorySize, GEMM_SMEM);
    cudaFuncSetAttribute(attn_mma,          cudaFuncAttributeMaxDynamicSharedMemorySize, ATT_SMEM);

    // 1) ragged bookkeeping + padded dense (fused zero+scatter)
    find_starts<<<(NN+255)/256, 256>>>(gb, p_starts, NN);
    pad_kernel<<<ROWS_Q, 128>>>(nodes, p_starts, p_dense);

    // 2) fold projections + bias combines + round remaining operands
    fold3_gemm<<<dim3(4,6,3), 256>>>(Wq, Wk, Wv, in_w, p_Wq2, p_Wk2, p_Wv2);
    bias3<<<dim3(1,3), 512>>>(bq, bk, bv, in_w, in_b, p_bq2, p_bk2, p_bv2);
    round3<<<dim3(192,3), 256>>>(cond, Wo, W1, p_cond, p_Wo2, p_W12);

    // 3) projections
    gemm_one<0,true><<<dim3(4,124), 256, GEMM_SMEM>>>(p_dense, p_Wq2, p_bq2, nullptr, p_qh, DMODEL, DMODEL);
    gemm_kv<<<dim3(4,32,2), 256, GEMM_SMEM>>>(p_cond, p_Wk2, p_Wv2, p_bk2, p_bv2, p_kh, p_vh);

    // 4) tensor-core attention
    attn_mma<<<dim3(16, BGR), 512, ATT_SMEM>>>(p_qh, p_kh, p_vh, maskp, p_ctx, av_out);

    // 5) out proj + residual, LN1, FFN, LN2
    gemm_one<1,false><<<dim3(4,124), 256, GEMM_SMEM>>>(p_ctx, p_Wo2, bo, p_dense, p_y, DMODEL, DMODEL);
    ln_kernel<true><<<ROWS_Q, 128>>>(p_y, ln1g, ln1b, p_x1);
    gemm_one<2,false><<<dim3(4,124), 256, GEMM_SMEM>>>(p_x1, p_W12, b1, p_x1, p_h, DMODEL, DMODEL);
    ln_kernel<false><<<ROWS_Q, 128>>>(p_h, ln2g, ln2b, p_y);

    // 6) ragged gather
    gather_kernel<<<NN, 128>>>(p_y, gb, p_starts, out);
}

// round 5
// speedup vs baseline: 3.4417x; 1.0194x over previous
#include <cuda_runtime.h>
#include <cuda_bf16.h>
#include <math.h>

// ---------------- problem constants ----------------
#define NN    12032
#define DMODEL 512
#define BGR   16
#define SEQ   256
#define NH    8
#define DH    64
#define LMAX  992
#define LATD  768
#define ROWS_Q  (BGR*LMAX)   // 15872
#define ROWS_KV (BGR*SEQ)    // 4096

// ---------------- scratch ----------
__device__ float g_dense[ROWS_Q*DMODEL];
__device__ float g_qh   [ROWS_Q*DMODEL];
__device__ float g_ctx  [ROWS_Q*DMODEL];
__device__ float g_y    [ROWS_Q*DMODEL];
__device__ float g_x1   [ROWS_Q*DMODEL];
__device__ float g_h    [ROWS_Q*DMODEL];
__device__ float g_kh   [ROWS_KV*DMODEL];
__device__ float g_vh   [ROWS_KV*DMODEL];
__device__ float g_Wq2  [DMODEL*DMODEL];
__device__ float g_Wk2  [LATD*DMODEL];
__device__ float g_Wv2  [LATD*DMODEL];
__device__ float g_Wo2  [DMODEL*DMODEL];
__device__ float g_W12  [DMODEL*DMODEL];
__device__ float g_cond [BGR*SEQ*LATD];
__device__ float g_bq2  [DMODEL];
__device__ float g_bk2  [DMODEL];
__device__ float g_bv2  [DMODEL];
__device__ int   g_starts[BGR];

// ---------------- helpers ----------------
__device__ __forceinline__ unsigned f2tf32(float x) {
    unsigned y;
    asm("cvt.rna.tf32.f32 %0, %1;" : "=r"(y) : "f"(x));
    return y;
}
__device__ __forceinline__ float rtf(float x) { return __uint_as_float(f2tf32(x)); }

__device__ __forceinline__ void mma_tf32(float c[4],
    unsigned a0, unsigned a1, unsigned a2, unsigned a3,
    unsigned b0, unsigned b1)
{
    asm volatile(
        "mma.sync.aligned.m16n8k8.row.col.f32.tf32.tf32.f32 "
        "{%0,%1,%2,%3}, {%4,%5,%6,%7}, {%8,%9}, {%0,%1,%2,%3};"
        : "+f"(c[0]), "+f"(c[1]), "+f"(c[2]), "+f"(c[3])
        : "r"(a0), "r"(a1), "r"(a2), "r"(a3), "r"(b0), "r"(b1));
}

#define CP16(dst, src) asm volatile("cp.async.cg.shared.global [%0], [%1], 16;" :: "r"(dst), "l"(src))

__global__ void find_starts(const int* __restrict__ gb, int* starts, int n) {
    int i = blockIdx.x*blockDim.x + threadIdx.x;
    if (i < n) {
        if (i == 0 || gb[i] != gb[i-1]) starts[gb[i]] = i;
    }
}

// one block per dense row: copy rounded node or write zeros
__global__ __launch_bounds__(128) void pad_kernel(
    const float* __restrict__ nodes, const int* __restrict__ starts,
    float* __restrict__ dense)
{
    int r = blockIdx.x;
    int b = r / LMAX, pp = r - b*LMAX;
    int s = starts[b];
    int e = (b == BGR-1) ? NN : starts[b+1];
    int i = s + pp;
    float4 v = make_float4(0.f, 0.f, 0.f, 0.f);
    if (i < e) {
        v = ((const float4*)(nodes + (size_t)i*DMODEL))[threadIdx.x];
        v.x = rtf(v.x); v.y = rtf(v.y); v.z = rtf(v.z); v.w = rtf(v.w);
    }
    ((float4*)(dense + (size_t)r*DMODEL))[threadIdx.x] = v;
}

// batched tf32 round-copy of the three remaining raw operands
__global__ void round3(const float* __restrict__ cond, const float* __restrict__ Wo,
                       const float* __restrict__ W1,
                       float* __restrict__ dc, float* __restrict__ dwo, float* __restrict__ dw1)
{
    int z = blockIdx.y;
    const float* s = (z==0) ? cond : (z==1) ? Wo : W1;
    float* d = (z==0) ? dc : (z==1) ? dwo : dw1;
    int n4 = ((z==0) ? BGR*SEQ*LATD : DMODEL*DMODEL) >> 2;
    int i = blockIdx.x*blockDim.x + threadIdx.x;
    int stride = gridDim.x*blockDim.x;
    for (; i < n4; i += stride) {
        float4 v = ((const float4*)s)[i];
        v.x = rtf(v.x); v.y = rtf(v.y); v.z = rtf(v.z); v.w = rtf(v.w);
        ((float4*)d)[i] = v;
    }
}

// parallel bias combine: grid (8, 3), 512 threads.
// block handles 64 output columns; i-dim split 8 ways, smem-reduced.
__global__ __launch_bounds__(512) void bias3p(
    const float* __restrict__ bq, const float* __restrict__ bk,
    const float* __restrict__ bv, const float* __restrict__ inw,
    const float* __restrict__ inb,
    float* __restrict__ oq, float* __restrict__ ok, float* __restrict__ ov)
{
    __shared__ float red[8][64];
    int z = blockIdx.y;
    const float* bin = (z==0) ? bq : (z==1) ? bk : bv;
    const float* W = inw + (size_t)z*DMODEL*DMODEL;
    const float* ab = inb + z*DMODEL;
    float* outp = (z==0) ? oq : (z==1) ? ok : ov;
    int jj = threadIdx.x & 63;
    int r  = threadIdx.x >> 6;          // 0..7
    int j  = blockIdx.x*64 + jj;
    float a = 0.f;
    #pragma unroll 8
    for (int i = r*64; i < r*64 + 64; i++)
        a += bin[i]*W[(size_t)i*DMODEL + j];
    red[r][jj] = a;
    __syncthreads();
    if (r == 0) {
        float s = ab[j];
        #pragma unroll
        for (int k = 0; k < 8; k++) s += red[k][jj];
        outp[j] = s;
    }
}

// ---------------- fold3: three small weight GEMMs in one launch -------------
#define SMP 132

__global__ __launch_bounds__(256) void fold3_gemm(
    const float* __restrict__ Wq, const float* __restrict__ Wk,
    const float* __restrict__ Wv, const float* __restrict__ inw,
    float* __restrict__ Cq, float* __restrict__ Ck, float* __restrict__ Cv)
{
    int z = blockIdx.z;
    int M = (z == 0) ? DMODEL : LATD;
    if ((int)blockIdx.y*128 >= M) return;
    const float* A = (z==0) ? Wq : (z==1) ? Wk : Wv;
    const float* B = inw + (size_t)z*DMODEL*DMODEL;
    float* C = (z==0) ? Cq : (z==1) ? Ck : Cv;
    const int N = DMODEL, K = DMODEL;

    __shared__ unsigned As[16][SMP];
    __shared__ unsigned Bs[16][SMP];
    int tid = threadIdx.x;
    int warp = tid >> 5, lane = tid & 31;
    int warp_m = warp & 3, warp_n = warp >> 2;
    int p = lane >> 2, q = lane & 3;
    int blockM = blockIdx.y * 128;
    int blockN = blockIdx.x * 128;

    int ia0 = tid*2, ia1 = tid*2 + 1;
    int arow0 = ia0 >> 2, akq0 = ia0 & 3;
    int arow1 = ia1 >> 2, akq1 = ia1 & 3;
    int bk0 = ia0 >> 5, bn0 = ia0 & 31;
    int bk1 = ia1 >> 5, bn1 = ia1 & 31;

    const float* Ap0 = A + (size_t)(blockM + arow0)*K + akq0*4;
    const float* Ap1 = A + (size_t)(blockM + arow1)*K + akq1*4;
    const float* Bp0 = B + (size_t)bk0*N + blockN + bn0*4;
    const float* Bp1 = B + (size_t)bk1*N + blockN + bn1*4;

    float acc[2][8][4];
    #pragma unroll
    for (int mt = 0; mt < 2; mt++)
        #pragma unroll
        for (int nt = 0; nt < 8; nt++)
            #pragma unroll
            for (int i = 0; i < 4; i++) acc[mt][nt][i] = 0.f;

    float4 av0 = *(const float4*)(Ap0);
    float4 av1 = *(const float4*)(Ap1);
    float4 bv0 = *(const float4*)(Bp0);
    float4 bv1 = *(const float4*)(Bp1);

    for (int kt = 16; kt <= K; kt += 16) {
        As[akq0*4+0][arow0] = f2tf32(av0.x);
        As[akq0*4+1][arow0] = f2tf32(av0.y);
        As[akq0*4+2][arow0] = f2tf32(av0.z);
        As[akq0*4+3][arow0] = f2tf32(av0.w);
        As[akq1*4+0][arow1] = f2tf32(av1.x);
        As[akq1*4+1][arow1] = f2tf32(av1.y);
        As[akq1*4+2][arow1] = f2tf32(av1.z);
        As[akq1*4+3][arow1] = f2tf32(av1.w);
        {
            uint4 t0, t1;
            t0.x = f2tf32(bv0.x); t0.y = f2tf32(bv0.y);
            t0.z = f2tf32(bv0.z); t0.w = f2tf32(bv0.w);
            t1.x = f2tf32(bv1.x); t1.y = f2tf32(bv1.y);
            t1.z = f2tf32(bv1.z); t1.w = f2tf32(bv1.w);
            *(uint4*)&Bs[bk0][bn0*4] = t0;
            *(uint4*)&Bs[bk1][bn1*4] = t1;
        }
        __syncthreads();
        if (kt < K) {
            av0 = *(const float4*)(Ap0 + kt);
            av1 = *(const float4*)(Ap1 + kt);
            bv0 = *(const float4*)(Bp0 + (size_t)kt*N);
            bv1 = *(const float4*)(Bp1 + (size_t)kt*N);
        }
        #pragma unroll
        for (int kk = 0; kk < 16; kk += 8) {
            unsigned afr[2][4];
            #pragma unroll
            for (int mt = 0; mt < 2; mt++) {
                int mb = warp_m*32 + mt*16;
                afr[mt][0] = As[kk+q  ][mb + p];
                afr[mt][1] = As[kk+q  ][mb + p + 8];
                afr[mt][2] = As[kk+q+4][mb + p];
                afr[mt][3] = As[kk+q+4][mb + p + 8];
            }
            unsigned bfr[8][2];
            #pragma unroll
            for (int nt = 0; nt < 8; nt++) {
                int nb = warp_n*64 + nt*8;
                bfr[nt][0] = Bs[kk+q  ][nb + p];
                bfr[nt][1] = Bs[kk+q+4][nb + p];
            }
            #pragma unroll
            for (int mt = 0; mt < 2; mt++)
                #pragma unroll
                for (int nt = 0; nt < 8; nt++)
                    mma_tf32(acc[mt][nt], afr[mt][0], afr[mt][1], afr[mt][2], afr[mt][3],
                             bfr[nt][0], bfr[nt][1]);
        }
        __syncthreads();
    }

    #pragma unroll
    for (int mt = 0; mt < 2; mt++) {
        int r0 = blockM + warp_m*32 + mt*16 + p;
        #pragma unroll
        for (int nt = 0; nt < 8; nt++) {
            int c0 = blockN + warp_n*64 + nt*8 + 2*q;
            size_t o0 = (size_t)r0*N + c0;
            size_t o1 = (size_t)(r0+8)*N + c0;
            *(float2*)(C + o0) = make_float2(rtf(acc[mt][nt][0]), rtf(acc[mt][nt][1]));
            *(float2*)(C + o1) = make_float2(rtf(acc[mt][nt][2]), rtf(acc[mt][nt][3]));
        }
    }
}

// ---------------- 3-stage cp.async TF32 GEMM ----------------
#define AS_STRIDE 20
#define BS_STRIDE 136
#define GEMM_SMEM ((3*128*AS_STRIDE + 3*16*BS_STRIDE)*4)

template<int MODE, bool RND>
__device__ __forceinline__ void gemm_body(
    const float* __restrict__ A, const float* __restrict__ B,
    const float* __restrict__ bias, const float* __restrict__ Dm,
    float* __restrict__ C, int N, int K, float* smem)
{
    float* As = smem;
    float* Bs = smem + 3*128*AS_STRIDE;

    int tid = threadIdx.x;
    int warp = tid >> 5, lane = tid & 31;
    int warp_m = warp & 3, warp_n = warp >> 2;
    int p = lane >> 2, q = lane & 3;
    int blockM = blockIdx.y * 128;
    int blockN = blockIdx.x * 128;

    int c0 = tid*2, c1 = c0 + 1;
    int ar0 = c0 >> 2, ak0 = (c0 & 3)*4;
    int ar1 = c1 >> 2, ak1 = (c1 & 3)*4;
    int bk0 = c0 >> 5, bn0 = (c0 & 31)*4;
    int bk1 = c1 >> 5, bn1 = (c1 & 31)*4;

    const float* gA0 = A + (size_t)(blockM + ar0)*K + ak0;
    const float* gA1 = A + (size_t)(blockM + ar1)*K + ak1;
    const float* gB0 = B + (size_t)bk0*N + blockN + bn0;
    const float* gB1 = B + (size_t)bk1*N + blockN + bn1;

    unsigned sa = (unsigned)__cvta_generic_to_shared(As);
    unsigned sb = (unsigned)__cvta_generic_to_shared(Bs);
    unsigned dA0[3], dA1[3], dB0[3], dB1[3];
    #pragma unroll
    for (int s = 0; s < 3; s++) {
        dA0[s] = sa + (s*128*AS_STRIDE + ar0*AS_STRIDE + ak0)*4;
        dA1[s] = sa + (s*128*AS_STRIDE + ar1*AS_STRIDE + ak1)*4;
        dB0[s] = sb + (s*16*BS_STRIDE + bk0*BS_STRIDE + bn0)*4;
        dB1[s] = sb + (s*16*BS_STRIDE + bk1*BS_STRIDE + bn1)*4;
    }

    float acc[2][8][4];
    #pragma unroll
    for (int mt = 0; mt < 2; mt++)
        #pragma unroll
        for (int nt = 0; nt < 8; nt++)
            #pragma unroll
            for (int i = 0; i < 4; i++) acc[mt][nt][i] = 0.f;

    CP16(dA0[0], gA0); CP16(dA1[0], gA1);
    CP16(dB0[0], gB0); CP16(dB1[0], gB1);
    asm volatile("cp.async.commit_group;");
    CP16(dA0[1], gA0 + 16); CP16(dA1[1], gA1 + 16);
    CP16(dB0[1], gB0 + (size_t)16*N); CP16(dB1[1], gB1 + (size_t)16*N);
    asm volatile("cp.async.commit_group;");

    int nk = K >> 4;
    int sc = 0, sp = 2;
    for (int t = 0; t < nk; t++) {
        asm volatile("cp.async.wait_group 1;");
        __syncthreads();
        if (t + 2 < nk) {
            int kt = (t + 2) << 4;
            CP16(dA0[sp], gA0 + kt); CP16(dA1[sp], gA1 + kt);
            CP16(dB0[sp], gB0 + (size_t)kt*N); CP16(dB1[sp], gB1 + (size_t)kt*N);
        }
        asm volatile("cp.async.commit_group;");
        const float* as = As + sc*128*AS_STRIDE;
        const float* bs = Bs + sc*16*BS_STRIDE;
        #pragma unroll
        for (int kk = 0; kk < 16; kk += 8) {
            unsigned afr[2][4];
            #pragma unroll
            for (int mt = 0; mt < 2; mt++) {
                int mb = warp_m*32 + mt*16;
                afr[mt][0] = __float_as_uint(as[(mb+p  )*AS_STRIDE + kk+q  ]);
                afr[mt][1] = __float_as_uint(as[(mb+p+8)*AS_STRIDE + kk+q  ]);
                afr[mt][2] = __float_as_uint(as[(mb+p  )*AS_STRIDE + kk+q+4]);
                afr[mt][3] = __float_as_uint(as[(mb+p+8)*AS_STRIDE + kk+q+4]);
            }
            unsigned bfr[8][2];
            #pragma unroll
            for (int nt = 0; nt < 8; nt++) {
                int nb = warp_n*64 + nt*8;
                bfr[nt][0] = __float_as_uint(bs[(kk+q  )*BS_STRIDE + nb+p]);
                bfr[nt][1] = __float_as_uint(bs[(kk+q+4)*BS_STRIDE + nb+p]);
            }
            #pragma unroll
            for (int mt = 0; mt < 2; mt++)
                #pragma unroll
                for (int nt = 0; nt < 8; nt++)
                    mma_tf32(acc[mt][nt], afr[mt][0], afr[mt][1], afr[mt][2], afr[mt][3],
                             bfr[nt][0], bfr[nt][1]);
        }
        sc++; if (sc == 3) sc = 0;
        sp++; if (sp == 3) sp = 0;
    }

    #pragma unroll
    for (int mt = 0; mt < 2; mt++) {
        int r0 = blockM + warp_m*32 + mt*16 + p;
        #pragma unroll
        for (int nt = 0; nt < 8; nt++) {
            int c0c = blockN + warp_n*64 + nt*8 + 2*q;
            float b0 = 0.f, b1 = 0.f;
            if (bias) { b0 = bias[c0c]; b1 = bias[c0c+1]; }
            float v0 = acc[mt][nt][0] + b0;
            float v1 = acc[mt][nt][1] + b1;
            float v2 = acc[mt][nt][2] + b0;
            float v3 = acc[mt][nt][3] + b1;
            size_t o0 = (size_t)r0*N + c0c;
            size_t o1 = (size_t)(r0+8)*N + c0c;
            if (MODE == 1) {
                float2 d0 = *(const float2*)(Dm + o0);
                float2 d1 = *(const float2*)(Dm + o1);
                v0 += d0.x; v1 += d0.y; v2 += d1.x; v3 += d1.y;
            }
            if (MODE == 2) {
                v0 = (v0 > 0.f) ? v0 : 0.01f*v0;
                v1 = (v1 > 0.f) ? v1 : 0.01f*v1;
                v2 = (v2 > 0.f) ? v2 : 0.01f*v2;
                v3 = (v3 > 0.f) ? v3 : 0.01f*v3;
                float2 d0 = *(const float2*)(Dm + o0);
                float2 d1 = *(const float2*)(Dm + o1);
                v0 += d0.x; v1 += d0.y; v2 += d1.x; v3 += d1.y;
            }
            if (RND) { v0 = rtf(v0); v1 = rtf(v1); v2 = rtf(v2); v3 = rtf(v3); }
            *(float2*)(C + o0) = make_float2(v0, v1);
            *(float2*)(C + o1) = make_float2(v2, v3);
        }
    }
}

template<int MODE, bool RND>
__global__ __launch_bounds__(256, 2) void gemm_one(
    const float* __restrict__ A, const float* __restrict__ B,
    const float* __restrict__ bias, const float* __restrict__ Dm,
    float* __restrict__ C, int N, int K)
{
    extern __shared__ float smem[];
    gemm_body<MODE, RND>(A, B, bias, Dm, C, N, K, smem);
}

__global__ __launch_bounds__(256, 2) void gemm_kv(
    const float* __restrict__ cond,
    const float* __restrict__ Wk2, const float* __restrict__ Wv2,
    const float* __restrict__ bk2, const float* __restrict__ bv2,
    float* __restrict__ kh, float* __restrict__ vh)
{
    extern __shared__ float smem[];
    const float* B = blockIdx.z ? Wv2 : Wk2;
    const float* bias = blockIdx.z ? bv2 : bk2;
    float* C = blockIdx.z ? vh : kh;
    gemm_body<0, true>(cond, B, bias, nullptr, C, DMODEL, LATD, smem);
}

// ---------------- tensor-core attention ----------------
#define TB   64
#define KSTR 68
#define VSTR 72
#define PSTR 260
#define ATT_SMEM ((SEQ*KSTR + SEQ*VSTR + TB*PSTR)*4 + SEQ*4)

__global__ __launch_bounds__(512, 1) void attn_mma(
    const float* __restrict__ qh, const float* __restrict__ kh,
    const float* __restrict__ vh, const int* __restrict__ maskp,
    float* __restrict__ ctx, float* __restrict__ av_out)
{
    extern __shared__ float sm[];
    float* sK = sm;
    float* sV = sK + SEQ*KSTR;
    float* sU = sV + SEQ*VSTR;
    int* sMask = (int*)(sU + TB*PSTR);

    int b = blockIdx.y, lt = blockIdx.x;
    int tid = threadIdx.x;
    int w = tid >> 5, lane = tid & 31;
    int p = lane >> 2, q = lane & 3;

    if (tid < SEQ) sMask[tid] = maskp[b*SEQ + tid];

    float avacc[2][4][4];
    #pragma unroll
    for (int j = 0; j < 2; j++)
        #pragma unroll
        for (int mt = 0; mt < 4; mt++)
            #pragma unroll
            for (int i = 0; i < 4; i++) avacc[j][mt][i] = 0.f;

    for (int h = 0; h < NH; h++) {
        __syncthreads();
        for (int idx = tid; idx < SEQ*DH; idx += 512) {
            int s = idx >> 6, d = idx & 63;
            size_t g = ((size_t)(b*SEQ + s))*DMODEL + h*DH + d;
            sK[s*KSTR + d] = kh[g];
            sV[s*VSTR + d] = vh[g];
        }
        for (int idx = tid; idx < TB*DH; idx += 512) {
            int r = idx >> 6, d = idx & 63;
            int l = lt*TB + r; if (l > LMAX-1) l = LMAX-1;
            sU[r*KSTR + d] = qh[((size_t)(b*LMAX) + l)*DMODEL + h*DH + d];
        }
        __syncthreads();

        float csc[2][4][4];
        #pragma unroll
        for (int j = 0; j < 2; j++)
            #pragma unroll
            for (int mt = 0; mt < 4; mt++)
                #pragma unroll
                for (int i = 0; i < 4; i++) csc[j][mt][i] = 0.f;
        #pragma unroll
        for (int k = 0; k < 8; k++) {
            int kc = k*8 + q;
            unsigned bf0[2], bf1[2];
            #pragma unroll
            for (int j = 0; j < 2; j++) {
                int sc = (2*w + j)*8 + p;
                bf0[j] = __float_as_uint(sK[sc*KSTR + kc]);
                bf1[j] = __float_as_uint(sK[sc*KSTR + kc + 4]);
            }
            #pragma unroll
            for (int mt = 0; mt < 4; mt++) {
                int r0 = mt*16 + p;
                unsigned a0 = __float_as_uint(sU[r0*KSTR + kc]);
                unsigned a1 = __float_as_uint(sU[(r0+8)*KSTR + kc]);
                unsigned a2 = __float_as_uint(sU[r0*KSTR + kc + 4]);
                unsigned a3 = __float_as_uint(sU[(r0+8)*KSTR + kc + 4]);
                mma_tf32(csc[0][mt], a0, a1, a2, a3, bf0[0], bf1[0]);
                mma_tf32(csc[1][mt], a0, a1, a2, a3, bf0[1], bf1[1]);
            }
        }
        __syncthreads();
        #pragma unroll
        for (int j = 0; j < 2; j++)
            #pragma unroll
            for (int mt = 0; mt < 4; mt++) {
                int row = mt*16 + p;
                int col = (2*w + j)*8 + 2*q;
                *(float2*)&sU[row*PSTR + col]     = make_float2(csc[j][mt][0], csc[j][mt][1]);
                *(float2*)&sU[(row+8)*PSTR + col] = make_float2(csc[j][mt][2], csc[j][mt][3]);
            }
        __syncthreads();
        #pragma unroll
        for (int rr = 0; rr < 4; rr++) {
            int row = 4*w + rr;
            float v[8];
            float m = -1e30f;
            #pragma unroll
            for (int jj = 0; jj < 8; jj++) {
                int s = lane + 32*jj;
                float x = sMask[s] ? -1e30f : sU[row*PSTR + s]*0.125f;
                v[jj] = x;
                m = fmaxf(m, x);
            }
            #pragma unroll
            for (int o = 16; o > 0; o >>= 1) m = fmaxf(m, __shfl_xor_sync(0xffffffffu, m, o));
            float sum = 0.f;
            #pragma unroll
            for (int jj = 0; jj < 8; jj++) { v[jj] = __expf(v[jj] - m); sum += v[jj]; }
            #pragma unroll
            for (int o = 16; o > 0; o >>= 1) sum += __shfl_xor_sync(0xffffffffu, sum, o);
            float inv = 1.f/sum;
            #pragma unroll
            for (int jj = 0; jj < 8; jj++)
                sU[row*PSTR + lane + 32*jj] = rtf(v[jj]*inv);
        }
        __syncthreads();
        #pragma unroll
        for (int j = 0; j < 2; j++)
            #pragma unroll
            for (int mt = 0; mt < 4; mt++) {
                int row = mt*16 + p;
                int col = (2*w + j)*8 + 2*q;
                avacc[j][mt][0] += sU[row*PSTR + col];
                avacc[j][mt][1] += sU[row*PSTR + col + 1];
                avacc[j][mt][2] += sU[(row+8)*PSTR + col];
                avacc[j][mt][3] += sU[(row+8)*PSTR + col + 1];
            }
        int mtw = w & 3, nt0 = w >> 2;
        float cct[2][4];
        #pragma unroll
        for (int j = 0; j < 2; j++)
            #pragma unroll
            for (int i = 0; i < 4; i++) cct[j][i] = 0.f;
        #pragma unroll 8
        for (int k = 0; k < 32; k++) {
            int sc = k*8 + q;
            int r0 = mtw*16 + p;
            unsigned a0 = __float_as_uint(sU[r0*PSTR + sc]);
            unsigned a1 = __float_as_uint(sU[(r0+8)*PSTR + sc]);
            unsigned a2 = __float_as_uint(sU[r0*PSTR + sc + 4]);
            unsigned a3 = __float_as_uint(sU[(r0+8)*PSTR + sc + 4]);
            #pragma unroll
            for (int j = 0; j < 2; j++) {
                int dc = (nt0 + 4*j)*8 + p;
                unsigned b0 = __float_as_uint(sV[sc*VSTR + dc]);
                unsigned b1 = __float_as_uint(sV[(sc+4)*VSTR + dc]);
                mma_tf32(cct[j], a0, a1, a2, a3, b0, b1);
            }
        }
        #pragma unroll
        for (int j = 0; j < 2; j++) {
            int dc = h*DH + (nt0 + 4*j)*8 + 2*q;
            int l0 = lt*TB + mtw*16 + p;
            if (l0 < LMAX)
                *(float2*)&ctx[((size_t)(b*LMAX) + l0)*DMODEL + dc] =
                    make_float2(rtf(cct[j][0]), rtf(cct[j][1]));
            int l1 = l0 + 8;
            if (l1 < LMAX)
                *(float2*)&ctx[((size_t)(b*LMAX) + l1)*DMODEL + dc] =
                    make_float2(rtf(cct[j][2]), rtf(cct[j][3]));
        }
    }

    #pragma unroll
    for (int j = 0; j < 2; j++)
        #pragma unroll
        for (int mt = 0; mt < 4; mt++) {
            int col = (2*w + j)*8 + 2*q;
            int l0 = lt*TB + mt*16 + p;
            if (l0 < LMAX)
                *(float2*)&av_out[((size_t)(b*LMAX) + l0)*SEQ + col] =
                    make_float2(avacc[j][mt][0]*0.125f, avacc[j][mt][1]*0.125f);
            int l1 = l0 + 8;
            if (l1 < LMAX)
                *(float2*)&av_out[((size_t)(b*LMAX) + l1)*SEQ + col] =
                    make_float2(avacc[j][mt][2]*0.125f, avacc[j][mt][3]*0.125f);
        }
}

// ---------------- LayerNorm (full padded matrix) ----------
template<bool RND>
__global__ __launch_bounds__(128) void ln_kernel(
    const float* __restrict__ x, const float* __restrict__ g,
    const float* __restrict__ bb, float* __restrict__ y)
{
    __shared__ float ws[4], wss[4];
    int r = blockIdx.x;
    int tid = threadIdx.x;
    const float4* xr = (const float4*)(x + (size_t)r*DMODEL);
    float4 v = xr[tid];
    float s  = v.x + v.y + v.z + v.w;
    float ss = v.x*v.x + v.y*v.y + v.z*v.z + v.w*v.w;
    #pragma unroll
    for (int o = 16; o > 0; o >>= 1) {
        s  += __shfl_xor_sync(0xffffffffu, s,  o);
        ss += __shfl_xor_sync(0xffffffffu, ss, o);
    }
    int warp = tid >> 5, lane = tid & 31;
    if (lane == 0) { ws[warp] = s; wss[warp] = ss; }
    __syncthreads();
    float S  = ws[0] + ws[1] + ws[2] + ws[3];
    float SS = wss[0] + wss[1] + wss[2] + wss[3];
    float mean = S * (1.f/DMODEL);
    float var  = SS * (1.f/DMODEL) - mean*mean;
    float rstd = rsqrtf(var + 1e-5f);
    float4 gg = ((const float4*)g)[tid];
    float4 b4 = ((const float4*)bb)[tid];
    float4 o4;
    o4.x = (v.x - mean)*rstd*gg.x + b4.x;
    o4.y = (v.y - mean)*rstd*gg.y + b4.y;
    o4.z = (v.z - mean)*rstd*gg.z + b4.z;
    o4.w = (v.w - mean)*rstd*gg.w + b4.w;
    if (RND) { o4.x = rtf(o4.x); o4.y = rtf(o4.y); o4.z = rtf(o4.z); o4.w = rtf(o4.w); }
    ((float4*)(y + (size_t)r*DMODEL))[tid] = o4;
}

// ---------------- fused LN2 + ragged gather: only real rows ----------
__global__ __launch_bounds__(128) void ln_gather(
    const float* __restrict__ x, const int* __restrict__ gb,
    const int* __restrict__ starts,
    const float* __restrict__ g, const float* __restrict__ bb,
    float* __restrict__ out)
{
    __shared__ float ws[4], wss[4];
    int i = blockIdx.x;
    int b = gb[i];
    int pp = i - starts[b];
    size_t row = (size_t)b*LMAX + pp;
    int tid = threadIdx.x;
    float4 v = ((const float4*)(x + row*DMODEL))[tid];
    float s  = v.x + v.y + v.z + v.w;
    float ss = v.x*v.x + v.y*v.y + v.z*v.z + v.w*v.w;
    #pragma unroll
    for (int o = 16; o > 0; o >>= 1) {
        s  += __shfl_xor_sync(0xffffffffu, s,  o);
        ss += __shfl_xor_sync(0xffffffffu, ss, o);
    }
    int warp = tid >> 5, lane = tid & 31;
    if (lane == 0) { ws[warp] = s; wss[warp] = ss; }
    __syncthreads();
    float S  = ws[0] + ws[1] + ws[2] + ws[3];
    float SS = wss[0] + wss[1] + wss[2] + wss[3];
    float mean = S * (1.f/DMODEL);
    float var  = SS * (1.f/DMODEL) - mean*mean;
    float rstd = rsqrtf(var + 1e-5f);
    float4 gg = ((const float4*)g)[tid];
    float4 b4 = ((const float4*)bb)[tid];
    float4 o4;
    o4.x = (v.x - mean)*rstd*gg.x + b4.x;
    o4.y = (v.y - mean)*rstd*gg.y + b4.y;
    o4.z = (v.z - mean)*rstd*gg.z + b4.z;
    o4.w = (v.w - mean)*rstd*gg.w + b4.w;
    ((float4*)(out + (size_t)i*DMODEL))[tid] = o4;
}

// ---------------- launch ----------------
extern "C" void kernel_launch(void* const* d_in, const int* in_sizes, int n_in,
                              void* d_out, int out_size)
{
    int off = (n_in >= 22) ? 0 : 2;
    const float* nodes  = (const float*)d_in[0];
    const int*   gb     = (const int*)  d_in[1];
    const float* cond   = (const float*)d_in[2];
    const int*   maskp  = (const int*)  d_in[3];
    const float* Wq     = (const float*)d_in[6-off];
    const float* bq     = (const float*)d_in[7-off];
    const float* Wk     = (const float*)d_in[8-off];
    const float* bk     = (const float*)d_in[9-off];
    const float* Wv     = (const float*)d_in[10-off];
    const float* bv     = (const float*)d_in[11-off];
    const float* in_w   = (const float*)d_in[12-off];
    const float* in_b   = (const float*)d_in[13-off];
    const float* Wo     = (const float*)d_in[14-off];
    const float* bo     = (const float*)d_in[15-off];
    const float* ln1g   = (const float*)d_in[16-off];
    const float* ln1b   = (const float*)d_in[17-off];
    const float* W1     = (const float*)d_in[18-off];
    const float* b1     = (const float*)d_in[19-off];
    const float* ln2g   = (const float*)d_in[20-off];
    const float* ln2b   = (const float*)d_in[21-off];
    float* out = (float*)d_out;
    float* av_out = out + (size_t)NN*DMODEL;

    float *p_dense, *p_qh, *p_kh, *p_vh, *p_ctx, *p_y, *p_x1, *p_h;
    float *p_Wq2, *p_Wk2, *p_Wv2, *p_Wo2, *p_W12, *p_cond;
    float *p_bq2, *p_bk2, *p_bv2;
    int *p_starts;
    cudaGetSymbolAddress((void**)&p_dense, g_dense);
    cudaGetSymbolAddress((void**)&p_qh, g_qh);
    cudaGetSymbolAddress((void**)&p_kh, g_kh);
    cudaGetSymbolAddress((void**)&p_vh, g_vh);
    cudaGetSymbolAddress((void**)&p_ctx, g_ctx);
    cudaGetSymbolAddress((void**)&p_y, g_y);
    cudaGetSymbolAddress((void**)&p_x1, g_x1);
    cudaGetSymbolAddress((void**)&p_h, g_h);
    cudaGetSymbolAddress((void**)&p_Wq2, g_Wq2);
    cudaGetSymbolAddress((void**)&p_Wk2, g_Wk2);
    cudaGetSymbolAddress((void**)&p_Wv2, g_Wv2);
    cudaGetSymbolAddress((void**)&p_Wo2, g_Wo2);
    cudaGetSymbolAddress((void**)&p_W12, g_W12);
    cudaGetSymbolAddress((void**)&p_cond, g_cond);
    cudaGetSymbolAddress((void**)&p_bq2, g_bq2);
    cudaGetSymbolAddress((void**)&p_bk2, g_bk2);
    cudaGetSymbolAddress((void**)&p_bv2, g_bv2);
    cudaGetSymbolAddress((void**)&p_starts, g_starts);

    cudaFuncSetAttribute(gemm_one<0,true>,  cudaFuncAttributeMaxDynamicSharedMemorySize, GEMM_SMEM);
    cudaFuncSetAttribute(gemm_one<1,false>, cudaFuncAttributeMaxDynamicSharedMemorySize, GEMM_SMEM);
    cudaFuncSetAttribute(gemm_one<2,false>, cudaFuncAttributeMaxDynamicSharedMemorySize, GEMM_SMEM);
    cudaFuncSetAttribute(gemm_kv,           cudaFuncAttributeMaxDynamicSharedMemorySize, GEMM_SMEM);
    cudaFuncSetAttribute(attn_mma,          cudaFuncAttributeMaxDynamicSharedMemorySize, ATT_SMEM);

    // ---- ordered so launch #4 == gemm_kv (profiled next round) ----
    // 1) round remaining operands (independent)
    round3<<<dim3(192,3), 256>>>(cond, Wo, W1, p_cond, p_Wo2, p_W12);
    // 2) fold projection weights
    fold3_gemm<<<dim3(4,6,3), 256>>>(Wq, Wk, Wv, in_w, p_Wq2, p_Wk2, p_Wv2);
    // 3) parallel bias combines
    bias3p<<<dim3(8,3), 512>>>(bq, bk, bv, in_w, in_b, p_bq2, p_bk2, p_bv2);
    // 4) K/V projections  <-- profiled launch
    gemm_kv<<<dim3(4,32,2), 256, GEMM_SMEM>>>(p_cond, p_Wk2, p_Wv2, p_bk2, p_bv2, p_kh, p_vh);
    // 5) ragged bookkeeping
    find_starts<<<(NN+255)/256, 256>>>(gb, p_starts, NN);
    // 6) dense padding (fused zero+scatter, rounded)
    pad_kernel<<<ROWS_Q, 128>>>(nodes, p_starts, p_dense);
    // 7) Q projection
    gemm_one<0,true><<<dim3(4,124), 256, GEMM_SMEM>>>(p_dense, p_Wq2, p_bq2, nullptr, p_qh, DMODEL, DMODEL);
    // 8) attention
    attn_mma<<<dim3(16, BGR), 512, ATT_SMEM>>>(p_qh, p_kh, p_vh, maskp, p_ctx, av_out);
    // 9) out proj + residual
    gemm_one<1,false><<<dim3(4,124), 256, GEMM_SMEM>>>(p_ctx, p_Wo2, bo, p_dense, p_y, DMODEL, DMODEL);
    // 10) LN1
    ln_kernel<true><<<ROWS_Q, 128>>>(p_y, ln1g, ln1b, p_x1);
    // 11) FFN + leaky + residual
    gemm_one<2,false><<<dim3(4,124), 256, GEMM_SMEM>>>(p_x1, p_W12, b1, p_x1, p_h, DMODEL, DMODEL);
    // 12) LN2 fused with ragged gather (real rows only)
    ln_gather<<<NN, 128>>>(p_h, gb, p_starts, ln2g, ln2b, out);
}

// round 6
// speedup vs baseline: 3.5345x; 1.0269x over previous
#include <cuda_runtime.h>
#include <cuda_bf16.h>
#include <math.h>

// ---------------- problem constants ----------------
#define NN    12032
#define DMODEL 512
#define BGR   16
#define SEQ   256
#define NH    8
#define DH    64
#define LMAX  992
#define LATD  768
#define ROWS_Q  (BGR*LMAX)   // 15872
#define ROWS_KV (BGR*SEQ)    // 4096

// ---------------- scratch (weights stored TRANSPOSED [n][k]) ----------
__device__ float g_dense[ROWS_Q*DMODEL];
__device__ float g_qh   [ROWS_Q*DMODEL];
__device__ float g_ctx  [ROWS_Q*DMODEL];
__device__ float g_y    [ROWS_Q*DMODEL];
__device__ float g_x1   [ROWS_Q*DMODEL];
__device__ float g_h    [ROWS_Q*DMODEL];
__device__ float g_kh   [ROWS_KV*DMODEL];
__device__ float g_vh   [ROWS_KV*DMODEL];
__device__ float g_Wq2  [DMODEL*DMODEL];   // Wq2^T [512][512]
__device__ float g_Wk2  [LATD*DMODEL];     // Wk2^T [512][768]
__device__ float g_Wv2  [LATD*DMODEL];     // Wv2^T [512][768]
__device__ float g_Wo2  [DMODEL*DMODEL];   // Wo^T
__device__ float g_W12  [DMODEL*DMODEL];   // W1^T
__device__ float g_cond [BGR*SEQ*LATD];
__device__ float g_bq2  [DMODEL];
__device__ float g_bk2  [DMODEL];
__device__ float g_bv2  [DMODEL];
__device__ int   g_starts[BGR];

// ---------------- helpers ----------------
__device__ __forceinline__ unsigned f2tf32(float x) {
    unsigned y;
    asm("cvt.rna.tf32.f32 %0, %1;" : "=r"(y) : "f"(x));
    return y;
}
__device__ __forceinline__ float rtf(float x) { return __uint_as_float(f2tf32(x)); }

__device__ __forceinline__ void mma_tf32(float c[4],
    unsigned a0, unsigned a1, unsigned a2, unsigned a3,
    unsigned b0, unsigned b1)
{
    asm volatile(
        "mma.sync.aligned.m16n8k8.row.col.f32.tf32.tf32.f32 "
        "{%0,%1,%2,%3}, {%4,%5,%6,%7}, {%8,%9}, {%0,%1,%2,%3};"
        : "+f"(c[0]), "+f"(c[1]), "+f"(c[2]), "+f"(c[3])
        : "r"(a0), "r"(a1), "r"(a2), "r"(a3), "r"(b0), "r"(b1));
}

#define CP16(dst, src) asm volatile("cp.async.cg.shared.global [%0], [%1], 16;" :: "r"(dst), "l"(src))
#define LDSM4(r, addr) asm volatile( \
    "ldmatrix.sync.aligned.m8n8.x4.shared.b16 {%0,%1,%2,%3}, [%4];" \
    : "=r"((r)[0]), "=r"((r)[1]), "=r"((r)[2]), "=r"((r)[3]) : "r"(addr))

__global__ void find_starts(const int* __restrict__ gb, int* starts, int n) {
    int i = blockIdx.x*blockDim.x + threadIdx.x;
    if (i < n) {
        if (i == 0 || gb[i] != gb[i-1]) starts[gb[i]] = i;
    }
}

__global__ __launch_bounds__(128) void pad_kernel(
    const float* __restrict__ nodes, const int* __restrict__ starts,
    float* __restrict__ dense)
{
    int r = blockIdx.x;
    int b = r / LMAX, pp = r - b*LMAX;
    int s = starts[b];
    int e = (b == BGR-1) ? NN : starts[b+1];
    int i = s + pp;
    float4 v = make_float4(0.f, 0.f, 0.f, 0.f);
    if (i < e) {
        v = ((const float4*)(nodes + (size_t)i*DMODEL))[threadIdx.x];
        v.x = rtf(v.x); v.y = rtf(v.y); v.z = rtf(v.z); v.w = rtf(v.w);
    }
    ((float4*)(dense + (size_t)r*DMODEL))[threadIdx.x] = v;
}

// round-copy conditioning (A operand; stays row-major)
__global__ void round_cond(const float* __restrict__ src, float* __restrict__ dst) {
    int i = blockIdx.x*blockDim.x + threadIdx.x;
    int stride = gridDim.x*blockDim.x;
    int n4 = (BGR*SEQ*LATD) >> 2;
    for (; i < n4; i += stride) {
        float4 v = ((const float4*)src)[i];
        v.x = rtf(v.x); v.y = rtf(v.y); v.z = rtf(v.z); v.w = rtf(v.w);
        ((float4*)dst)[i] = v;
    }
}

// transpose + round Wo / W1 (512x512), 32x32 tiles
__global__ __launch_bounds__(256) void roundT(
    const float* __restrict__ Wo, const float* __restrict__ W1,
    float* __restrict__ dwo, float* __restrict__ dw1)
{
    __shared__ float t[32][33];
    int z = blockIdx.z;
    const float* s = z ? W1 : Wo;
    float* d = z ? dw1 : dwo;
    int bx = blockIdx.x*32, by = blockIdx.y*32;
    int x = threadIdx.x & 31, y0 = threadIdx.x >> 5;   // 32 x 8
    #pragma unroll
    for (int i = 0; i < 32; i += 8)
        t[y0+i][x] = s[(size_t)(by + y0 + i)*DMODEL + bx + x];
    __syncthreads();
    #pragma unroll
    for (int i = 0; i < 32; i += 8)
        d[(size_t)(bx + y0 + i)*DMODEL + by + x] = rtf(t[x][y0+i]);
}

// parallel bias combine
__global__ __launch_bounds__(512) void bias3p(
    const float* __restrict__ bq, const float* __restrict__ bk,
    const float* __restrict__ bv, const float* __restrict__ inw,
    const float* __restrict__ inb,
    float* __restrict__ oq, float* __restrict__ ok, float* __restrict__ ov)
{
    __shared__ float red[8][64];
    int z = blockIdx.y;
    const float* bin = (z==0) ? bq : (z==1) ? bk : bv;
    const float* W = inw + (size_t)z*DMODEL*DMODEL;
    const float* ab = inb + z*DMODEL;
    float* outp = (z==0) ? oq : (z==1) ? ok : ov;
    int jj = threadIdx.x & 63;
    int r  = threadIdx.x >> 6;
    int j  = blockIdx.x*64 + jj;
    float a = 0.f;
    #pragma unroll 8
    for (int i = r*64; i < r*64 + 64; i++)
        a += bin[i]*W[(size_t)i*DMODEL + j];
    red[r][jj] = a;
    __syncthreads();
    if (r == 0) {
        float s = ab[j];
        #pragma unroll
        for (int k = 0; k < 8; k++) s += red[k][jj];
        outp[j] = s;
    }
}

// ---------------- fold3: weight GEMMs, epilogue writes C^T -------------
#define SMP 132

__global__ __launch_bounds__(256) void fold3_gemm(
    const float* __restrict__ Wq, const float* __restrict__ Wk,
    const float* __restrict__ Wv, const float* __restrict__ inw,
    float* __restrict__ Cq, float* __restrict__ Ck, float* __restrict__ Cv)
{
    int z = blockIdx.z;
    int M = (z == 0) ? DMODEL : LATD;
    if ((int)blockIdx.y*128 >= M) return;
    const float* A = (z==0) ? Wq : (z==1) ? Wk : Wv;
    const float* B = inw + (size_t)z*DMODEL*DMODEL;
    float* C = (z==0) ? Cq : (z==1) ? Ck : Cv;
    const int N = DMODEL, K = DMODEL;

    __shared__ unsigned As[16][SMP];
    __shared__ unsigned Bs[16][SMP];
    int tid = threadIdx.x;
    int warp = tid >> 5, lane = tid & 31;
    int warp_m = warp & 3, warp_n = warp >> 2;
    int p = lane >> 2, q = lane & 3;
    int blockM = blockIdx.y * 128;
    int blockN = blockIdx.x * 128;

    int ia0 = tid*2, ia1 = tid*2 + 1;
    int arow0 = ia0 >> 2, akq0 = ia0 & 3;
    int arow1 = ia1 >> 2, akq1 = ia1 & 3;
    int bk0 = ia0 >> 5, bn0 = ia0 & 31;
    int bk1 = ia1 >> 5, bn1 = ia1 & 31;

    const float* Ap0 = A + (size_t)(blockM + arow0)*K + akq0*4;
    const float* Ap1 = A + (size_t)(blockM + arow1)*K + akq1*4;
    const float* Bp0 = B + (size_t)bk0*N + blockN + bn0*4;
    const float* Bp1 = B + (size_t)bk1*N + blockN + bn1*4;

    float acc[2][8][4];
    #pragma unroll
    for (int mt = 0; mt < 2; mt++)
        #pragma unroll
        for (int nt = 0; nt < 8; nt++)
            #pragma unroll
            for (int i = 0; i < 4; i++) acc[mt][nt][i] = 0.f;

    float4 av0 = *(const float4*)(Ap0);
    float4 av1 = *(const float4*)(Ap1);
    float4 bv0 = *(const float4*)(Bp0);
    float4 bv1 = *(const float4*)(Bp1);

    for (int kt = 16; kt <= K; kt += 16) {
        As[akq0*4+0][arow0] = f2tf32(av0.x);
        As[akq0*4+1][arow0] = f2tf32(av0.y);
        As[akq0*4+2][arow0] = f2tf32(av0.z);
        As[akq0*4+3][arow0] = f2tf32(av0.w);
        As[akq1*4+0][arow1] = f2tf32(av1.x);
        As[akq1*4+1][arow1] = f2tf32(av1.y);
        As[akq1*4+2][arow1] = f2tf32(av1.z);
        As[akq1*4+3][arow1] = f2tf32(av1.w);
        {
            uint4 t0, t1;
            t0.x = f2tf32(bv0.x); t0.y = f2tf32(bv0.y);
            t0.z = f2tf32(bv0.z); t0.w = f2tf32(bv0.w);
            t1.x = f2tf32(bv1.x); t1.y = f2tf32(bv1.y);
            t1.z = f2tf32(bv1.z); t1.w = f2tf32(bv1.w);
            *(uint4*)&Bs[bk0][bn0*4] = t0;
            *(uint4*)&Bs[bk1][bn1*4] = t1;
        }
        __syncthreads();
        if (kt < K) {
            av0 = *(const float4*)(Ap0 + kt);
            av1 = *(const float4*)(Ap1 + kt);
            bv0 = *(const float4*)(Bp0 + (size_t)kt*N);
            bv1 = *(const float4*)(Bp1 + (size_t)kt*N);
        }
        #pragma unroll
        for (int kk = 0; kk < 16; kk += 8) {
            unsigned afr[2][4];
            #pragma unroll
            for (int mt = 0; mt < 2; mt++) {
                int mb = warp_m*32 + mt*16;
                afr[mt][0] = As[kk+q  ][mb + p];
                afr[mt][1] = As[kk+q  ][mb + p + 8];
                afr[mt][2] = As[kk+q+4][mb + p];
                afr[mt][3] = As[kk+q+4][mb + p + 8];
            }
            unsigned bfr[8][2];
            #pragma unroll
            for (int nt = 0; nt < 8; nt++) {
                int nb = warp_n*64 + nt*8;
                bfr[nt][0] = Bs[kk+q  ][nb + p];
                bfr[nt][1] = Bs[kk+q+4][nb + p];
            }
            #pragma unroll
            for (int mt = 0; mt < 2; mt++)
                #pragma unroll
                for (int nt = 0; nt < 8; nt++)
                    mma_tf32(acc[mt][nt], afr[mt][0], afr[mt][1], afr[mt][2], afr[mt][3],
                             bfr[nt][0], bfr[nt][1]);
        }
        __syncthreads();
    }

    // epilogue: write transposed CT[n*M + m]
    #pragma unroll
    for (int mt = 0; mt < 2; mt++) {
        int r0 = blockM + warp_m*32 + mt*16 + p;
        #pragma unroll
        for (int nt = 0; nt < 8; nt++) {
            int c0 = blockN + warp_n*64 + nt*8 + 2*q;
            C[(size_t)(c0  )*M + r0    ] = rtf(acc[mt][nt][0]);
            C[(size_t)(c0+1)*M + r0    ] = rtf(acc[mt][nt][1]);
            C[(size_t)(c0  )*M + r0 + 8] = rtf(acc[mt][nt][2]);
            C[(size_t)(c0+1)*M + r0 + 8] = rtf(acc[mt][nt][3]);
        }
    }
}

// ---------------- 3-stage cp.async TF32 GEMM with ldmatrix fragments --------
// A row-major [M][K]; Bt TRANSPOSED row-major [N][K]. Both pre-rounded tf32.
#define TSTR 20
#define STG_F (128*TSTR)                 // floats per stage per operand
#define GEMM_SMEM (3*2*STG_F*4)          // 61440 bytes

template<int MODE, bool RND>
__device__ __forceinline__ void gemm_body(
    const float* __restrict__ A, const float* __restrict__ Bt,
    const float* __restrict__ bias, const float* __restrict__ Dm,
    float* __restrict__ C, int N, int K, float* smem)
{
    float* As = smem;
    float* Bs = smem + 3*STG_F;

    int tid = threadIdx.x;
    int warp = tid >> 5, lane = tid & 31;
    int warp_m = warp & 3, warp_n = warp >> 2;
    int p = lane >> 2, q = lane & 3;
    int blockM = blockIdx.y * 128;
    int blockN = blockIdx.x * 128;

    // global->smem: chunk c (0..511): row = c>>2, kq = (c&3)*4 floats
    int c0 = tid*2, c1 = c0 + 1;
    int r0c = c0 >> 2, k0c = (c0 & 3)*4;
    int r1c = c1 >> 2, k1c = (c1 & 3)*4;

    const float* gA0 = A  + (size_t)(blockM + r0c)*K + k0c;
    const float* gA1 = A  + (size_t)(blockM + r1c)*K + k1c;
    const float* gB0 = Bt + (size_t)(blockN + r0c)*K + k0c;
    const float* gB1 = Bt + (size_t)(blockN + r1c)*K + k1c;

    unsigned sa = (unsigned)__cvta_generic_to_shared(As);
    unsigned sb = (unsigned)__cvta_generic_to_shared(Bs);
    unsigned dA0[3], dA1[3], dB0[3], dB1[3];
    #pragma unroll
    for (int s = 0; s < 3; s++) {
        dA0[s] = sa + (s*STG_F + r0c*TSTR + k0c)*4;
        dA1[s] = sa + (s*STG_F + r1c*TSTR + k1c)*4;
        dB0[s] = sb + (s*STG_F + r0c*TSTR + k0c)*4;
        dB1[s] = sb + (s*STG_F + r1c*TSTR + k1c)*4;
    }

    // ldmatrix base addresses (per-lane):
    // A: m = warp_m*32 + (lane&15) (+ mt*16), k = (lane>>4)*4 (+ kk)
    unsigned aBase = sa + (((warp_m*32 + (lane & 15))*TSTR) + ((lane >> 4) << 2))*4;
    // B: n = warp_n*64 + ((lane>>4)<<3) + (lane&7) (+ pair*16), k = ((lane>>3)&1)*4 (+ kk)
    unsigned bBase = sb + (((warp_n*64 + ((lane >> 4) << 3) + (lane & 7))*TSTR)
                           + (((lane >> 3) & 1) << 2))*4;

    float acc[2][8][4];
    #pragma unroll
    for (int mt = 0; mt < 2; mt++)
        #pragma unroll
        for (int nt = 0; nt < 8; nt++)
            #pragma unroll
            for (int i = 0; i < 4; i++) acc[mt][nt][i] = 0.f;

    CP16(dA0[0], gA0); CP16(dA1[0], gA1);
    CP16(dB0[0], gB0); CP16(dB1[0], gB1);
    asm volatile("cp.async.commit_group;");
    CP16(dA0[1], gA0 + 16); CP16(dA1[1], gA1 + 16);
    CP16(dB0[1], gB0 + 16); CP16(dB1[1], gB1 + 16);
    asm volatile("cp.async.commit_group;");

    int nk = K >> 4;
    int sc = 0, sp = 2;
    for (int t = 0; t < nk; t++) {
        asm volatile("cp.async.wait_group 1;");
        __syncthreads();
        if (t + 2 < nk) {
            int kt = (t + 2) << 4;
            CP16(dA0[sp], gA0 + kt); CP16(dA1[sp], gA1 + kt);
            CP16(dB0[sp], gB0 + kt); CP16(dB1[sp], gB1 + kt);
        }
        asm volatile("cp.async.commit_group;");
        unsigned ao = aBase + sc*STG_F*4;
        unsigned bo = bBase + sc*STG_F*4;
        #pragma unroll
        for (int kk = 0; kk < 16; kk += 8) {
            unsigned afr[2][4];
            LDSM4(afr[0], ao + kk*4);
            LDSM4(afr[1], ao + (16*TSTR + kk)*4);
            unsigned bfr[4][4];
            #pragma unroll
            for (int j = 0; j < 4; j++)
                LDSM4(bfr[j], bo + (j*16*TSTR + kk)*4);
            #pragma unroll
            for (int mt = 0; mt < 2; mt++)
                #pragma unroll
                for (int nt = 0; nt < 8; nt++)
                    mma_tf32(acc[mt][nt],
                             afr[mt][0], afr[mt][1], afr[mt][2], afr[mt][3],
                             bfr[nt >> 1][(nt & 1)*2], bfr[nt >> 1][(nt & 1)*2 + 1]);
        }
        sc++; if (sc == 3) sc = 0;
        sp++; if (sp == 3) sp = 0;
    }

    #pragma unroll
    for (int mt = 0; mt < 2; mt++) {
        int r0 = blockM + warp_m*32 + mt*16 + p;
        #pragma unroll
        for (int nt = 0; nt < 8; nt++) {
            int c0c = blockN + warp_n*64 + nt*8 + 2*q;
            float b0 = 0.f, b1 = 0.f;
            if (bias) { b0 = bias[c0c]; b1 = bias[c0c+1]; }
            float v0 = acc[mt][nt][0] + b0;
            float v1 = acc[mt][nt][1] + b1;
            float v2 = acc[mt][nt][2] + b0;
            float v3 = acc[mt][nt][3] + b1;
            size_t o0 = (size_t)r0*N + c0c;
            size_t o1 = (size_t)(r0+8)*N + c0c;
            if (MODE == 1) {
                float2 d0 = *(const float2*)(Dm + o0);
                float2 d1 = *(const float2*)(Dm + o1);
                v0 += d0.x; v1 += d0.y; v2 += d1.x; v3 += d1.y;
            }
            if (MODE == 2) {
                v0 = (v0 > 0.f) ? v0 : 0.01f*v0;
                v1 = (v1 > 0.f) ? v1 : 0.01f*v1;
                v2 = (v2 > 0.f) ? v2 : 0.01f*v2;
                v3 = (v3 > 0.f) ? v3 : 0.01f*v3;
                float2 d0 = *(const float2*)(Dm + o0);
                float2 d1 = *(const float2*)(Dm + o1);
                v0 += d0.x; v1 += d0.y; v2 += d1.x; v3 += d1.y;
            }
            if (RND) { v0 = rtf(v0); v1 = rtf(v1); v2 = rtf(v2); v3 = rtf(v3); }
            *(float2*)(C + o0) = make_float2(v0, v1);
            *(float2*)(C + o1) = make_float2(v2, v3);
        }
    }
}

template<int MODE, bool RND>
__global__ __launch_bounds__(256, 2) void gemm_one(
    const float* __restrict__ A, const float* __restrict__ Bt,
    const float* __restrict__ bias, const float* __restrict__ Dm,
    float* __restrict__ C, int N, int K)
{
    extern __shared__ float smem[];
    gemm_body<MODE, RND>(A, Bt, bias, Dm, C, N, K, smem);
}

__global__ __launch_bounds__(256, 2) void gemm_kv(
    const float* __restrict__ cond,
    const float* __restrict__ Wk2T, const float* __restrict__ Wv2T,
    const float* __restrict__ bk2, const float* __restrict__ bv2,
    float* __restrict__ kh, float* __restrict__ vh)
{
    extern __shared__ float smem[];
    const float* Bt = blockIdx.z ? Wv2T : Wk2T;
    const float* bias = blockIdx.z ? bv2 : bk2;
    float* C = blockIdx.z ? vh : kh;
    gemm_body<0, true>(cond, Bt, bias, nullptr, C, DMODEL, LATD, smem);
}

// ---------------- tensor-core attention (unchanged) ----------------
#define TB   64
#define KSTR 68
#define VSTR 72
#define PSTR 260
#define ATT_SMEM ((SEQ*KSTR + SEQ*VSTR + TB*PSTR)*4 + SEQ*4)

__global__ __launch_bounds__(512, 1) void attn_mma(
    const float* __restrict__ qh, const float* __restrict__ kh,
    const float* __restrict__ vh, const int* __restrict__ maskp,
    float* __restrict__ ctx, float* __restrict__ av_out)
{
    extern __shared__ float sm[];
    float* sK = sm;
    float* sV = sK + SEQ*KSTR;
    float* sU = sV + SEQ*VSTR;
    int* sMask = (int*)(sU + TB*PSTR);

    int b = blockIdx.y, lt = blockIdx.x;
    int tid = threadIdx.x;
    int w = tid >> 5, lane = tid & 31;
    int p = lane >> 2, q = lane & 3;

    if (tid < SEQ) sMask[tid] = maskp[b*SEQ + tid];

    float avacc[2][4][4];
    #pragma unroll
    for (int j = 0; j < 2; j++)
        #pragma unroll
        for (int mt = 0; mt < 4; mt++)
            #pragma unroll
            for (int i = 0; i < 4; i++) avacc[j][mt][i] = 0.f;

    for (int h = 0; h < NH; h++) {
        __syncthreads();
        for (int idx = tid; idx < SEQ*DH; idx += 512) {
            int s = idx >> 6, d = idx & 63;
            size_t g = ((size_t)(b*SEQ + s))*DMODEL + h*DH + d;
            sK[s*KSTR + d] = kh[g];
            sV[s*VSTR + d] = vh[g];
        }
        for (int idx = tid; idx < TB*DH; idx += 512) {
            int r = idx >> 6, d = idx & 63;
            int l = lt*TB + r; if (l > LMAX-1) l = LMAX-1;
            sU[r*KSTR + d] = qh[((size_t)(b*LMAX) + l)*DMODEL + h*DH + d];
        }
        __syncthreads();

        float csc[2][4][4];
        #pragma unroll
        for (int j = 0; j < 2; j++)
            #pragma unroll
            for (int mt = 0; mt < 4; mt++)
                #pragma unroll
                for (int i = 0; i < 4; i++) csc[j][mt][i] = 0.f;
        #pragma unroll
        for (int k = 0; k < 8; k++) {
            int kc = k*8 + q;
            unsigned bf0[2], bf1[2];
            #pragma unroll
            for (int j = 0; j < 2; j++) {
                int sc = (2*w + j)*8 + p;
                bf0[j] = __float_as_uint(sK[sc*KSTR + kc]);
                bf1[j] = __float_as_uint(sK[sc*KSTR + kc + 4]);
            }
            #pragma unroll
            for (int mt = 0; mt < 4; mt++) {
                int r0 = mt*16 + p;
                unsigned a0 = __float_as_uint(sU[r0*KSTR + kc]);
                unsigned a1 = __float_as_uint(sU[(r0+8)*KSTR + kc]);
                unsigned a2 = __float_as_uint(sU[r0*KSTR + kc + 4]);
                unsigned a3 = __float_as_uint(sU[(r0+8)*KSTR + kc + 4]);
                mma_tf32(csc[0][mt], a0, a1, a2, a3, bf0[0], bf1[0]);
                mma_tf32(csc[1][mt], a0, a1, a2, a3, bf0[1], bf1[1]);
            }
        }
        __syncthreads();
        #pragma unroll
        for (int j = 0; j < 2; j++)
            #pragma unroll
            for (int mt = 0; mt < 4; mt++) {
                int row = mt*16 + p;
                int col = (2*w + j)*8 + 2*q;
                *(float2*)&sU[row*PSTR + col]     = make_float2(csc[j][mt][0], csc[j][mt][1]);
                *(float2*)&sU[(row+8)*PSTR + col] = make_float2(csc[j][mt][2], csc[j][mt][3]);
            }
        __syncthreads();
        #pragma unroll
        for (int rr = 0; rr < 4; rr++) {
            int row = 4*w + rr;
            float v[8];
            float m = -1e30f;
            #pragma unroll
            for (int jj = 0; jj < 8; jj++) {
                int s = lane + 32*jj;
                float x = sMask[s] ? -1e30f : sU[row*PSTR + s]*0.125f;
                v[jj] = x;
                m = fmaxf(m, x);
            }
            #pragma unroll
            for (int o = 16; o > 0; o >>= 1) m = fmaxf(m, __shfl_xor_sync(0xffffffffu, m, o));
            float sum = 0.f;
            #pragma unroll
            for (int jj = 0; jj < 8; jj++) { v[jj] = __expf(v[jj] - m); sum += v[jj]; }
            #pragma unroll
            for (int o = 16; o > 0; o >>= 1) sum += __shfl_xor_sync(0xffffffffu, sum, o);
            float inv = 1.f/sum;
            #pragma unroll
            for (int jj = 0; jj < 8; jj++)
                sU[row*PSTR + lane + 32*jj] = rtf(v[jj]*inv);
        }
        __syncthreads();
        #pragma unroll
        for (int j = 0; j < 2; j++)
            #pragma unroll
            for (int mt = 0; mt < 4; mt++) {
                int row = mt*16 + p;
                int col = (2*w + j)*8 + 2*q;
                avacc[j][mt][0] += sU[row*PSTR + col];
                avacc[j][mt][1] += sU[row*PSTR + col + 1];
                avacc[j][mt][2] += sU[(row+8)*PSTR + col];
                avacc[j][mt][3] += sU[(row+8)*PSTR + col + 1];
            }
        int mtw = w & 3, nt0 = w >> 2;
        float cct[2][4];
        #pragma unroll
        for (int j = 0; j < 2; j++)
            #pragma unroll
            for (int i = 0; i < 4; i++) cct[j][i] = 0.f;
        #pragma unroll 8
        for (int k = 0; k < 32; k++) {
            int sc = k*8 + q;
            int r0 = mtw*16 + p;
            unsigned a0 = __float_as_uint(sU[r0*PSTR + sc]);
            unsigned a1 = __float_as_uint(sU[(r0+8)*PSTR + sc]);
            unsigned a2 = __float_as_uint(sU[r0*PSTR + sc + 4]);
            unsigned a3 = __float_as_uint(sU[(r0+8)*PSTR + sc + 4]);
            #pragma unroll
            for (int j = 0; j < 2; j++) {
                int dc = (nt0 + 4*j)*8 + p;
                unsigned b0 = __float_as_uint(sV[sc*VSTR + dc]);
                unsigned b1 = __float_as_uint(sV[(sc+4)*VSTR + dc]);
                mma_tf32(cct[j], a0, a1, a2, a3, b0, b1);
            }
        }
        #pragma unroll
        for (int j = 0; j < 2; j++) {
            int dc = h*DH + (nt0 + 4*j)*8 + 2*q;
            int l0 = lt*TB + mtw*16 + p;
            if (l0 < LMAX)
                *(float2*)&ctx[((size_t)(b*LMAX) + l0)*DMODEL + dc] =
                    make_float2(rtf(cct[j][0]), rtf(cct[j][1]));
            int l1 = l0 + 8;
            if (l1 < LMAX)
                *(float2*)&ctx[((size_t)(b*LMAX) + l1)*DMODEL + dc] =
                    make_float2(rtf(cct[j][2]), rtf(cct[j][3]));
        }
    }

    #pragma unroll
    for (int j = 0; j < 2; j++)
        #pragma unroll
        for (int mt = 0; mt < 4; mt++) {
            int col = (2*w + j)*8 + 2*q;
            int l0 = lt*TB + mt*16 + p;
            if (l0 < LMAX)
                *(float2*)&av_out[((size_t)(b*LMAX) + l0)*SEQ + col] =
                    make_float2(avacc[j][mt][0]*0.125f, avacc[j][mt][1]*0.125f);
            int l1 = l0 + 8;
            if (l1 < LMAX)
                *(float2*)&av_out[((size_t)(b*LMAX) + l1)*SEQ + col] =
                    make_float2(avacc[j][mt][2]*0.125f, avacc[j][mt][3]*0.125f);
        }
}

// ---------------- LayerNorm ----------
template<bool RND>
__global__ __launch_bounds__(128) void ln_kernel(
    const float* __restrict__ x, const float* __restrict__ g,
    const float* __restrict__ bb, float* __restrict__ y)
{
    __shared__ float ws[4], wss[4];
    int r = blockIdx.x;
    int tid = threadIdx.x;
    const float4* xr = (const float4*)(x + (size_t)r*DMODEL);
    float4 v = xr[tid];
    float s  = v.x + v.y + v.z + v.w;
    float ss = v.x*v.x + v.y*v.y + v.z*v.z + v.w*v.w;
    #pragma unroll
    for (int o = 16; o > 0; o >>= 1) {
        s  += __shfl_xor_sync(0xffffffffu, s,  o);
        ss += __shfl_xor_sync(0xffffffffu, ss, o);
    }
    int warp = tid >> 5, lane = tid & 31;
    if (lane == 0) { ws[warp] = s; wss[warp] = ss; }
    __syncthreads();
    float S  = ws[0] + ws[1] + ws[2] + ws[3];
    float SS = wss[0] + wss[1] + wss[2] + wss[3];
    float mean = S * (1.f/DMODEL);
    float var  = SS * (1.f/DMODEL) - mean*mean;
    float rstd = rsqrtf(var + 1e-5f);
    float4 gg = ((const float4*)g)[tid];
    float4 b4 = ((const float4*)bb)[tid];
    float4 o4;
    o4.x = (v.x - mean)*rstd*gg.x + b4.x;
    o4.y = (v.y - mean)*rstd*gg.y + b4.y;
    o4.z = (v.z - mean)*rstd*gg.z + b4.z;
    o4.w = (v.w - mean)*rstd*gg.w + b4.w;
    if (RND) { o4.x = rtf(o4.x); o4.y = rtf(o4.y); o4.z = rtf(o4.z); o4.w = rtf(o4.w); }
    ((float4*)(y + (size_t)r*DMODEL))[tid] = o4;
}

// ---------------- fused LN2 + ragged gather ----------
__global__ __launch_bounds__(128) void ln_gather(
    const float* __restrict__ x, const int* __restrict__ gb,
    const int* __restrict__ starts,
    const float* __restrict__ g, const float* __restrict__ bb,
    float* __restrict__ out)
{
    __shared__ float ws[4], wss[4];
    int i = blockIdx.x;
    int b = gb[i];
    int pp = i - starts[b];
    size_t row = (size_t)b*LMAX + pp;
    int tid = threadIdx.x;
    float4 v = ((const float4*)(x + row*DMODEL))[tid];
    float s  = v.x + v.y + v.z + v.w;
    float ss = v.x*v.x + v.y*v.y + v.z*v.z + v.w*v.w;
    #pragma unroll
    for (int o = 16; o > 0; o >>= 1) {
        s  += __shfl_xor_sync(0xffffffffu, s,  o);
        ss += __shfl_xor_sync(0xffffffffu, ss, o);
    }
    int warp = tid >> 5, lane = tid & 31;
    if (lane == 0) { ws[warp] = s; wss[warp] = ss; }
    __syncthreads();
    float S  = ws[0] + ws[1] + ws[2] + ws[3];
    float SS = wss[0] + wss[1] + wss[2] + wss[3];
    float mean = S * (1.f/DMODEL);
    float var  = SS * (1.f/DMODEL) - mean*mean;
    float rstd = rsqrtf(var + 1e-5f);
    float4 gg = ((const float4*)g)[tid];
    float4 b4 = ((const float4*)bb)[tid];
    float4 o4;
    o4.x = (v.x - mean)*rstd*gg.x + b4.x;
    o4.y = (v.y - mean)*rstd*gg.y + b4.y;
    o4.z = (v.z - mean)*rstd*gg.z + b4.z;
    o4.w = (v.w - mean)*rstd*gg.w + b4.w;
    ((float4*)(out + (size_t)i*DMODEL))[tid] = o4;
}

// ---------------- launch ----------------
extern "C" void kernel_launch(void* const* d_in, const int* in_sizes, int n_in,
                              void* d_out, int out_size)
{
    int off = (n_in >= 22) ? 0 : 2;
    const float* nodes  = (const float*)d_in[0];
    const int*   gb     = (const int*)  d_in[1];
    const float* cond   = (const float*)d_in[2];
    const int*   maskp  = (const int*)  d_in[3];
    const float* Wq     = (const float*)d_in[6-off];
    const float* bq     = (const float*)d_in[7-off];
    const float* Wk     = (const float*)d_in[8-off];
    const float* bk     = (const float*)d_in[9-off];
    const float* Wv     = (const float*)d_in[10-off];
    const float* bv     = (const float*)d_in[11-off];
    const float* in_w   = (const float*)d_in[12-off];
    const float* in_b   = (const float*)d_in[13-off];
    const float* Wo     = (const float*)d_in[14-off];
    const float* bo     = (const float*)d_in[15-off];
    const float* ln1g   = (const float*)d_in[16-off];
    const float* ln1b   = (const float*)d_in[17-off];
    const float* W1     = (const float*)d_in[18-off];
    const float* b1     = (const float*)d_in[19-off];
    const float* ln2g   = (const float*)d_in[20-off];
    const float* ln2b   = (const float*)d_in[21-off];
    float* out = (float*)d_out;
    float* av_out = out + (size_t)NN*DMODEL;

    float *p_dense, *p_qh, *p_kh, *p_vh, *p_ctx, *p_y, *p_x1, *p_h;
    float *p_Wq2, *p_Wk2, *p_Wv2, *p_Wo2, *p_W12, *p_cond;
    float *p_bq2, *p_bk2, *p_bv2;
    int *p_starts;
    cudaGetSymbolAddress((void**)&p_dense, g_dense);
    cudaGetSymbolAddress((void**)&p_qh, g_qh);
    cudaGetSymbolAddress((void**)&p_kh, g_kh);
    cudaGetSymbolAddress((void**)&p_vh, g_vh);
    cudaGetSymbolAddress((void**)&p_ctx, g_ctx);
    cudaGetSymbolAddress((void**)&p_y, g_y);
    cudaGetSymbolAddress((void**)&p_x1, g_x1);
    cudaGetSymbolAddress((void**)&p_h, g_h);
    cudaGetSymbolAddress((void**)&p_Wq2, g_Wq2);
    cudaGetSymbolAddress((void**)&p_Wk2, g_Wk2);
    cudaGetSymbolAddress((void**)&p_Wv2, g_Wv2);
    cudaGetSymbolAddress((void**)&p_Wo2, g_Wo2);
    cudaGetSymbolAddress((void**)&p_W12, g_W12);
    cudaGetSymbolAddress((void**)&p_cond, g_cond);
    cudaGetSymbolAddress((void**)&p_bq2, g_bq2);
    cudaGetSymbolAddress((void**)&p_bk2, g_bk2);
    cudaGetSymbolAddress((void**)&p_bv2, g_bv2);
    cudaGetSymbolAddress((void**)&p_starts, g_starts);

    cudaFuncSetAttribute(gemm_one<0,true>,  cudaFuncAttributeMaxDynamicSharedMemorySize, GEMM_SMEM);
    cudaFuncSetAttribute(gemm_one<1,false>, cudaFuncAttributeMaxDynamicSharedMemorySize, GEMM_SMEM);
    cudaFuncSetAttribute(gemm_one<2,false>, cudaFuncAttributeMaxDynamicSharedMemorySize, GEMM_SMEM);
    cudaFuncSetAttribute(gemm_kv,           cudaFuncAttributeMaxDynamicSharedMemorySize, GEMM_SMEM);
    cudaFuncSetAttribute(attn_mma,          cudaFuncAttributeMaxDynamicSharedMemorySize, ATT_SMEM);

    // 1) round conditioning (A operand of K/V GEMM)
    round_cond<<<512, 256>>>(cond, p_cond);
    // 2) fold projection weights -> TRANSPOSED
    fold3_gemm<<<dim3(4,6,3), 256>>>(Wq, Wk, Wv, in_w, p_Wq2, p_Wk2, p_Wv2);
    // 3) bias combines
    bias3p<<<dim3(8,3), 512>>>(bq, bk, bv, in_w, in_b, p_bq2, p_bk2, p_bv2);
    // 4) K/V projections  <-- profiled launch
    gemm_kv<<<dim3(4,32,2), 256, GEMM_SMEM>>>(p_cond, p_Wk2, p_Wv2, p_bk2, p_bv2, p_kh, p_vh);
    // 5) transpose+round Wo, W1
    roundT<<<dim3(16,16,2), 256>>>(Wo, W1, p_Wo2, p_W12);
    // 6) ragged bookkeeping + dense padding
    find_starts<<<(NN+255)/256, 256>>>(gb, p_starts, NN);
    pad_kernel<<<ROWS_Q, 128>>>(nodes, p_starts, p_dense);
    // 7) Q projection
    gemm_one<0,true><<<dim3(4,124), 256, GEMM_SMEM>>>(p_dense, p_Wq2, p_bq2, nullptr, p_qh, DMODEL, DMODEL);
    // 8) attention
    attn_mma<<<dim3(16, BGR), 512, ATT_SMEM>>>(p_qh, p_kh, p_vh, maskp, p_ctx, av_out);
    // 9) out proj + residual
    gemm_one<1,false><<<dim3(4,124), 256, GEMM_SMEM>>>(p_ctx, p_Wo2, bo, p_dense, p_y, DMODEL, DMODEL);
    // 10) LN1
    ln_kernel<true><<<ROWS_Q, 128>>>(p_y, ln1g, ln1b, p_x1);
    // 11) FFN + leaky + residual
    gemm_one<2,false><<<dim3(4,124), 256, GEMM_SMEM>>>(p_x1, p_W12, b1, p_x1, p_h, DMODEL, DMODEL);
    // 12) LN2 fused with ragged gather
    ln_gather<<<NN, 128>>>(p_h, gb, p_starts, ln2g, ln2b, out);
}

// round 7
// speedup vs baseline: 4.5885x; 1.2982x over previous
#include <cuda_runtime.h>
#include <cuda_fp16.h>
#include <cuda_bf16.h>
#include <math.h>

// ---------------- problem constants ----------------
#define NN    12032
#define DMODEL 512
#define BGR   16
#define SEQ   256
#define NH    8
#define DH    64
#define LMAX  992
#define LATD  768
#define ROWS_Q  (BGR*LMAX)   // 15872
#define ROWS_KV (BGR*SEQ)    // 4096

// ---------------- scratch ----------
__device__ float  g_dense_f[ROWS_Q*DMODEL];    // raw fp32 (residual)
__device__ __half g_dense_h[ROWS_Q*DMODEL];    // half (GEMM A)
__device__ float  g_qh  [ROWS_Q*DMODEL];
__device__ __half g_ctx [ROWS_Q*DMODEL];       // half (GEMM A)
__device__ float  g_y   [ROWS_Q*DMODEL];
__device__ float  g_x1f [ROWS_Q*DMODEL];       // fp32 residual
__device__ __half g_x1h [ROWS_Q*DMODEL];       // half (GEMM A)
__device__ float  g_h   [ROWS_Q*DMODEL];
__device__ float  g_kh  [ROWS_KV*DMODEL];
__device__ float  g_vh  [ROWS_KV*DMODEL];
__device__ __half g_WqT [DMODEL*DMODEL];       // transposed half weights [n][k]
__device__ __half g_WkT [LATD*DMODEL];
__device__ __half g_WvT [LATD*DMODEL];
__device__ __half g_WoT [DMODEL*DMODEL];
__device__ __half g_W1T [DMODEL*DMODEL];
__device__ __half g_cond[BGR*SEQ*LATD];
__device__ float  g_bq2 [DMODEL];
__device__ float  g_bk2 [DMODEL];
__device__ float  g_bv2 [DMODEL];
__device__ int    g_starts[BGR];

// ---------------- helpers ----------------
__device__ __forceinline__ unsigned f2tf32(float x) {
    unsigned y;
    asm("cvt.rna.tf32.f32 %0, %1;" : "=r"(y) : "f"(x));
    return y;
}
__device__ __forceinline__ float rtf(float x) { return __uint_as_float(f2tf32(x)); }

__device__ __forceinline__ void mma_tf32(float c[4],
    unsigned a0, unsigned a1, unsigned a2, unsigned a3,
    unsigned b0, unsigned b1)
{
    asm volatile(
        "mma.sync.aligned.m16n8k8.row.col.f32.tf32.tf32.f32 "
        "{%0,%1,%2,%3}, {%4,%5,%6,%7}, {%8,%9}, {%0,%1,%2,%3};"
        : "+f"(c[0]), "+f"(c[1]), "+f"(c[2]), "+f"(c[3])
        : "r"(a0), "r"(a1), "r"(a2), "r"(a3), "r"(b0), "r"(b1));
}

__device__ __forceinline__ void mma_f16(float c[4],
    unsigned a0, unsigned a1, unsigned a2, unsigned a3,
    unsigned b0, unsigned b1)
{
    asm volatile(
        "mma.sync.aligned.m16n8k16.row.col.f32.f16.f16.f32 "
        "{%0,%1,%2,%3}, {%4,%5,%6,%7}, {%8,%9}, {%0,%1,%2,%3};"
        : "+f"(c[0]), "+f"(c[1]), "+f"(c[2]), "+f"(c[3])
        : "r"(a0), "r"(a1), "r"(a2), "r"(a3), "r"(b0), "r"(b1));
}

#define CP16(dst, src) asm volatile("cp.async.cg.shared.global [%0], [%1], 16;" :: "r"(dst), "l"(src))
#define LDSM4(r, addr) asm volatile( \
    "ldmatrix.sync.aligned.m8n8.x4.shared.b16 {%0,%1,%2,%3}, [%4];" \
    : "=r"((r)[0]), "=r"((r)[1]), "=r"((r)[2]), "=r"((r)[3]) : "r"(addr))

__global__ void find_starts(const int* __restrict__ gb, int* starts, int n) {
    int i = blockIdx.x*blockDim.x + threadIdx.x;
    if (i < n) {
        if (i == 0 || gb[i] != gb[i-1]) starts[gb[i]] = i;
    }
}

// pad: writes raw fp32 (residual) + half (GEMM operand)
__global__ __launch_bounds__(128) void pad_kernel(
    const float* __restrict__ nodes, const int* __restrict__ starts,
    float* __restrict__ dense_f, __half* __restrict__ dense_h)
{
    int r = blockIdx.x;
    int b = r / LMAX, pp = r - b*LMAX;
    int s = starts[b];
    int e = (b == BGR-1) ? NN : starts[b+1];
    int i = s + pp;
    float4 v = make_float4(0.f, 0.f, 0.f, 0.f);
    if (i < e) v = ((const float4*)(nodes + (size_t)i*DMODEL))[threadIdx.x];
    ((float4*)(dense_f + (size_t)r*DMODEL))[threadIdx.x] = v;
    __half2* dh = (__half2*)(dense_h + (size_t)r*DMODEL);
    dh[threadIdx.x*2]   = __floats2half2_rn(v.x, v.y);
    dh[threadIdx.x*2+1] = __floats2half2_rn(v.z, v.w);
}

// conditioning -> half
__global__ void half_cond(const float* __restrict__ src, __half* __restrict__ dst) {
    int i = blockIdx.x*blockDim.x + threadIdx.x;
    int stride = gridDim.x*blockDim.x;
    int n4 = (BGR*SEQ*LATD) >> 2;
    for (; i < n4; i += stride) {
        float4 v = ((const float4*)src)[i];
        __half2* d = (__half2*)dst;
        d[i*2]   = __floats2half2_rn(v.x, v.y);
        d[i*2+1] = __floats2half2_rn(v.z, v.w);
    }
}

// transpose + half Wo / W1 (512x512)
__global__ __launch_bounds__(256) void halfT(
    const float* __restrict__ Wo, const float* __restrict__ W1,
    __half* __restrict__ dwo, __half* __restrict__ dw1)
{
    __shared__ float t[32][33];
    int z = blockIdx.z;
    const float* s = z ? W1 : Wo;
    __half* d = z ? dw1 : dwo;
    int bx = blockIdx.x*32, by = blockIdx.y*32;
    int x = threadIdx.x & 31, y0 = threadIdx.x >> 5;
    #pragma unroll
    for (int i = 0; i < 32; i += 8)
        t[y0+i][x] = s[(size_t)(by + y0 + i)*DMODEL + bx + x];
    __syncthreads();
    #pragma unroll
    for (int i = 0; i < 32; i += 8)
        d[(size_t)(bx + y0 + i)*DMODEL + by + x] = __float2half_rn(t[x][y0+i]);
}

// parallel bias combine (fp32)
__global__ __launch_bounds__(512) void bias3p(
    const float* __restrict__ bq, const float* __restrict__ bk,
    const float* __restrict__ bv, const float* __restrict__ inw,
    const float* __restrict__ inb,
    float* __restrict__ oq, float* __restrict__ ok, float* __restrict__ ov)
{
    __shared__ float red[8][64];
    int z = blockIdx.y;
    const float* bin = (z==0) ? bq : (z==1) ? bk : bv;
    const float* W = inw + (size_t)z*DMODEL*DMODEL;
    const float* ab = inb + z*DMODEL;
    float* outp = (z==0) ? oq : (z==1) ? ok : ov;
    int jj = threadIdx.x & 63;
    int r  = threadIdx.x >> 6;
    int j  = blockIdx.x*64 + jj;
    float a = 0.f;
    #pragma unroll 8
    for (int i = r*64; i < r*64 + 64; i++)
        a += bin[i]*W[(size_t)i*DMODEL + j];
    red[r][jj] = a;
    __syncthreads();
    if (r == 0) {
        float s = ab[j];
        #pragma unroll
        for (int k = 0; k < 8; k++) s += red[k][jj];
        outp[j] = s;
    }
}

// ---------------- fold3: weight GEMMs (tf32), epilogue writes half C^T ------
#define SMP 132

__global__ __launch_bounds__(256) void fold3_gemm(
    const float* __restrict__ Wq, const float* __restrict__ Wk,
    const float* __restrict__ Wv, const float* __restrict__ inw,
    __half* __restrict__ Cq, __half* __restrict__ Ck, __half* __restrict__ Cv)
{
    int z = blockIdx.z;
    int M = (z == 0) ? DMODEL : LATD;
    if ((int)blockIdx.y*128 >= M) return;
    const float* A = (z==0) ? Wq : (z==1) ? Wk : Wv;
    const float* B = inw + (size_t)z*DMODEL*DMODEL;
    __half* C = (z==0) ? Cq : (z==1) ? Ck : Cv;
    const int N = DMODEL, K = DMODEL;

    __shared__ unsigned As[16][SMP];
    __shared__ unsigned Bs[16][SMP];
    int tid = threadIdx.x;
    int warp = tid >> 5, lane = tid & 31;
    int warp_m = warp & 3, warp_n = warp >> 2;
    int p = lane >> 2, q = lane & 3;
    int blockM = blockIdx.y * 128;
    int blockN = blockIdx.x * 128;

    int ia0 = tid*2, ia1 = tid*2 + 1;
    int arow0 = ia0 >> 2, akq0 = ia0 & 3;
    int arow1 = ia1 >> 2, akq1 = ia1 & 3;
    int bk0 = ia0 >> 5, bn0 = ia0 & 31;
    int bk1 = ia1 >> 5, bn1 = ia1 & 31;

    const float* Ap0 = A + (size_t)(blockM + arow0)*K + akq0*4;
    const float* Ap1 = A + (size_t)(blockM + arow1)*K + akq1*4;
    const float* Bp0 = B + (size_t)bk0*N + blockN + bn0*4;
    const float* Bp1 = B + (size_t)bk1*N + blockN + bn1*4;

    float acc[2][8][4];
    #pragma unroll
    for (int mt = 0; mt < 2; mt++)
        #pragma unroll
        for (int nt = 0; nt < 8; nt++)
            #pragma unroll
            for (int i = 0; i < 4; i++) acc[mt][nt][i] = 0.f;

    float4 av0 = *(const float4*)(Ap0);
    float4 av1 = *(const float4*)(Ap1);
    float4 bv0 = *(const float4*)(Bp0);
    float4 bv1 = *(const float4*)(Bp1);

    for (int kt = 16; kt <= K; kt += 16) {
        As[akq0*4+0][arow0] = f2tf32(av0.x);
        As[akq0*4+1][arow0] = f2tf32(av0.y);
        As[akq0*4+2][arow0] = f2tf32(av0.z);
        As[akq0*4+3][arow0] = f2tf32(av0.w);
        As[akq1*4+0][arow1] = f2tf32(av1.x);
        As[akq1*4+1][arow1] = f2tf32(av1.y);
        As[akq1*4+2][arow1] = f2tf32(av1.z);
        As[akq1*4+3][arow1] = f2tf32(av1.w);
        {
            uint4 t0, t1;
            t0.x = f2tf32(bv0.x); t0.y = f2tf32(bv0.y);
            t0.z = f2tf32(bv0.z); t0.w = f2tf32(bv0.w);
            t1.x = f2tf32(bv1.x); t1.y = f2tf32(bv1.y);
            t1.z = f2tf32(bv1.z); t1.w = f2tf32(bv1.w);
            *(uint4*)&Bs[bk0][bn0*4] = t0;
            *(uint4*)&Bs[bk1][bn1*4] = t1;
        }
        __syncthreads();
        if (kt < K) {
            av0 = *(const float4*)(Ap0 + kt);
            av1 = *(const float4*)(Ap1 + kt);
            bv0 = *(const float4*)(Bp0 + (size_t)kt*N);
            bv1 = *(const float4*)(Bp1 + (size_t)kt*N);
        }
        #pragma unroll
        for (int kk = 0; kk < 16; kk += 8) {
            unsigned afr[2][4];
            #pragma unroll
            for (int mt = 0; mt < 2; mt++) {
                int mb = warp_m*32 + mt*16;
                afr[mt][0] = As[kk+q  ][mb + p];
                afr[mt][1] = As[kk+q  ][mb + p + 8];
                afr[mt][2] = As[kk+q+4][mb + p];
                afr[mt][3] = As[kk+q+4][mb + p + 8];
            }
            unsigned bfr[8][2];
            #pragma unroll
            for (int nt = 0; nt < 8; nt++) {
                int nb = warp_n*64 + nt*8;
                bfr[nt][0] = Bs[kk+q  ][nb + p];
                bfr[nt][1] = Bs[kk+q+4][nb + p];
            }
            #pragma unroll
            for (int mt = 0; mt < 2; mt++)
                #pragma unroll
                for (int nt = 0; nt < 8; nt++)
                    mma_tf32(acc[mt][nt], afr[mt][0], afr[mt][1], afr[mt][2], afr[mt][3],
                             bfr[nt][0], bfr[nt][1]);
        }
        __syncthreads();
    }

    // epilogue: write transposed half CT[n*M + m]
    #pragma unroll
    for (int mt = 0; mt < 2; mt++) {
        int r0 = blockM + warp_m*32 + mt*16 + p;
        #pragma unroll
        for (int nt = 0; nt < 8; nt++) {
            int c0 = blockN + warp_n*64 + nt*8 + 2*q;
            C[(size_t)(c0  )*M + r0    ] = __float2half_rn(acc[mt][nt][0]);
            C[(size_t)(c0+1)*M + r0    ] = __float2half_rn(acc[mt][nt][1]);
            C[(size_t)(c0  )*M + r0 + 8] = __float2half_rn(acc[mt][nt][2]);
            C[(size_t)(c0+1)*M + r0 + 8] = __float2half_rn(acc[mt][nt][3]);
        }
    }
}

// ---------------- 3-stage cp.async FP16 GEMM ----------------
// A row-major half [M][K]; Bt transposed half [N][K]. fp32 accum/epilogue.
#define TSTRH 40                          // halves per smem row (80 bytes)
#define STG_B (128*TSTRH*2)               // bytes per stage per operand (10240)
#define GEMM_SMEM (3*2*STG_B)             // 61440 bytes

template<int MODE, bool RND>
__device__ __forceinline__ void gemm_body(
    const __half* __restrict__ A, const __half* __restrict__ Bt,
    const float* __restrict__ bias, const float* __restrict__ Dm,
    float* __restrict__ C, int N, int K, char* smem)
{
    char* As = smem;
    char* Bs = smem + 3*STG_B;

    int tid = threadIdx.x;
    int warp = tid >> 5, lane = tid & 31;
    int warp_m = warp & 3, warp_n = warp >> 2;
    int p = lane >> 2, q = lane & 3;
    int blockM = blockIdx.y * 128;
    int blockN = blockIdx.x * 128;

    // gmem->smem: 512 chunks of 16B per operand per 32-K tile; 2 chunks/thread
    int c0 = tid*2, c1 = c0 + 1;
    int r0c = c0 >> 2, k0c = (c0 & 3)*8;   // halves
    int r1c = c1 >> 2, k1c = (c1 & 3)*8;

    const __half* gA0 = A  + (size_t)(blockM + r0c)*K + k0c;
    const __half* gA1 = A  + (size_t)(blockM + r1c)*K + k1c;
    const __half* gB0 = Bt + (size_t)(blockN + r0c)*K + k0c;
    const __half* gB1 = Bt + (size_t)(blockN + r1c)*K + k1c;

    unsigned sa = (unsigned)__cvta_generic_to_shared(As);
    unsigned sb = (unsigned)__cvta_generic_to_shared(Bs);
    unsigned dA0[3], dA1[3], dB0[3], dB1[3];
    #pragma unroll
    for (int s = 0; s < 3; s++) {
        dA0[s] = sa + s*STG_B + (r0c*TSTRH + k0c)*2;
        dA1[s] = sa + s*STG_B + (r1c*TSTRH + k1c)*2;
        dB0[s] = sb + s*STG_B + (r0c*TSTRH + k0c)*2;
        dB1[s] = sb + s*STG_B + (r1c*TSTRH + k1c)*2;
    }

    // ldmatrix per-lane bases (byte offsets)
    unsigned aBase = sa + ((warp_m*32 + (lane & 15))*TSTRH + (lane >> 4)*8)*2;
    unsigned bBase = sb + ((warp_n*64 + ((lane >> 4) << 3) + (lane & 7))*TSTRH
                           + ((lane >> 3) & 1)*8)*2;

    float acc[2][8][4];
    #pragma unroll
    for (int mt = 0; mt < 2; mt++)
        #pragma unroll
        for (int nt = 0; nt < 8; nt++)
            #pragma unroll
            for (int i = 0; i < 4; i++) acc[mt][nt][i] = 0.f;

    CP16(dA0[0], gA0); CP16(dA1[0], gA1);
    CP16(dB0[0], gB0); CP16(dB1[0], gB1);
    asm volatile("cp.async.commit_group;");
    CP16(dA0[1], gA0 + 32); CP16(dA1[1], gA1 + 32);
    CP16(dB0[1], gB0 + 32); CP16(dB1[1], gB1 + 32);
    asm volatile("cp.async.commit_group;");

    int nk = K >> 5;
    int sc = 0, sp = 2;
    for (int t = 0; t < nk; t++) {
        asm volatile("cp.async.wait_group 1;");
        __syncthreads();
        if (t + 2 < nk) {
            int kt = (t + 2) << 5;
            CP16(dA0[sp], gA0 + kt); CP16(dA1[sp], gA1 + kt);
            CP16(dB0[sp], gB0 + kt); CP16(dB1[sp], gB1 + kt);
        }
        asm volatile("cp.async.commit_group;");
        unsigned ao = aBase + sc*STG_B;
        unsigned bo = bBase + sc*STG_B;
        #pragma unroll
        for (int kk = 0; kk < 32; kk += 16) {
            unsigned afr[2][4];
            LDSM4(afr[0], ao + kk*2);
            LDSM4(afr[1], ao + (16*TSTRH + kk)*2);
            unsigned bfr[4][4];
            #pragma unroll
            for (int j = 0; j < 4; j++)
                LDSM4(bfr[j], bo + (j*16*TSTRH + kk)*2);
            #pragma unroll
            for (int mt = 0; mt < 2; mt++)
                #pragma unroll
                for (int nt = 0; nt < 8; nt++)
                    mma_f16(acc[mt][nt],
                            afr[mt][0], afr[mt][1], afr[mt][2], afr[mt][3],
                            bfr[nt >> 1][(nt & 1)*2], bfr[nt >> 1][(nt & 1)*2 + 1]);
        }
        sc++; if (sc == 3) sc = 0;
        sp++; if (sp == 3) sp = 0;
    }

    #pragma unroll
    for (int mt = 0; mt < 2; mt++) {
        int r0 = blockM + warp_m*32 + mt*16 + p;
        #pragma unroll
        for (int nt = 0; nt < 8; nt++) {
            int c0c = blockN + warp_n*64 + nt*8 + 2*q;
            float b0 = 0.f, b1 = 0.f;
            if (bias) { b0 = bias[c0c]; b1 = bias[c0c+1]; }
            float v0 = acc[mt][nt][0] + b0;
            float v1 = acc[mt][nt][1] + b1;
            float v2 = acc[mt][nt][2] + b0;
            float v3 = acc[mt][nt][3] + b1;
            size_t o0 = (size_t)r0*N + c0c;
            size_t o1 = (size_t)(r0+8)*N + c0c;
            if (MODE == 1) {
                float2 d0 = *(const float2*)(Dm + o0);
                float2 d1 = *(const float2*)(Dm + o1);
                v0 += d0.x; v1 += d0.y; v2 += d1.x; v3 += d1.y;
            }
            if (MODE == 2) {
                v0 = (v0 > 0.f) ? v0 : 0.01f*v0;
                v1 = (v1 > 0.f) ? v1 : 0.01f*v1;
                v2 = (v2 > 0.f) ? v2 : 0.01f*v2;
                v3 = (v3 > 0.f) ? v3 : 0.01f*v3;
                float2 d0 = *(const float2*)(Dm + o0);
                float2 d1 = *(const float2*)(Dm + o1);
                v0 += d0.x; v1 += d0.y; v2 += d1.x; v3 += d1.y;
            }
            if (RND) { v0 = rtf(v0); v1 = rtf(v1); v2 = rtf(v2); v3 = rtf(v3); }
            *(float2*)(C + o0) = make_float2(v0, v1);
            *(float2*)(C + o1) = make_float2(v2, v3);
        }
    }
}

template<int MODE, bool RND>
__global__ __launch_bounds__(256, 2) void gemm_one(
    const __half* __restrict__ A, const __half* __restrict__ Bt,
    const float* __restrict__ bias, const float* __restrict__ Dm,
    float* __restrict__ C, int N, int K)
{
    extern __shared__ char smem[];
    gemm_body<MODE, RND>(A, Bt, bias, Dm, C, N, K, smem);
}

__global__ __launch_bounds__(256, 2) void gemm_kv(
    const __half* __restrict__ cond,
    const __half* __restrict__ WkT, const __half* __restrict__ WvT,
    const float* __restrict__ bk2, const float* __restrict__ bv2,
    float* __restrict__ kh, float* __restrict__ vh)
{
    extern __shared__ char smem[];
    const __half* Bt = blockIdx.z ? WvT : WkT;
    const float* bias = blockIdx.z ? bv2 : bk2;
    float* C = blockIdx.z ? vh : kh;
    gemm_body<0, true>(cond, Bt, bias, nullptr, C, DMODEL, LATD, smem);
}

// ---------------- tensor-core attention (tf32; ctx written as half) --------
#define TB   64
#define KSTR 68
#define VSTR 72
#define PSTR 260
#define ATT_SMEM ((SEQ*KSTR + SEQ*VSTR + TB*PSTR)*4 + SEQ*4)

__global__ __launch_bounds__(512, 1) void attn_mma(
    const float* __restrict__ qh, const float* __restrict__ kh,
    const float* __restrict__ vh, const int* __restrict__ maskp,
    __half* __restrict__ ctx, float* __restrict__ av_out)
{
    extern __shared__ float sm[];
    float* sK = sm;
    float* sV = sK + SEQ*KSTR;
    float* sU = sV + SEQ*VSTR;
    int* sMask = (int*)(sU + TB*PSTR);

    int b = blockIdx.y, lt = blockIdx.x;
    int tid = threadIdx.x;
    int w = tid >> 5, lane = tid & 31;
    int p = lane >> 2, q = lane & 3;

    if (tid < SEQ) sMask[tid] = maskp[b*SEQ + tid];

    float avacc[2][4][4];
    #pragma unroll
    for (int j = 0; j < 2; j++)
        #pragma unroll
        for (int mt = 0; mt < 4; mt++)
            #pragma unroll
            for (int i = 0; i < 4; i++) avacc[j][mt][i] = 0.f;

    for (int h = 0; h < NH; h++) {
        __syncthreads();
        for (int idx = tid; idx < SEQ*DH; idx += 512) {
            int s = idx >> 6, d = idx & 63;
            size_t g = ((size_t)(b*SEQ + s))*DMODEL + h*DH + d;
            sK[s*KSTR + d] = kh[g];
            sV[s*VSTR + d] = vh[g];
        }
        for (int idx = tid; idx < TB*DH; idx += 512) {
            int r = idx >> 6, d = idx & 63;
            int l = lt*TB + r; if (l > LMAX-1) l = LMAX-1;
            sU[r*KSTR + d] = qh[((size_t)(b*LMAX) + l)*DMODEL + h*DH + d];
        }
        __syncthreads();

        float csc[2][4][4];
        #pragma unroll
        for (int j = 0; j < 2; j++)
            #pragma unroll
            for (int mt = 0; mt < 4; mt++)
                #pragma unroll
                for (int i = 0; i < 4; i++) csc[j][mt][i] = 0.f;
        #pragma unroll
        for (int k = 0; k < 8; k++) {
            int kc = k*8 + q;
            unsigned bf0[2], bf1[2];
            #pragma unroll
            for (int j = 0; j < 2; j++) {
                int sc = (2*w + j)*8 + p;
                bf0[j] = __float_as_uint(sK[sc*KSTR + kc]);
                bf1[j] = __float_as_uint(sK[sc*KSTR + kc + 4]);
            }
            #pragma unroll
            for (int mt = 0; mt < 4; mt++) {
                int r0 = mt*16 + p;
                unsigned a0 = __float_as_uint(sU[r0*KSTR + kc]);
                unsigned a1 = __float_as_uint(sU[(r0+8)*KSTR + kc]);
                unsigned a2 = __float_as_uint(sU[r0*KSTR + kc + 4]);
                unsigned a3 = __float_as_uint(sU[(r0+8)*KSTR + kc + 4]);
                mma_tf32(csc[0][mt], a0, a1, a2, a3, bf0[0], bf1[0]);
                mma_tf32(csc[1][mt], a0, a1, a2, a3, bf0[1], bf1[1]);
            }
        }
        __syncthreads();
        #pragma unroll
        for (int j = 0; j < 2; j++)
            #pragma unroll
            for (int mt = 0; mt < 4; mt++) {
                int row = mt*16 + p;
                int col = (2*w + j)*8 + 2*q;
                *(float2*)&sU[row*PSTR + col]     = make_float2(csc[j][mt][0], csc[j][mt][1]);
                *(float2*)&sU[(row+8)*PSTR + col] = make_float2(csc[j][mt][2], csc[j][mt][3]);
            }
        __syncthreads();
        #pragma unroll
        for (int rr = 0; rr < 4; rr++) {
            int row = 4*w + rr;
            float v[8];
            float m = -1e30f;
            #pragma unroll
            for (int jj = 0; jj < 8; jj++) {
                int s = lane + 32*jj;
                float x = sMask[s] ? -1e30f : sU[row*PSTR + s]*0.125f;
                v[jj] = x;
                m = fmaxf(m, x);
            }
            #pragma unroll
            for (int o = 16; o > 0; o >>= 1) m = fmaxf(m, __shfl_xor_sync(0xffffffffu, m, o));
            float sum = 0.f;
            #pragma unroll
            for (int jj = 0; jj < 8; jj++) { v[jj] = __expf(v[jj] - m); sum += v[jj]; }
            #pragma unroll
            for (int o = 16; o > 0; o >>= 1) sum += __shfl_xor_sync(0xffffffffu, sum, o);
            float inv = 1.f/sum;
            #pragma unroll
            for (int jj = 0; jj < 8; jj++)
                sU[row*PSTR + lane + 32*jj] = rtf(v[jj]*inv);
        }
        __syncthreads();
        #pragma unroll
        for (int j = 0; j < 2; j++)
            #pragma unroll
            for (int mt = 0; mt < 4; mt++) {
                int row = mt*16 + p;
                int col = (2*w + j)*8 + 2*q;
                avacc[j][mt][0] += sU[row*PSTR + col];
                avacc[j][mt][1] += sU[row*PSTR + col + 1];
                avacc[j][mt][2] += sU[(row+8)*PSTR + col];
                avacc[j][mt][3] += sU[(row+8)*PSTR + col + 1];
            }
        int mtw = w & 3, nt0 = w >> 2;
        float cct[2][4];
        #pragma unroll
        for (int j = 0; j < 2; j++)
            #pragma unroll
            for (int i = 0; i < 4; i++) cct[j][i] = 0.f;
        #pragma unroll 8
        for (int k = 0; k < 32; k++) {
            int sc = k*8 + q;
            int r0 = mtw*16 + p;
            unsigned a0 = __float_as_uint(sU[r0*PSTR + sc]);
            unsigned a1 = __float_as_uint(sU[(r0+8)*PSTR + sc]);
            unsigned a2 = __float_as_uint(sU[r0*PSTR + sc + 4]);
            unsigned a3 = __float_as_uint(sU[(r0+8)*PSTR + sc + 4]);
            #pragma unroll
            for (int j = 0; j < 2; j++) {
                int dc = (nt0 + 4*j)*8 + p;
                unsigned b0 = __float_as_uint(sV[sc*VSTR + dc]);
                unsigned b1 = __float_as_uint(sV[(sc+4)*VSTR + dc]);
                mma_tf32(cct[j], a0, a1, a2, a3, b0, b1);
            }
        }
        #pragma unroll
        for (int j = 0; j < 2; j++) {
            int dc = h*DH + (nt0 + 4*j)*8 + 2*q;
            int l0 = lt*TB + mtw*16 + p;
            if (l0 < LMAX)
                *(__half2*)&ctx[((size_t)(b*LMAX) + l0)*DMODEL + dc] =
                    __floats2half2_rn(cct[j][0], cct[j][1]);
            int l1 = l0 + 8;
            if (l1 < LMAX)
                *(__half2*)&ctx[((size_t)(b*LMAX) + l1)*DMODEL + dc] =
                    __floats2half2_rn(cct[j][2], cct[j][3]);
        }
    }

    #pragma unroll
    for (int j = 0; j < 2; j++)
        #pragma unroll
        for (int mt = 0; mt < 4; mt++) {
            int col = (2*w + j)*8 + 2*q;
            int l0 = lt*TB + mt*16 + p;
            if (l0 < LMAX)
                *(float2*)&av_out[((size_t)(b*LMAX) + l0)*SEQ + col] =
                    make_float2(avacc[j][mt][0]*0.125f, avacc[j][mt][1]*0.125f);
            int l1 = l0 + 8;
            if (l1 < LMAX)
                *(float2*)&av_out[((size_t)(b*LMAX) + l1)*SEQ + col] =
                    make_float2(avacc[j][mt][2]*0.125f, avacc[j][mt][3]*0.125f);
        }
}

// ---------------- LN1: writes fp32 residual + half GEMM operand ----------
__global__ __launch_bounds__(128) void ln_dual(
    const float* __restrict__ x, const float* __restrict__ g,
    const float* __restrict__ bb, float* __restrict__ yf, __half* __restrict__ yh)
{
    __shared__ float ws[4], wss[4];
    int r = blockIdx.x;
    int tid = threadIdx.x;
    const float4* xr = (const float4*)(x + (size_t)r*DMODEL);
    float4 v = xr[tid];
    float s  = v.x + v.y + v.z + v.w;
    float ss = v.x*v.x + v.y*v.y + v.z*v.z + v.w*v.w;
    #pragma unroll
    for (int o = 16; o > 0; o >>= 1) {
        s  += __shfl_xor_sync(0xffffffffu, s,  o);
        ss += __shfl_xor_sync(0xffffffffu, ss, o);
    }
    int warp = tid >> 5, lane = tid & 31;
    if (lane == 0) { ws[warp] = s; wss[warp] = ss; }
    __syncthreads();
    float S  = ws[0] + ws[1] + ws[2] + ws[3];
    float SS = wss[0] + wss[1] + wss[2] + wss[3];
    float mean = S * (1.f/DMODEL);
    float var  = SS * (1.f/DMODEL) - mean*mean;
    float rstd = rsqrtf(var + 1e-5f);
    float4 gg = ((const float4*)g)[tid];
    float4 b4 = ((const float4*)bb)[tid];
    float4 o4;
    o4.x = (v.x - mean)*rstd*gg.x + b4.x;
    o4.y = (v.y - mean)*rstd*gg.y + b4.y;
    o4.z = (v.z - mean)*rstd*gg.z + b4.z;
    o4.w = (v.w - mean)*rstd*gg.w + b4.w;
    ((float4*)(yf + (size_t)r*DMODEL))[tid] = o4;
    __half2* yhp = (__half2*)(yh + (size_t)r*DMODEL);
    yhp[tid*2]   = __floats2half2_rn(o4.x, o4.y);
    yhp[tid*2+1] = __floats2half2_rn(o4.z, o4.w);
}

// ---------------- fused LN2 + ragged gather ----------
__global__ __launch_bounds__(128) void ln_gather(
    const float* __restrict__ x, const int* __restrict__ gb,
    const int* __restrict__ starts,
    const float* __restrict__ g, const float* __restrict__ bb,
    float* __restrict__ out)
{
    __shared__ float ws[4], wss[4];
    int i = blockIdx.x;
    int b = gb[i];
    int pp = i - starts[b];
    size_t row = (size_t)b*LMAX + pp;
    int tid = threadIdx.x;
    float4 v = ((const float4*)(x + row*DMODEL))[tid];
    float s  = v.x + v.y + v.z + v.w;
    float ss = v.x*v.x + v.y*v.y + v.z*v.z + v.w*v.w;
    #pragma unroll
    for (int o = 16; o > 0; o >>= 1) {
        s  += __shfl_xor_sync(0xffffffffu, s,  o);
        ss += __shfl_xor_sync(0xffffffffu, ss, o);
    }
    int warp = tid >> 5, lane = tid & 31;
    if (lane == 0) { ws[warp] = s; wss[warp] = ss; }
    __syncthreads();
    float S  = ws[0] + ws[1] + ws[2] + ws[3];
    float SS = wss[0] + wss[1] + wss[2] + wss[3];
    float mean = S * (1.f/DMODEL);
    float var  = SS * (1.f/DMODEL) - mean*mean;
    float rstd = rsqrtf(var + 1e-5f);
    float4 gg = ((const float4*)g)[tid];
    float4 b4 = ((const float4*)bb)[tid];
    float4 o4;
    o4.x = (v.x - mean)*rstd*gg.x + b4.x;
    o4.y = (v.y - mean)*rstd*gg.y + b4.y;
    o4.z = (v.z - mean)*rstd*gg.z + b4.z;
    o4.w = (v.w - mean)*rstd*gg.w + b4.w;
    ((float4*)(out + (size_t)i*DMODEL))[tid] = o4;
}

// ---------------- launch ----------------
extern "C" void kernel_launch(void* const* d_in, const int* in_sizes, int n_in,
                              void* d_out, int out_size)
{
    int off = (n_in >= 22) ? 0 : 2;
    const float* nodes  = (const float*)d_in[0];
    const int*   gb     = (const int*)  d_in[1];
    const float* cond   = (const float*)d_in[2];
    const int*   maskp  = (const int*)  d_in[3];
    const float* Wq     = (const float*)d_in[6-off];
    const float* bq     = (const float*)d_in[7-off];
    const float* Wk     = (const float*)d_in[8-off];
    const float* bk     = (const float*)d_in[9-off];
    const float* Wv     = (const float*)d_in[10-off];
    const float* bv     = (const float*)d_in[11-off];
    const float* in_w   = (const float*)d_in[12-off];
    const float* in_b   = (const float*)d_in[13-off];
    const float* Wo     = (const float*)d_in[14-off];
    const float* bo     = (const float*)d_in[15-off];
    const float* ln1g   = (const float*)d_in[16-off];
    const float* ln1b   = (const float*)d_in[17-off];
    const float* W1     = (const float*)d_in[18-off];
    const float* b1     = (const float*)d_in[19-off];
    const float* ln2g   = (const float*)d_in[20-off];
    const float* ln2b   = (const float*)d_in[21-off];
    float* out = (float*)d_out;
    float* av_out = out + (size_t)NN*DMODEL;

    float *p_dense_f, *p_qh, *p_kh, *p_vh, *p_y, *p_x1f, *p_h;
    float *p_bq2, *p_bk2, *p_bv2;
    __half *p_dense_h, *p_ctx, *p_x1h, *p_WqT, *p_WkT, *p_WvT, *p_WoT, *p_W1T, *p_cond;
    int *p_starts;
    cudaGetSymbolAddress((void**)&p_dense_f, g_dense_f);
    cudaGetSymbolAddress((void**)&p_dense_h, g_dense_h);
    cudaGetSymbolAddress((void**)&p_qh, g_qh);
    cudaGetSymbolAddress((void**)&p_kh, g_kh);
    cudaGetSymbolAddress((void**)&p_vh, g_vh);
    cudaGetSymbolAddress((void**)&p_ctx, g_ctx);
    cudaGetSymbolAddress((void**)&p_y, g_y);
    cudaGetSymbolAddress((void**)&p_x1f, g_x1f);
    cudaGetSymbolAddress((void**)&p_x1h, g_x1h);
    cudaGetSymbolAddress((void**)&p_h, g_h);
    cudaGetSymbolAddress((void**)&p_WqT, g_WqT);
    cudaGetSymbolAddress((void**)&p_WkT, g_WkT);
    cudaGetSymbolAddress((void**)&p_WvT, g_WvT);
    cudaGetSymbolAddress((void**)&p_WoT, g_WoT);
    cudaGetSymbolAddress((void**)&p_W1T, g_W1T);
    cudaGetSymbolAddress((void**)&p_cond, g_cond);
    cudaGetSymbolAddress((void**)&p_bq2, g_bq2);
    cudaGetSymbolAddress((void**)&p_bk2, g_bk2);
    cudaGetSymbolAddress((void**)&p_bv2, g_bv2);
    cudaGetSymbolAddress((void**)&p_starts, g_starts);

    cudaFuncSetAttribute(gemm_one<0,true>,  cudaFuncAttributeMaxDynamicSharedMemorySize, GEMM_SMEM);
    cudaFuncSetAttribute(gemm_one<1,false>, cudaFuncAttributeMaxDynamicSharedMemorySize, GEMM_SMEM);
    cudaFuncSetAttribute(gemm_one<2,false>, cudaFuncAttributeMaxDynamicSharedMemorySize, GEMM_SMEM);
    cudaFuncSetAttribute(gemm_kv,           cudaFuncAttributeMaxDynamicSharedMemorySize, GEMM_SMEM);
    cudaFuncSetAttribute(attn_mma,          cudaFuncAttributeMaxDynamicSharedMemorySize, ATT_SMEM);

    // 1) conditioning -> half
    half_cond<<<512, 256>>>(cond, p_cond);
    // 2) fold projection weights -> transposed half
    fold3_gemm<<<dim3(4,6,3), 256>>>(Wq, Wk, Wv, in_w, p_WqT, p_WkT, p_WvT);
    // 3) bias combines
    bias3p<<<dim3(8,3), 512>>>(bq, bk, bv, in_w, in_b, p_bq2, p_bk2, p_bv2);
    // 4) K/V projections  <-- profiled launch
    gemm_kv<<<dim3(4,32,2), 256, GEMM_SMEM>>>(p_cond, p_WkT, p_WvT, p_bk2, p_bv2, p_kh, p_vh);
    // 5) transpose+half Wo, W1
    halfT<<<dim3(16,16,2), 256>>>(Wo, W1, p_WoT, p_W1T);
    // 6) ragged bookkeeping + dense padding (fp32 raw + half)
    find_starts<<<(NN+255)/256, 256>>>(gb, p_starts, NN);
    pad_kernel<<<ROWS_Q, 128>>>(nodes, p_starts, p_dense_f, p_dense_h);
    // 7) Q projection (output tf32-rounded for attention)
    gemm_one<0,true><<<dim3(4,124), 256, GEMM_SMEM>>>(p_dense_h, p_WqT, p_bq2, nullptr, p_qh, DMODEL, DMODEL);
    // 8) attention (ctx -> half)
    attn_mma<<<dim3(16, BGR), 512, ATT_SMEM>>>(p_qh, p_kh, p_vh, maskp, p_ctx, av_out);
    // 9) out proj + residual (raw fp32 dense)
    gemm_one<1,false><<<dim3(4,124), 256, GEMM_SMEM>>>(p_ctx, p_WoT, bo, p_dense_f, p_y, DMODEL, DMODEL);
    // 10) LN1 -> fp32 residual + half operand
    ln_dual<<<ROWS_Q, 128>>>(p_y, ln1g, ln1b, p_x1f, p_x1h);
    // 11) FFN + leaky + residual (raw fp32 x1)
    gemm_one<2,false><<<dim3(4,124), 256, GEMM_SMEM>>>(p_x1h, p_W1T, b1, p_x1f, p_h, DMODEL, DMODEL);
    // 12) LN2 fused with ragged gather
    ln_gather<<<NN, 128>>>(p_h, gb, p_starts, ln2g, ln2b, out);
}

// round 8
// speedup vs baseline: 4.9956x; 1.0887x over previous
#include <cuda_runtime.h>
#include <cuda_fp16.h>
#include <cuda_bf16.h>
#include <math.h>

// ---------------- problem constants ----------------
#define NN    12032
#define DMODEL 512
#define BGR   16
#define SEQ   256
#define NH    8
#define DH    64
#define LMAX  992
#define LATD  768
#define ROWS_Q  (BGR*LMAX)   // 15872
#define ROWS_KV (BGR*SEQ)    // 4096

// ---------------- scratch ----------
__device__ float  g_dense_f[ROWS_Q*DMODEL];
__device__ __half g_dense_h[ROWS_Q*DMODEL];
__device__ __half g_qh2 [ROWS_Q*DMODEL];
__device__ __half g_kh2 [ROWS_KV*DMODEL];
__device__ __half g_vh2 [ROWS_KV*DMODEL];
__device__ __half g_ctx [ROWS_Q*DMODEL];
__device__ float  g_y   [ROWS_Q*DMODEL];
__device__ float  g_x1f [ROWS_Q*DMODEL];
__device__ __half g_x1h [ROWS_Q*DMODEL];
__device__ float  g_h   [ROWS_Q*DMODEL];
__device__ __half g_WqT [DMODEL*DMODEL];
__device__ __half g_WkT [LATD*DMODEL];
__device__ __half g_WvT [LATD*DMODEL];
__device__ __half g_WoT [DMODEL*DMODEL];
__device__ __half g_W1T [DMODEL*DMODEL];
__device__ __half g_cond[BGR*SEQ*LATD];
__device__ float  g_bq2 [DMODEL];
__device__ float  g_bk2 [DMODEL];
__device__ float  g_bv2 [DMODEL];

// ---------------- helpers ----------------
__device__ __forceinline__ unsigned f2tf32(float x) {
    unsigned y;
    asm("cvt.rna.tf32.f32 %0, %1;" : "=r"(y) : "f"(x));
    return y;
}

__device__ __forceinline__ void mma_tf32(float c[4],
    unsigned a0, unsigned a1, unsigned a2, unsigned a3,
    unsigned b0, unsigned b1)
{
    asm volatile(
        "mma.sync.aligned.m16n8k8.row.col.f32.tf32.tf32.f32 "
        "{%0,%1,%2,%3}, {%4,%5,%6,%7}, {%8,%9}, {%0,%1,%2,%3};"
        : "+f"(c[0]), "+f"(c[1]), "+f"(c[2]), "+f"(c[3])
        : "r"(a0), "r"(a1), "r"(a2), "r"(a3), "r"(b0), "r"(b1));
}

__device__ __forceinline__ void mma_f16(float c[4],
    unsigned a0, unsigned a1, unsigned a2, unsigned a3,
    unsigned b0, unsigned b1)
{
    asm volatile(
        "mma.sync.aligned.m16n8k16.row.col.f32.f16.f16.f32 "
        "{%0,%1,%2,%3}, {%4,%5,%6,%7}, {%8,%9}, {%0,%1,%2,%3};"
        : "+f"(c[0]), "+f"(c[1]), "+f"(c[2]), "+f"(c[3])
        : "r"(a0), "r"(a1), "r"(a2), "r"(a3), "r"(b0), "r"(b1));
}

#define CP16(dst, src) asm volatile("cp.async.cg.shared.global [%0], [%1], 16;" :: "r"(dst), "l"(src))
#define LDSM4(r, addr) asm volatile( \
    "ldmatrix.sync.aligned.m8n8.x4.shared.b16 {%0,%1,%2,%3}, [%4];" \
    : "=r"((r)[0]), "=r"((r)[1]), "=r"((r)[2]), "=r"((r)[3]) : "r"(addr))

__device__ __forceinline__ int lower_bound_gb(const int* __restrict__ gb, int b) {
    int lo = 0, hi = NN;
    while (lo < hi) { int mid = (lo + hi) >> 1; if (gb[mid] < b) lo = mid + 1; else hi = mid; }
    return lo;
}

// ---------------- mega-prologue: pad + cond->half + W transpose + bias -----
#define PM_PAD   ROWS_Q            // 15872
#define PM_COND  (PM_PAD + 2048)   // 17920
#define PM_HT    (PM_COND + 512)   // 18432
#define PM_BIAS  (PM_HT + 48)      // 18480

__global__ __launch_bounds__(128) void prologue_misc(
    const float* __restrict__ nodes, const int* __restrict__ gb,
    const float* __restrict__ cond,  const float* __restrict__ Wo,
    const float* __restrict__ W1,
    const float* __restrict__ bq, const float* __restrict__ bk,
    const float* __restrict__ bv, const float* __restrict__ inw,
    const float* __restrict__ inb,
    float* __restrict__ dense_f, __half* __restrict__ dense_h,
    __half* __restrict__ cond_h, __half* __restrict__ WoT, __half* __restrict__ W1T,
    float* __restrict__ bq2, float* __restrict__ bk2, float* __restrict__ bv2)
{
    __shared__ float sh[32*33];
    int bid = blockIdx.x, tid = threadIdx.x;
    if (bid < PM_PAD) {
        // pad role: one block per dense row (binary search for start)
        int r = bid;
        int b = r / LMAX, pp = r - b*LMAX;
        int start = lower_bound_gb(gb, b);
        int i = start + pp;
        float4 v = make_float4(0.f, 0.f, 0.f, 0.f);
        if (i < NN && gb[i] == b)
            v = ((const float4*)(nodes + (size_t)i*DMODEL))[tid];
        ((float4*)(dense_f + (size_t)r*DMODEL))[tid] = v;
        __half2* dh = (__half2*)(dense_h + (size_t)r*DMODEL);
        dh[tid*2]   = __floats2half2_rn(v.x, v.y);
        dh[tid*2+1] = __floats2half2_rn(v.z, v.w);
    } else if (bid < PM_COND) {
        int j = bid - PM_PAD;
        int n4 = (BGR*SEQ*LATD) >> 2;
        for (int i = j*128 + tid; i < n4; i += 2048*128) {
            float4 v = ((const float4*)cond)[i];
            __half2* d = (__half2*)cond_h;
            d[i*2]   = __floats2half2_rn(v.x, v.y);
            d[i*2+1] = __floats2half2_rn(v.z, v.w);
        }
    } else if (bid < PM_HT) {
        int t = bid - PM_COND;
        int z = t >> 8, rem = t & 255;
        const float* s = z ? W1 : Wo;
        __half* d = z ? W1T : WoT;
        int bx = (rem & 15)*32, by = (rem >> 4)*32;
        int x = tid & 31, y0 = tid >> 5;
        #pragma unroll
        for (int i = 0; i < 32; i += 4)
            sh[(y0+i)*33 + x] = s[(size_t)(by + y0 + i)*DMODEL + bx + x];
        __syncthreads();
        #pragma unroll
        for (int i = 0; i < 32; i += 4)
            d[(size_t)(bx + y0 + i)*DMODEL + by + x] = __float2half_rn(sh[x*33 + y0+i]);
    } else {
        int t = bid - PM_HT;
        int z = t >> 4, blk = t & 15;
        const float* bin = (z==0) ? bq : (z==1) ? bk : bv;
        const float* W = inw + (size_t)z*DMODEL*DMODEL;
        const float* ab = inb + z*DMODEL;
        float* outp = (z==0) ? bq2 : (z==1) ? bk2 : bv2;
        int jj = tid & 31;
        int r = tid >> 5;                 // 0..3
        int j = blk*32 + jj;
        float a = 0.f;
        #pragma unroll 8
        for (int i = r*128; i < r*128 + 128; i++)
            a += bin[i]*W[(size_t)i*DMODEL + j];
        sh[r*32 + jj] = a;
        __syncthreads();
        if (r == 0) {
            float s = ab[j];
            #pragma unroll
            for (int k = 0; k < 4; k++) s += sh[k*32 + jj];
            outp[j] = s;
        }
    }
}

// ---------------- fold3: weight GEMMs (tf32), writes half C^T ---------------
#define SMP 132

__global__ __launch_bounds__(256) void fold3_gemm(
    const float* __restrict__ Wq, const float* __restrict__ Wk,
    const float* __restrict__ Wv, const float* __restrict__ inw,
    __half* __restrict__ Cq, __half* __restrict__ Ck, __half* __restrict__ Cv)
{
    int z = blockIdx.z;
    int M = (z == 0) ? DMODEL : LATD;
    if ((int)blockIdx.y*128 >= M) return;
    const float* A = (z==0) ? Wq : (z==1) ? Wk : Wv;
    const float* B = inw + (size_t)z*DMODEL*DMODEL;
    __half* C = (z==0) ? Cq : (z==1) ? Ck : Cv;
    const int N = DMODEL, K = DMODEL;

    __shared__ unsigned As[16][SMP];
    __shared__ unsigned Bs[16][SMP];
    int tid = threadIdx.x;
    int warp = tid >> 5, lane = tid & 31;
    int warp_m = warp & 3, warp_n = warp >> 2;
    int p = lane >> 2, q = lane & 3;
    int blockM = blockIdx.y * 128;
    int blockN = blockIdx.x * 128;

    int ia0 = tid*2, ia1 = tid*2 + 1;
    int arow0 = ia0 >> 2, akq0 = ia0 & 3;
    int arow1 = ia1 >> 2, akq1 = ia1 & 3;
    int bk0 = ia0 >> 5, bn0 = ia0 & 31;
    int bk1 = ia1 >> 5, bn1 = ia1 & 31;

    const float* Ap0 = A + (size_t)(blockM + arow0)*K + akq0*4;
    const float* Ap1 = A + (size_t)(blockM + arow1)*K + akq1*4;
    const float* Bp0 = B + (size_t)bk0*N + blockN + bn0*4;
    const float* Bp1 = B + (size_t)bk1*N + blockN + bn1*4;

    float acc[2][8][4];
    #pragma unroll
    for (int mt = 0; mt < 2; mt++)
        #pragma unroll
        for (int nt = 0; nt < 8; nt++)
            #pragma unroll
            for (int i = 0; i < 4; i++) acc[mt][nt][i] = 0.f;

    float4 av0 = *(const float4*)(Ap0);
    float4 av1 = *(const float4*)(Ap1);
    float4 bv0 = *(const float4*)(Bp0);
    float4 bv1 = *(const float4*)(Bp1);

    for (int kt = 16; kt <= K; kt += 16) {
        As[akq0*4+0][arow0] = f2tf32(av0.x);
        As[akq0*4+1][arow0] = f2tf32(av0.y);
        As[akq0*4+2][arow0] = f2tf32(av0.z);
        As[akq0*4+3][arow0] = f2tf32(av0.w);
        As[akq1*4+0][arow1] = f2tf32(av1.x);
        As[akq1*4+1][arow1] = f2tf32(av1.y);
        As[akq1*4+2][arow1] = f2tf32(av1.z);
        As[akq1*4+3][arow1] = f2tf32(av1.w);
        {
            uint4 t0, t1;
            t0.x = f2tf32(bv0.x); t0.y = f2tf32(bv0.y);
            t0.z = f2tf32(bv0.z); t0.w = f2tf32(bv0.w);
            t1.x = f2tf32(bv1.x); t1.y = f2tf32(bv1.y);
            t1.z = f2tf32(bv1.z); t1.w = f2tf32(bv1.w);
            *(uint4*)&Bs[bk0][bn0*4] = t0;
            *(uint4*)&Bs[bk1][bn1*4] = t1;
        }
        __syncthreads();
        if (kt < K) {
            av0 = *(const float4*)(Ap0 + kt);
            av1 = *(const float4*)(Ap1 + kt);
            bv0 = *(const float4*)(Bp0 + (size_t)kt*N);
            bv1 = *(const float4*)(Bp1 + (size_t)kt*N);
        }
        #pragma unroll
        for (int kk = 0; kk < 16; kk += 8) {
            unsigned afr[2][4];
            #pragma unroll
            for (int mt = 0; mt < 2; mt++) {
                int mb = warp_m*32 + mt*16;
                afr[mt][0] = As[kk+q  ][mb + p];
                afr[mt][1] = As[kk+q  ][mb + p + 8];
                afr[mt][2] = As[kk+q+4][mb + p];
                afr[mt][3] = As[kk+q+4][mb + p + 8];
            }
            unsigned bfr[8][2];
            #pragma unroll
            for (int nt = 0; nt < 8; nt++) {
                int nb = warp_n*64 + nt*8;
                bfr[nt][0] = Bs[kk+q  ][nb + p];
                bfr[nt][1] = Bs[kk+q+4][nb + p];
            }
            #pragma unroll
            for (int mt = 0; mt < 2; mt++)
                #pragma unroll
                for (int nt = 0; nt < 8; nt++)
                    mma_tf32(acc[mt][nt], afr[mt][0], afr[mt][1], afr[mt][2], afr[mt][3],
                             bfr[nt][0], bfr[nt][1]);
        }
        __syncthreads();
    }

    #pragma unroll
    for (int mt = 0; mt < 2; mt++) {
        int r0 = blockM + warp_m*32 + mt*16 + p;
        #pragma unroll
        for (int nt = 0; nt < 8; nt++) {
            int c0 = blockN + warp_n*64 + nt*8 + 2*q;
            C[(size_t)(c0  )*M + r0    ] = __float2half_rn(acc[mt][nt][0]);
            C[(size_t)(c0+1)*M + r0    ] = __float2half_rn(acc[mt][nt][1]);
            C[(size_t)(c0  )*M + r0 + 8] = __float2half_rn(acc[mt][nt][2]);
            C[(size_t)(c0+1)*M + r0 + 8] = __float2half_rn(acc[mt][nt][3]);
        }
    }
}

// ---------------- 3-stage cp.async FP16 GEMM ----------------
// MODE 0: C(fp32) = A@B + bias ; MODE 1: += Dm ; MODE 2: leaky+ += Dm
// MODE 3: C(half) = A@B + bias
#define TSTRH 40
#define STG_B (128*TSTRH*2)
#define GEMM_SMEM (3*2*STG_B)

template<int MODE>
__device__ __forceinline__ void gemm_body(
    const __half* __restrict__ A, const __half* __restrict__ Bt,
    const float* __restrict__ bias, const float* __restrict__ Dm,
    void* __restrict__ Cv, int N, int K, char* smem)
{
    char* As = smem;
    char* Bs = smem + 3*STG_B;

    int tid = threadIdx.x;
    int warp = tid >> 5, lane = tid & 31;
    int warp_m = warp & 3, warp_n = warp >> 2;
    int p = lane >> 2, q = lane & 3;
    int blockM = blockIdx.y * 128;
    int blockN = blockIdx.x * 128;

    int c0 = tid*2, c1 = c0 + 1;
    int r0c = c0 >> 2, k0c = (c0 & 3)*8;
    int r1c = c1 >> 2, k1c = (c1 & 3)*8;

    const __half* gA0 = A  + (size_t)(blockM + r0c)*K + k0c;
    const __half* gA1 = A  + (size_t)(blockM + r1c)*K + k1c;
    const __half* gB0 = Bt + (size_t)(blockN + r0c)*K + k0c;
    const __half* gB1 = Bt + (size_t)(blockN + r1c)*K + k1c;

    unsigned sa = (unsigned)__cvta_generic_to_shared(As);
    unsigned sb = (unsigned)__cvta_generic_to_shared(Bs);
    unsigned dA0[3], dA1[3], dB0[3], dB1[3];
    #pragma unroll
    for (int s = 0; s < 3; s++) {
        dA0[s] = sa + s*STG_B + (r0c*TSTRH + k0c)*2;
        dA1[s] = sa + s*STG_B + (r1c*TSTRH + k1c)*2;
        dB0[s] = sb + s*STG_B + (r0c*TSTRH + k0c)*2;
        dB1[s] = sb + s*STG_B + (r1c*TSTRH + k1c)*2;
    }

    unsigned aBase = sa + ((warp_m*32 + (lane & 15))*TSTRH + (lane >> 4)*8)*2;
    unsigned bBase = sb + ((warp_n*64 + ((lane >> 4) << 3) + (lane & 7))*TSTRH
                           + ((lane >> 3) & 1)*8)*2;

    float acc[2][8][4];
    #pragma unroll
    for (int mt = 0; mt < 2; mt++)
        #pragma unroll
        for (int nt = 0; nt < 8; nt++)
            #pragma unroll
            for (int i = 0; i < 4; i++) acc[mt][nt][i] = 0.f;

    CP16(dA0[0], gA0); CP16(dA1[0], gA1);
    CP16(dB0[0], gB0); CP16(dB1[0], gB1);
    asm volatile("cp.async.commit_group;");
    CP16(dA0[1], gA0 + 32); CP16(dA1[1], gA1 + 32);
    CP16(dB0[1], gB0 + 32); CP16(dB1[1], gB1 + 32);
    asm volatile("cp.async.commit_group;");

    int nk = K >> 5;
    int sc = 0, sp = 2;
    for (int t = 0; t < nk; t++) {
        asm volatile("cp.async.wait_group 1;");
        __syncthreads();
        if (t + 2 < nk) {
            int kt = (t + 2) << 5;
            CP16(dA0[sp], gA0 + kt); CP16(dA1[sp], gA1 + kt);
            CP16(dB0[sp], gB0 + kt); CP16(dB1[sp], gB1 + kt);
        }
        asm volatile("cp.async.commit_group;");
        unsigned ao = aBase + sc*STG_B;
        unsigned bo = bBase + sc*STG_B;
        #pragma unroll
        for (int kk = 0; kk < 32; kk += 16) {
            unsigned afr[2][4];
            LDSM4(afr[0], ao + kk*2);
            LDSM4(afr[1], ao + (16*TSTRH + kk)*2);
            unsigned bfr[4][4];
            #pragma unroll
            for (int j = 0; j < 4; j++)
                LDSM4(bfr[j], bo + (j*16*TSTRH + kk)*2);
            #pragma unroll
            for (int mt = 0; mt < 2; mt++)
                #pragma unroll
                for (int nt = 0; nt < 8; nt++)
                    mma_f16(acc[mt][nt],
                            afr[mt][0], afr[mt][1], afr[mt][2], afr[mt][3],
                            bfr[nt >> 1][(nt & 1)*2], bfr[nt >> 1][(nt & 1)*2 + 1]);
        }
        sc++; if (sc == 3) sc = 0;
        sp++; if (sp == 3) sp = 0;
    }

    #pragma unroll
    for (int mt = 0; mt < 2; mt++) {
        int r0 = blockM + warp_m*32 + mt*16 + p;
        #pragma unroll
        for (int nt = 0; nt < 8; nt++) {
            int c0c = blockN + warp_n*64 + nt*8 + 2*q;
            float b0 = 0.f, b1 = 0.f;
            if (bias) { b0 = bias[c0c]; b1 = bias[c0c+1]; }
            float v0 = acc[mt][nt][0] + b0;
            float v1 = acc[mt][nt][1] + b1;
            float v2 = acc[mt][nt][2] + b0;
            float v3 = acc[mt][nt][3] + b1;
            size_t o0 = (size_t)r0*N + c0c;
            size_t o1 = (size_t)(r0+8)*N + c0c;
            if (MODE == 3) {
                __half* Ch = (__half*)Cv;
                *(__half2*)&Ch[o0] = __floats2half2_rn(v0, v1);
                *(__half2*)&Ch[o1] = __floats2half2_rn(v2, v3);
            } else {
                float* C = (float*)Cv;
                if (MODE == 1) {
                    float2 d0 = *(const float2*)(Dm + o0);
                    float2 d1 = *(const float2*)(Dm + o1);
                    v0 += d0.x; v1 += d0.y; v2 += d1.x; v3 += d1.y;
                }
                if (MODE == 2) {
                    v0 = (v0 > 0.f) ? v0 : 0.01f*v0;
                    v1 = (v1 > 0.f) ? v1 : 0.01f*v1;
                    v2 = (v2 > 0.f) ? v2 : 0.01f*v2;
                    v3 = (v3 > 0.f) ? v3 : 0.01f*v3;
                    float2 d0 = *(const float2*)(Dm + o0);
                    float2 d1 = *(const float2*)(Dm + o1);
                    v0 += d0.x; v1 += d0.y; v2 += d1.x; v3 += d1.y;
                }
                *(float2*)(C + o0) = make_float2(v0, v1);
                *(float2*)(C + o1) = make_float2(v2, v3);
            }
        }
    }
}

template<int MODE>
__global__ __launch_bounds__(256, 2) void gemm_one(
    const __half* __restrict__ A, const __half* __restrict__ Bt,
    const float* __restrict__ bias, const float* __restrict__ Dm,
    float* __restrict__ C, int N, int K)
{
    extern __shared__ char smem[];
    gemm_body<MODE>(A, Bt, bias, Dm, C, N, K, smem);
}

// Q + K + V projections in one launch (half outputs)
__global__ __launch_bounds__(256, 2) void gemm_all(
    const __half* __restrict__ dense_h, const __half* __restrict__ cond_h,
    const __half* __restrict__ WqT, const __half* __restrict__ WkT,
    const __half* __restrict__ WvT,
    const float* __restrict__ bq2, const float* __restrict__ bk2,
    const float* __restrict__ bv2,
    __half* __restrict__ qh2, __half* __restrict__ kh2, __half* __restrict__ vh2)
{
    extern __shared__ char smem[];
    int z = blockIdx.z;
    if (z < 2) {
        if (blockIdx.y >= 32) return;
        gemm_body<3>(cond_h, z ? WvT : WkT, z ? bv2 : bk2, nullptr,
                     z ? (void*)vh2 : (void*)kh2, DMODEL, LATD, smem);
    } else {
        gemm_body<3>(dense_h, WqT, bq2, nullptr, (void*)qh2, DMODEL, DMODEL, smem);
    }
}

// ---------------- fp16 tensor-core attention ----------------
// smem (bytes): sK [256][72]h = 36864 ; sVt [64][264]h = 33792 ;
//               sU (Q [64][72]h / scores+P [64][264]h) = 33792 ; mask = 1024
#define TB    64
#define QKSTR 72
#define PSTRH 264
#define SM_K  0
#define SM_VT 36864
#define SM_U  (36864 + 33792)
#define SM_MASK (SM_U + 33792)
#define ATT_SMEM (SM_MASK + SEQ*4)

__global__ __launch_bounds__(512, 1) void attn_f16(
    const __half* __restrict__ qh2, const __half* __restrict__ kh2,
    const __half* __restrict__ vh2, const int* __restrict__ maskp,
    __half* __restrict__ ctx, float* __restrict__ av_out)
{
    extern __shared__ char smc[];
    __half* sK  = (__half*)(smc + SM_K);
    __half* sVt = (__half*)(smc + SM_VT);
    __half* sU  = (__half*)(smc + SM_U);
    int* sMask  = (int*)(smc + SM_MASK);

    int b = blockIdx.y, lt = blockIdx.x;
    int tid = threadIdx.x;
    int w = tid >> 5, lane = tid & 31;
    int p = lane >> 2, q = lane & 3;

    if (tid < SEQ) sMask[tid] = maskp[b*SEQ + tid];

    // per-lane ldmatrix bases (byte offsets within smem regions)
    unsigned su = (unsigned)__cvta_generic_to_shared(sU);
    unsigned sk = (unsigned)__cvta_generic_to_shared(sK);
    unsigned sv = (unsigned)__cvta_generic_to_shared(sVt);
    unsigned aQ = su + (((lane & 15))*QKSTR + (lane >> 4)*8)*2;
    unsigned bK = sk + ((w*16 + ((lane >> 4) << 3) + (lane & 7))*QKSTR + ((lane >> 3) & 1)*8)*2;
    int mtw = w & 3, nt0 = w >> 2;
    unsigned aP = su + ((mtw*16 + (lane & 15))*PSTRH + (lane >> 4)*8)*2;
    unsigned bV = sv + ((nt0*8 + (lane >> 4)*32 + (lane & 7))*PSTRH + ((lane >> 3) & 1)*8)*2;

    float avacc[4][8];
    #pragma unroll
    for (int rr = 0; rr < 4; rr++)
        #pragma unroll
        for (int jj = 0; jj < 8; jj++) avacc[rr][jj] = 0.f;

    for (int h = 0; h < NH; h++) {
        __syncthreads();   // smem reuse (also covers sMask at h=0)
        // K half2 loads: [256][32 half2]
        {
            const __half2* kg = (const __half2*)kh2;
            __half2* k2 = (__half2*)sK;
            for (int idx = tid; idx < SEQ*32; idx += 512) {
                int s = idx >> 5, d2 = idx & 31;
                k2[s*(QKSTR/2) + d2] = kg[((size_t)(b*SEQ + s))*(DMODEL/2) + h*32 + d2];
            }
        }
        // V transposed: sVt[d][s]
        for (int idx = tid; idx < SEQ*DH; idx += 512) {
            int d = idx & 63, s = idx >> 6;
            sVt[d*PSTRH + s] = vh2[((size_t)(b*SEQ + s))*DMODEL + h*DH + d];
        }
        // Q tile half2: [64][32 half2]
        {
            const __half2* qg = (const __half2*)qh2;
            __half2* q2 = (__half2*)sU;
            for (int idx = tid; idx < TB*32; idx += 512) {
                int r = idx >> 5, d2 = idx & 31;
                int l = lt*TB + r; if (l > LMAX-1) l = LMAX-1;
                q2[r*(QKSTR/2) + d2] = qg[((size_t)(b*LMAX + l))*(DMODEL/2) + h*32 + d2];
            }
        }
        __syncthreads();

        // ---- QK^T (fp16): warp w owns cols [16w,16w+16), all 4 m-tiles ----
        float csc[2][4][4];
        #pragma unroll
        for (int j = 0; j < 2; j++)
            #pragma unroll
            for (int mt = 0; mt < 4; mt++)
                #pragma unroll
                for (int i = 0; i < 4; i++) csc[j][mt][i] = 0.f;
        #pragma unroll
        for (int ks = 0; ks < 4; ks++) {
            int kk = ks*16;
            unsigned bfr[4];
            LDSM4(bfr, bK + kk*2);
            #pragma unroll
            for (int mt = 0; mt < 4; mt++) {
                unsigned afr[4];
                LDSM4(afr, aQ + (mt*16*QKSTR + kk)*2);
                mma_f16(csc[0][mt], afr[0], afr[1], afr[2], afr[3], bfr[0], bfr[1]);
                mma_f16(csc[1][mt], afr[0], afr[1], afr[2], afr[3], bfr[2], bfr[3]);
            }
        }
        __syncthreads();   // Q reads done; sU becomes score/P region
        // write raw scores (half)
        #pragma unroll
        for (int j = 0; j < 2; j++)
            #pragma unroll
            for (int mt = 0; mt < 4; mt++) {
                int row = mt*16 + p;
                int col = (2*w + j)*8 + 2*q;
                *(__half2*)&sU[row*PSTRH + col]     = __floats2half2_rn(csc[j][mt][0], csc[j][mt][1]);
                *(__half2*)&sU[(row+8)*PSTRH + col] = __floats2half2_rn(csc[j][mt][2], csc[j][mt][3]);
            }
        __syncthreads();
        // ---- softmax: warp w owns rows [4w,4w+4); av accumulated fp32 ----
        #pragma unroll
        for (int rr = 0; rr < 4; rr++) {
            int row = 4*w + rr;
            float v[8];
            float m = -1e30f;
            #pragma unroll
            for (int jj = 0; jj < 8; jj++) {
                int s = lane + 32*jj;
                float x = sMask[s] ? -1e30f : __half2float(sU[row*PSTRH + s])*0.125f;
                v[jj] = x;
                m = fmaxf(m, x);
            }
            #pragma unroll
            for (int o = 16; o > 0; o >>= 1) m = fmaxf(m, __shfl_xor_sync(0xffffffffu, m, o));
            float sum = 0.f;
            #pragma unroll
            for (int jj = 0; jj < 8; jj++) { v[jj] = __expf(v[jj] - m); sum += v[jj]; }
            #pragma unroll
            for (int o = 16; o > 0; o >>= 1) sum += __shfl_xor_sync(0xffffffffu, sum, o);
            float inv = 1.f/sum;
            #pragma unroll
            for (int jj = 0; jj < 8; jj++) {
                float pp = v[jj]*inv;
                avacc[rr][jj] += pp;
                sU[row*PSTRH + lane + 32*jj] = __float2half_rn(pp);
            }
        }
        __syncthreads();
        // ---- P@V (fp16): warp w -> m-tile mtw, d-tiles nt0 and nt0+4 ----
        float cct[2][4];
        #pragma unroll
        for (int j = 0; j < 2; j++)
            #pragma unroll
            for (int i = 0; i < 4; i++) cct[j][i] = 0.f;
        #pragma unroll 4
        for (int ks = 0; ks < 16; ks++) {
            int kk = ks*16;
            unsigned afr[4], bfr[4];
            LDSM4(afr, aP + kk*2);
            LDSM4(bfr, bV + kk*2);
            mma_f16(cct[0], afr[0], afr[1], afr[2], afr[3], bfr[0], bfr[1]);
            mma_f16(cct[1], afr[0], afr[1], afr[2], afr[3], bfr[2], bfr[3]);
        }
        #pragma unroll
        for (int j = 0; j < 2; j++) {
            int dc = h*DH + (nt0 + 4*j)*8 + 2*q;
            int l0 = lt*TB + mtw*16 + p;
            if (l0 < LMAX)
                *(__half2*)&ctx[((size_t)(b*LMAX) + l0)*DMODEL + dc] =
                    __floats2half2_rn(cct[j][0], cct[j][1]);
            int l1 = l0 + 8;
            if (l1 < LMAX)
                *(__half2*)&ctx[((size_t)(b*LMAX) + l1)*DMODEL + dc] =
                    __floats2half2_rn(cct[j][2], cct[j][3]);
        }
    }

    // ---- head-averaged attention from fp32 accumulators ----
    #pragma unroll
    for (int rr = 0; rr < 4; rr++) {
        int l = lt*TB + 4*w + rr;
        if (l < LMAX) {
            #pragma unroll
            for (int jj = 0; jj < 8; jj++)
                av_out[((size_t)(b*LMAX) + l)*SEQ + lane + 32*jj] = avacc[rr][jj]*0.125f;
        }
    }
}

// ---------------- LN1: fp32 residual + half operand ----------
__global__ __launch_bounds__(128) void ln_dual(
    const float* __restrict__ x, const float* __restrict__ g,
    const float* __restrict__ bb, float* __restrict__ yf, __half* __restrict__ yh)
{
    __shared__ float ws[4], wss[4];
    int r = blockIdx.x;
    int tid = threadIdx.x;
    const float4* xr = (const float4*)(x + (size_t)r*DMODEL);
    float4 v = xr[tid];
    float s  = v.x + v.y + v.z + v.w;
    float ss = v.x*v.x + v.y*v.y + v.z*v.z + v.w*v.w;
    #pragma unroll
    for (int o = 16; o > 0; o >>= 1) {
        s  += __shfl_xor_sync(0xffffffffu, s,  o);
        ss += __shfl_xor_sync(0xffffffffu, ss, o);
    }
    int warp = tid >> 5, lane = tid & 31;
    if (lane == 0) { ws[warp] = s; wss[warp] = ss; }
    __syncthreads();
    float S  = ws[0] + ws[1] + ws[2] + ws[3];
    float SS = wss[0] + wss[1] + wss[2] + wss[3];
    float mean = S * (1.f/DMODEL);
    float var  = SS * (1.f/DMODEL) - mean*mean;
    float rstd = rsqrtf(var + 1e-5f);
    float4 gg = ((const float4*)g)[tid];
    float4 b4 = ((const float4*)bb)[tid];
    float4 o4;
    o4.x = (v.x - mean)*rstd*gg.x + b4.x;
    o4.y = (v.y - mean)*rstd*gg.y + b4.y;
    o4.z = (v.z - mean)*rstd*gg.z + b4.z;
    o4.w = (v.w - mean)*rstd*gg.w + b4.w;
    ((float4*)(yf + (size_t)r*DMODEL))[tid] = o4;
    __half2* yhp = (__half2*)(yh + (size_t)r*DMODEL);
    yhp[tid*2]   = __floats2half2_rn(o4.x, o4.y);
    yhp[tid*2+1] = __floats2half2_rn(o4.z, o4.w);
}

// ---------------- fused LN2 + ragged gather (binary search) ----------
__global__ __launch_bounds__(128) void ln_gather(
    const float* __restrict__ x, const int* __restrict__ gb,
    const float* __restrict__ g, const float* __restrict__ bb,
    float* __restrict__ out)
{
    __shared__ float ws[4], wss[4];
    int i = blockIdx.x;
    int b = gb[i];
    int pp = i - lower_bound_gb(gb, b);
    size_t row = (size_t)b*LMAX + pp;
    int tid = threadIdx.x;
    float4 v = ((const float4*)(x + row*DMODEL))[tid];
    float s  = v.x + v.y + v.z + v.w;
    float ss = v.x*v.x + v.y*v.y + v.z*v.z + v.w*v.w;
    #pragma unroll
    for (int o = 16; o > 0; o >>= 1) {
        s  += __shfl_xor_sync(0xffffffffu, s,  o);
        ss += __shfl_xor_sync(0xffffffffu, ss, o);
    }
    int warp = tid >> 5, lane = tid & 31;
    if (lane == 0) { ws[warp] = s; wss[warp] = ss; }
    __syncthreads();
    float S  = ws[0] + ws[1] + ws[2] + ws[3];
    float SS = wss[0] + wss[1] + wss[2] + wss[3];
    float mean = S * (1.f/DMODEL);
    float var  = SS * (1.f/DMODEL) - mean*mean;
    float rstd = rsqrtf(var + 1e-5f);
    float4 gg = ((const float4*)g)[tid];
    float4 b4 = ((const float4*)bb)[tid];
    float4 o4;
    o4.x = (v.x - mean)*rstd*gg.x + b4.x;
    o4.y = (v.y - mean)*rstd*gg.y + b4.y;
    o4.z = (v.z - mean)*rstd*gg.z + b4.z;
    o4.w = (v.w - mean)*rstd*gg.w + b4.w;
    ((float4*)(out + (size_t)i*DMODEL))[tid] = o4;
}

// ---------------- launch ----------------
extern "C" void kernel_launch(void* const* d_in, const int* in_sizes, int n_in,
                              void* d_out, int out_size)
{
    int off = (n_in >= 22) ? 0 : 2;
    const float* nodes  = (const float*)d_in[0];
    const int*   gb     = (const int*)  d_in[1];
    const float* cond   = (const float*)d_in[2];
    const int*   maskp  = (const int*)  d_in[3];
    const float* Wq     = (const float*)d_in[6-off];
    const float* bq     = (const float*)d_in[7-off];
    const float* Wk     = (const float*)d_in[8-off];
    const float* bk     = (const float*)d_in[9-off];
    const float* Wv     = (const float*)d_in[10-off];
    const float* bv     = (const float*)d_in[11-off];
    const float* in_w   = (const float*)d_in[12-off];
    const float* in_b   = (const float*)d_in[13-off];
    const float* Wo     = (const float*)d_in[14-off];
    const float* bo     = (const float*)d_in[15-off];
    const float* ln1g   = (const float*)d_in[16-off];
    const float* ln1b   = (const float*)d_in[17-off];
    const float* W1     = (const float*)d_in[18-off];
    const float* b1     = (const float*)d_in[19-off];
    const float* ln2g   = (const float*)d_in[20-off];
    const float* ln2b   = (const float*)d_in[21-off];
    float* out = (float*)d_out;
    float* av_out = out + (size_t)NN*DMODEL;

    float *p_dense_f, *p_y, *p_x1f, *p_h, *p_bq2, *p_bk2, *p_bv2;
    __half *p_dense_h, *p_qh2, *p_kh2, *p_vh2, *p_ctx, *p_x1h;
    __half *p_WqT, *p_WkT, *p_WvT, *p_WoT, *p_W1T, *p_cond;
    cudaGetSymbolAddress((void**)&p_dense_f, g_dense_f);
    cudaGetSymbolAddress((void**)&p_dense_h, g_dense_h);
    cudaGetSymbolAddress((void**)&p_qh2, g_qh2);
    cudaGetSymbolAddress((void**)&p_kh2, g_kh2);
    cudaGetSymbolAddress((void**)&p_vh2, g_vh2);
    cudaGetSymbolAddress((void**)&p_ctx, g_ctx);
    cudaGetSymbolAddress((void**)&p_y, g_y);
    cudaGetSymbolAddress((void**)&p_x1f, g_x1f);
    cudaGetSymbolAddress((void**)&p_x1h, g_x1h);
    cudaGetSymbolAddress((void**)&p_h, g_h);
    cudaGetSymbolAddress((void**)&p_WqT, g_WqT);
    cudaGetSymbolAddress((void**)&p_WkT, g_WkT);
    cudaGetSymbolAddress((void**)&p_WvT, g_WvT);
    cudaGetSymbolAddress((void**)&p_WoT, g_WoT);
    cudaGetSymbolAddress((void**)&p_W1T, g_W1T);
    cudaGetSymbolAddress((void**)&p_cond, g_cond);
    cudaGetSymbolAddress((void**)&p_bq2, g_bq2);
    cudaGetSymbolAddress((void**)&p_bk2, g_bk2);
    cudaGetSymbolAddress((void**)&p_bv2, g_bv2);

    cudaFuncSetAttribute(gemm_one<1>, cudaFuncAttributeMaxDynamicSharedMemorySize, GEMM_SMEM);
    cudaFuncSetAttribute(gemm_one<2>, cudaFuncAttributeMaxDynamicSharedMemorySize, GEMM_SMEM);
    cudaFuncSetAttribute(gemm_all,    cudaFuncAttributeMaxDynamicSharedMemorySize, GEMM_SMEM);
    cudaFuncSetAttribute(attn_f16,    cudaFuncAttributeMaxDynamicSharedMemorySize, ATT_SMEM);

    // 1) mega prologue: pad + cond->half + Wo/W1 transpose + bias combines
    prologue_misc<<<PM_BIAS, 128>>>(nodes, gb, cond, Wo, W1, bq, bk, bv, in_w, in_b,
                                    p_dense_f, p_dense_h, p_cond, p_WoT, p_W1T,
                                    p_bq2, p_bk2, p_bv2);
    // 2) fold projection weights -> transposed half
    fold3_gemm<<<dim3(4,6,3), 256>>>(Wq, Wk, Wv, in_w, p_WqT, p_WkT, p_WvT);
    // 3) Q + K + V projections (half outputs)
    gemm_all<<<dim3(4,124,3), 256, GEMM_SMEM>>>(p_dense_h, p_cond, p_WqT, p_WkT, p_WvT,
                                                p_bq2, p_bk2, p_bv2, p_qh2, p_kh2, p_vh2);
    // 4) fp16 attention  <-- profiled launch
    attn_f16<<<dim3(16, BGR), 512, ATT_SMEM>>>(p_qh2, p_kh2, p_vh2, maskp, p_ctx, av_out);
    // 5) out proj + residual
    gemm_one<1><<<dim3(4,124), 256, GEMM_SMEM>>>(p_ctx, p_WoT, bo, p_dense_f, p_y, DMODEL, DMODEL);
    // 6) LN1
    ln_dual<<<ROWS_Q, 128>>>(p_y, ln1g, ln1b, p_x1f, p_x1h);
    // 7) FFN + leaky + residual
    gemm_one<2><<<dim3(4,124), 256, GEMM_SMEM>>>(p_x1h, p_W1T, b1, p_x1f, p_h, DMODEL, DMODEL);
    // 8) LN2 + ragged gather
    ln_gather<<<NN, 128>>>(p_h, gb, ln2g, ln2b, out);
}

// round 10
// speedup vs baseline: 5.9336x; 1.1878x over previous
#include <cuda_runtime.h>
#include <cuda_fp16.h>
#include <cuda_bf16.h>
#include <math.h>

// ---------------- problem constants ----------------
#define NN    12032
#define DMODEL 512
#define BGR   16
#define SEQ   256
#define NH    8
#define DH    64
#define LMAX  992
#define LATD  768
#define ROWS_Q  (BGR*LMAX)   // 15872
#define ROWS_KV (BGR*SEQ)    // 4096

// ---------------- scratch ----------
__device__ float  g_dense_f[ROWS_Q*DMODEL];
__device__ __half g_dense_h[ROWS_Q*DMODEL];
__device__ __half g_qh2 [ROWS_Q*DMODEL];
__device__ __half g_kh2 [ROWS_KV*DMODEL];
__device__ __half g_vh2 [ROWS_KV*DMODEL];
__device__ __half g_ctx [ROWS_Q*DMODEL];
__device__ float  g_y   [ROWS_Q*DMODEL];
__device__ float  g_x1f [ROWS_Q*DMODEL];
__device__ __half g_x1h [ROWS_Q*DMODEL];
__device__ float  g_h   [ROWS_Q*DMODEL];
__device__ __half g_WqT [DMODEL*DMODEL];
__device__ __half g_WkT [LATD*DMODEL];
__device__ __half g_WvT [LATD*DMODEL];
__device__ __half g_WoT [DMODEL*DMODEL];
__device__ __half g_W1T [DMODEL*DMODEL];
__device__ __half g_cond[BGR*SEQ*LATD];
__device__ float  g_bq2 [DMODEL];
__device__ float  g_bk2 [DMODEL];
__device__ float  g_bv2 [DMODEL];

// ---------------- helpers ----------------
__device__ __forceinline__ unsigned f2tf32(float x) {
    unsigned y;
    asm("cvt.rna.tf32.f32 %0, %1;" : "=r"(y) : "f"(x));
    return y;
}

__device__ __forceinline__ void mma_tf32(float c[4],
    unsigned a0, unsigned a1, unsigned a2, unsigned a3,
    unsigned b0, unsigned b1)
{
    asm volatile(
        "mma.sync.aligned.m16n8k8.row.col.f32.tf32.tf32.f32 "
        "{%0,%1,%2,%3}, {%4,%5,%6,%7}, {%8,%9}, {%0,%1,%2,%3};"
        : "+f"(c[0]), "+f"(c[1]), "+f"(c[2]), "+f"(c[3])
        : "r"(a0), "r"(a1), "r"(a2), "r"(a3), "r"(b0), "r"(b1));
}

__device__ __forceinline__ void mma_f16(float c[4],
    unsigned a0, unsigned a1, unsigned a2, unsigned a3,
    unsigned b0, unsigned b1)
{
    asm volatile(
        "mma.sync.aligned.m16n8k16.row.col.f32.f16.f16.f32 "
        "{%0,%1,%2,%3}, {%4,%5,%6,%7}, {%8,%9}, {%0,%1,%2,%3};"
        : "+f"(c[0]), "+f"(c[1]), "+f"(c[2]), "+f"(c[3])
        : "r"(a0), "r"(a1), "r"(a2), "r"(a3), "r"(b0), "r"(b1));
}

#define CP16(dst, src) asm volatile("cp.async.cg.shared.global [%0], [%1], 16;" :: "r"(dst), "l"(src))
#define LDSM4(r, addr) asm volatile( \
    "ldmatrix.sync.aligned.m8n8.x4.shared.b16 {%0,%1,%2,%3}, [%4];" \
    : "=r"((r)[0]), "=r"((r)[1]), "=r"((r)[2]), "=r"((r)[3]) : "r"(addr))
#define LDSM4T(r, addr) asm volatile( \
    "ldmatrix.sync.aligned.m8n8.x4.trans.shared.b16 {%0,%1,%2,%3}, [%4];" \
    : "=r"((r)[0]), "=r"((r)[1]), "=r"((r)[2]), "=r"((r)[3]) : "r"(addr))

__device__ __forceinline__ int lower_bound_gb(const int* __restrict__ gb, int b) {
    int lo = 0, hi = NN;
    while (lo < hi) { int mid = (lo + hi) >> 1; if (gb[mid] < b) lo = mid + 1; else hi = mid; }
    return lo;
}

// ---------------- mega-prologue ----------
#define PM_PAD   ROWS_Q            // 15872
#define PM_COND  (PM_PAD + 2048)   // 17920
#define PM_HT    (PM_COND + 512)   // 18432
#define PM_BIAS  (PM_HT + 48)      // 18480

__global__ __launch_bounds__(128) void prologue_misc(
    const float* __restrict__ nodes, const int* __restrict__ gb,
    const float* __restrict__ cond,  const float* __restrict__ Wo,
    const float* __restrict__ W1,
    const float* __restrict__ bq, const float* __restrict__ bk,
    const float* __restrict__ bv, const float* __restrict__ inw,
    const float* __restrict__ inb,
    float* __restrict__ dense_f, __half* __restrict__ dense_h,
    __half* __restrict__ cond_h, __half* __restrict__ WoT, __half* __restrict__ W1T,
    float* __restrict__ bq2, float* __restrict__ bk2, float* __restrict__ bv2)
{
    __shared__ float sh[32*33];
    int bid = blockIdx.x, tid = threadIdx.x;
    if (bid < PM_PAD) {
        int r = bid;
        int b = r / LMAX, pp = r - b*LMAX;
        int start = lower_bound_gb(gb, b);
        int i = start + pp;
        float4 v = make_float4(0.f, 0.f, 0.f, 0.f);
        if (i < NN && gb[i] == b)
            v = ((const float4*)(nodes + (size_t)i*DMODEL))[tid];
        ((float4*)(dense_f + (size_t)r*DMODEL))[tid] = v;
        __half2* dh = (__half2*)(dense_h + (size_t)r*DMODEL);
        dh[tid*2]   = __floats2half2_rn(v.x, v.y);
        dh[tid*2+1] = __floats2half2_rn(v.z, v.w);
    } else if (bid < PM_COND) {
        int j = bid - PM_PAD;
        int n4 = (BGR*SEQ*LATD) >> 2;
        for (int i = j*128 + tid; i < n4; i += 2048*128) {
            float4 v = ((const float4*)cond)[i];
            __half2* d = (__half2*)cond_h;
            d[i*2]   = __floats2half2_rn(v.x, v.y);
            d[i*2+1] = __floats2half2_rn(v.z, v.w);
        }
    } else if (bid < PM_HT) {
        int t = bid - PM_COND;
        int z = t >> 8, rem = t & 255;
        const float* s = z ? W1 : Wo;
        __half* d = z ? W1T : WoT;
        int bx = (rem & 15)*32, by = (rem >> 4)*32;
        int x = tid & 31, y0 = tid >> 5;
        #pragma unroll
        for (int i = 0; i < 32; i += 4)
            sh[(y0+i)*33 + x] = s[(size_t)(by + y0 + i)*DMODEL + bx + x];
        __syncthreads();
        #pragma unroll
        for (int i = 0; i < 32; i += 4)
            d[(size_t)(bx + y0 + i)*DMODEL + by + x] = __float2half_rn(sh[x*33 + y0+i]);
    } else {
        int t = bid - PM_HT;
        int z = t >> 4, blk = t & 15;
        const float* bin = (z==0) ? bq : (z==1) ? bk : bv;
        const float* W = inw + (size_t)z*DMODEL*DMODEL;
        const float* ab = inb + z*DMODEL;
        float* outp = (z==0) ? bq2 : (z==1) ? bk2 : bv2;
        int jj = tid & 31;
        int r = tid >> 5;
        int j = blk*32 + jj;
        float a = 0.f;
        #pragma unroll 8
        for (int i = r*128; i < r*128 + 128; i++)
            a += bin[i]*W[(size_t)i*DMODEL + j];
        sh[r*32 + jj] = a;
        __syncthreads();
        if (r == 0) {
            float s = ab[j];
            #pragma unroll
            for (int k = 0; k < 4; k++) s += sh[k*32 + jj];
            outp[j] = s;
        }
    }
}

// ---------------- fold3 (tf32) -> half transposed weights -------------------
#define SMP 132

__global__ __launch_bounds__(256) void fold3_gemm(
    const float* __restrict__ Wq, const float* __restrict__ Wk,
    const float* __restrict__ Wv, const float* __restrict__ inw,
    __half* __restrict__ Cq, __half* __restrict__ Ck, __half* __restrict__ Cv)
{
    int z = blockIdx.z;
    int M = (z == 0) ? DMODEL : LATD;
    if ((int)blockIdx.y*128 >= M) return;
    const float* A = (z==0) ? Wq : (z==1) ? Wk : Wv;
    const float* B = inw + (size_t)z*DMODEL*DMODEL;
    __half* C = (z==0) ? Cq : (z==1) ? Ck : Cv;
    const int N = DMODEL, K = DMODEL;

    __shared__ unsigned As[16][SMP];
    __shared__ unsigned Bs[16][SMP];
    int tid = threadIdx.x;
    int warp = tid >> 5, lane = tid & 31;
    int warp_m = warp & 3, warp_n = warp >> 2;
    int p = lane >> 2, q = lane & 3;
    int blockM = blockIdx.y * 128;
    int blockN = blockIdx.x * 128;

    int ia0 = tid*2, ia1 = tid*2 + 1;
    int arow0 = ia0 >> 2, akq0 = ia0 & 3;
    int arow1 = ia1 >> 2, akq1 = ia1 & 3;
    int bk0 = ia0 >> 5, bn0 = ia0 & 31;
    int bk1 = ia1 >> 5, bn1 = ia1 & 31;

    const float* Ap0 = A + (size_t)(blockM + arow0)*K + akq0*4;
    const float* Ap1 = A + (size_t)(blockM + arow1)*K + akq1*4;
    const float* Bp0 = B + (size_t)bk0*N + blockN + bn0*4;
    const float* Bp1 = B + (size_t)bk1*N + blockN + bn1*4;

    float acc[2][8][4];
    #pragma unroll
    for (int mt = 0; mt < 2; mt++)
        #pragma unroll
        for (int nt = 0; nt < 8; nt++)
            #pragma unroll
            for (int i = 0; i < 4; i++) acc[mt][nt][i] = 0.f;

    float4 av0 = *(const float4*)(Ap0);
    float4 av1 = *(const float4*)(Ap1);
    float4 bv0 = *(const float4*)(Bp0);
    float4 bv1 = *(const float4*)(Bp1);

    for (int kt = 16; kt <= K; kt += 16) {
        As[akq0*4+0][arow0] = f2tf32(av0.x);
        As[akq0*4+1][arow0] = f2tf32(av0.y);
        As[akq0*4+2][arow0] = f2tf32(av0.z);
        As[akq0*4+3][arow0] = f2tf32(av0.w);
        As[akq1*4+0][arow1] = f2tf32(av1.x);
        As[akq1*4+1][arow1] = f2tf32(av1.y);
        As[akq1*4+2][arow1] = f2tf32(av1.z);
        As[akq1*4+3][arow1] = f2tf32(av1.w);
        {
            uint4 t0, t1;
            t0.x = f2tf32(bv0.x); t0.y = f2tf32(bv0.y);
            t0.z = f2tf32(bv0.z); t0.w = f2tf32(bv0.w);
            t1.x = f2tf32(bv1.x); t1.y = f2tf32(bv1.y);
            t1.z = f2tf32(bv1.z); t1.w = f2tf32(bv1.w);
            *(uint4*)&Bs[bk0][bn0*4] = t0;
            *(uint4*)&Bs[bk1][bn1*4] = t1;
        }
        __syncthreads();
        if (kt < K) {
            av0 = *(const float4*)(Ap0 + kt);
            av1 = *(const float4*)(Ap1 + kt);
            bv0 = *(const float4*)(Bp0 + (size_t)kt*N);
            bv1 = *(const float4*)(Bp1 + (size_t)kt*N);
        }
        #pragma unroll
        for (int kk = 0; kk < 16; kk += 8) {
            unsigned afr[2][4];
            #pragma unroll
            for (int mt = 0; mt < 2; mt++) {
                int mb = warp_m*32 + mt*16;
                afr[mt][0] = As[kk+q  ][mb + p];
                afr[mt][1] = As[kk+q  ][mb + p + 8];
                afr[mt][2] = As[kk+q+4][mb + p];
                afr[mt][3] = As[kk+q+4][mb + p + 8];
            }
            unsigned bfr[8][2];
            #pragma unroll
            for (int nt = 0; nt < 8; nt++) {
                int nb = warp_n*64 + nt*8;
                bfr[nt][0] = Bs[kk+q  ][nb + p];
                bfr[nt][1] = Bs[kk+q+4][nb + p];
            }
            #pragma unroll
            for (int mt = 0; mt < 2; mt++)
                #pragma unroll
                for (int nt = 0; nt < 8; nt++)
                    mma_tf32(acc[mt][nt], afr[mt][0], afr[mt][1], afr[mt][2], afr[mt][3],
                             bfr[nt][0], bfr[nt][1]);
        }
        __syncthreads();
    }

    #pragma unroll
    for (int mt = 0; mt < 2; mt++) {
        int r0 = blockM + warp_m*32 + mt*16 + p;
        #pragma unroll
        for (int nt = 0; nt < 8; nt++) {
            int c0 = blockN + warp_n*64 + nt*8 + 2*q;
            C[(size_t)(c0  )*M + r0    ] = __float2half_rn(acc[mt][nt][0]);
            C[(size_t)(c0+1)*M + r0    ] = __float2half_rn(acc[mt][nt][1]);
            C[(size_t)(c0  )*M + r0 + 8] = __float2half_rn(acc[mt][nt][2]);
            C[(size_t)(c0+1)*M + r0 + 8] = __float2half_rn(acc[mt][nt][3]);
        }
    }
}

// ---------------- 3-stage cp.async FP16 GEMM ----------------
#define TSTRH 40
#define STG_B (128*TSTRH*2)
#define GEMM_SMEM (3*2*STG_B)

template<int MODE>
__device__ __forceinline__ void gemm_body(
    const __half* __restrict__ A, const __half* __restrict__ Bt,
    const float* __restrict__ bias, const float* __restrict__ Dm,
    void* __restrict__ Cv, int N, int K, char* smem)
{
    char* As = smem;
    char* Bs = smem + 3*STG_B;

    int tid = threadIdx.x;
    int warp = tid >> 5, lane = tid & 31;
    int warp_m = warp & 3, warp_n = warp >> 2;
    int p = lane >> 2, q = lane & 3;
    int blockM = blockIdx.y * 128;
    int blockN = blockIdx.x * 128;

    int c0 = tid*2, c1 = c0 + 1;
    int r0c = c0 >> 2, k0c = (c0 & 3)*8;
    int r1c = c1 >> 2, k1c = (c1 & 3)*8;

    const __half* gA0 = A  + (size_t)(blockM + r0c)*K + k0c;
    const __half* gA1 = A  + (size_t)(blockM + r1c)*K + k1c;
    const __half* gB0 = Bt + (size_t)(blockN + r0c)*K + k0c;
    const __half* gB1 = Bt + (size_t)(blockN + r1c)*K + k1c;

    unsigned sa = (unsigned)__cvta_generic_to_shared(As);
    unsigned sb = (unsigned)__cvta_generic_to_shared(Bs);
    unsigned dA0[3], dA1[3], dB0[3], dB1[3];
    #pragma unroll
    for (int s = 0; s < 3; s++) {
        dA0[s] = sa + s*STG_B + (r0c*TSTRH + k0c)*2;
        dA1[s] = sa + s*STG_B + (r1c*TSTRH + k1c)*2;
        dB0[s] = sb + s*STG_B + (r0c*TSTRH + k0c)*2;
        dB1[s] = sb + s*STG_B + (r1c*TSTRH + k1c)*2;
    }

    unsigned aBase = sa + ((warp_m*32 + (lane & 15))*TSTRH + (lane >> 4)*8)*2;
    unsigned bBase = sb + ((warp_n*64 + ((lane >> 4) << 3) + (lane & 7))*TSTRH
                           + ((lane >> 3) & 1)*8)*2;

    float acc[2][8][4];
    #pragma unroll
    for (int mt = 0; mt < 2; mt++)
        #pragma unroll
        for (int nt = 0; nt < 8; nt++)
            #pragma unroll
            for (int i = 0; i < 4; i++) acc[mt][nt][i] = 0.f;

    CP16(dA0[0], gA0); CP16(dA1[0], gA1);
    CP16(dB0[0], gB0); CP16(dB1[0], gB1);
    asm volatile("cp.async.commit_group;");
    CP16(dA0[1], gA0 + 32); CP16(dA1[1], gA1 + 32);
    CP16(dB0[1], gB0 + 32); CP16(dB1[1], gB1 + 32);
    asm volatile("cp.async.commit_group;");

    int nk = K >> 5;
    int sc = 0, sp = 2;
    for (int t = 0; t < nk; t++) {
        asm volatile("cp.async.wait_group 1;");
        __syncthreads();
        if (t + 2 < nk) {
            int kt = (t + 2) << 5;
            CP16(dA0[sp], gA0 + kt); CP16(dA1[sp], gA1 + kt);
            CP16(dB0[sp], gB0 + kt); CP16(dB1[sp], gB1 + kt);
        }
        asm volatile("cp.async.commit_group;");
        unsigned ao = aBase + sc*STG_B;
        unsigned bo = bBase + sc*STG_B;
        #pragma unroll
        for (int kk = 0; kk < 32; kk += 16) {
            unsigned afr[2][4];
            LDSM4(afr[0], ao + kk*2);
            LDSM4(afr[1], ao + (16*TSTRH + kk)*2);
            unsigned bfr[4][4];
            #pragma unroll
            for (int j = 0; j < 4; j++)
                LDSM4(bfr[j], bo + (j*16*TSTRH + kk)*2);
            #pragma unroll
            for (int mt = 0; mt < 2; mt++)
                #pragma unroll
                for (int nt = 0; nt < 8; nt++)
                    mma_f16(acc[mt][nt],
                            afr[mt][0], afr[mt][1], afr[mt][2], afr[mt][3],
                            bfr[nt >> 1][(nt & 1)*2], bfr[nt >> 1][(nt & 1)*2 + 1]);
        }
        sc++; if (sc == 3) sc = 0;
        sp++; if (sp == 3) sp = 0;
    }

    #pragma unroll
    for (int mt = 0; mt < 2; mt++) {
        int r0 = blockM + warp_m*32 + mt*16 + p;
        #pragma unroll
        for (int nt = 0; nt < 8; nt++) {
            int c0c = blockN + warp_n*64 + nt*8 + 2*q;
            float b0 = 0.f, b1 = 0.f;
            if (bias) { b0 = bias[c0c]; b1 = bias[c0c+1]; }
            float v0 = acc[mt][nt][0] + b0;
            float v1 = acc[mt][nt][1] + b1;
            float v2 = acc[mt][nt][2] + b0;
            float v3 = acc[mt][nt][3] + b1;
            size_t o0 = (size_t)r0*N + c0c;
            size_t o1 = (size_t)(r0+8)*N + c0c;
            if (MODE == 3) {
                __half* Ch = (__half*)Cv;
                *(__half2*)&Ch[o0] = __floats2half2_rn(v0, v1);
                *(__half2*)&Ch[o1] = __floats2half2_rn(v2, v3);
            } else {
                float* C = (float*)Cv;
                if (MODE == 1) {
                    float2 d0 = *(const float2*)(Dm + o0);
                    float2 d1 = *(const float2*)(Dm + o1);
                    v0 += d0.x; v1 += d0.y; v2 += d1.x; v3 += d1.y;
                }
                if (MODE == 2) {
                    v0 = (v0 > 0.f) ? v0 : 0.01f*v0;
                    v1 = (v1 > 0.f) ? v1 : 0.01f*v1;
                    v2 = (v2 > 0.f) ? v2 : 0.01f*v2;
                    v3 = (v3 > 0.f) ? v3 : 0.01f*v3;
                    float2 d0 = *(const float2*)(Dm + o0);
                    float2 d1 = *(const float2*)(Dm + o1);
                    v0 += d0.x; v1 += d0.y; v2 += d1.x; v3 += d1.y;
                }
                *(float2*)(C + o0) = make_float2(v0, v1);
                *(float2*)(C + o1) = make_float2(v2, v3);
            }
        }
    }
}

template<int MODE>
__global__ __launch_bounds__(256, 2) void gemm_one(
    const __half* __restrict__ A, const __half* __restrict__ Bt,
    const float* __restrict__ bias, const float* __restrict__ Dm,
    float* __restrict__ C, int N, int K)
{
    extern __shared__ char smem[];
    gemm_body<MODE>(A, Bt, bias, Dm, C, N, K, smem);
}

__global__ __launch_bounds__(256, 2) void gemm_all(
    const __half* __restrict__ dense_h, const __half* __restrict__ cond_h,
    const __half* __restrict__ WqT, const __half* __restrict__ WkT,
    const __half* __restrict__ WvT,
    const float* __restrict__ bq2, const float* __restrict__ bk2,
    const float* __restrict__ bv2,
    __half* __restrict__ qh2, __half* __restrict__ kh2, __half* __restrict__ vh2)
{
    extern __shared__ char smem[];
    int z = blockIdx.z;
    if (z < 2) {
        if (blockIdx.y >= 32) return;
        gemm_body<3>(cond_h, z ? WvT : WkT, z ? bv2 : bk2, nullptr,
                     z ? (void*)vh2 : (void*)kh2, DMODEL, LATD, smem);
    } else {
        gemm_body<3>(dense_h, WqT, bq2, nullptr, (void*)qh2, DMODEL, DMODEL, smem);
    }
}

// ---------------- fp16 attention v2: resident Q, cp.async K/V, trans-V -----
#define TB    64
#define QSTR  520
#define KVSTR 72
#define PSTR2 264
#define SM_Q  0
#define SM_K  66560
#define SM_V  (66560 + 36864)
#define SM_P  (SM_V + 36864)
#define SM_MASK (SM_P + 33792)
#define ATT_SMEM (SM_MASK + SEQ*4)

__global__ __launch_bounds__(512, 1) void attn_f16(
    const __half* __restrict__ qh2, const __half* __restrict__ kh2,
    const __half* __restrict__ vh2, const int* __restrict__ maskp,
    __half* __restrict__ ctx, float* __restrict__ av_out)
{
    extern __shared__ char smc[];
    __half* sP  = (__half*)(smc + SM_P);
    int* sMask  = (int*)(smc + SM_MASK);

    int b = blockIdx.y, lt = blockIdx.x;
    int tid = threadIdx.x;
    int w = tid >> 5, lane = tid & 31;
    int p = lane >> 2, q = lane & 3;

    unsigned sq = (unsigned)__cvta_generic_to_shared(smc + SM_Q);
    unsigned sk = (unsigned)__cvta_generic_to_shared(smc + SM_K);
    unsigned sv = (unsigned)__cvta_generic_to_shared(smc + SM_V);
    unsigned spb = (unsigned)__cvta_generic_to_shared(sP);

    if (tid < SEQ) sMask[tid] = maskp[b*SEQ + tid];

    // ---- Q all heads via cp.async: 64 rows x 512 halves = 4096 16B chunks --
    #pragma unroll
    for (int i = 0; i < 8; i++) {
        int c = tid + 512*i;
        int row = c >> 6, ch = c & 63;
        int l = lt*TB + row; if (l > LMAX-1) l = LMAX-1;
        CP16(sq + (row*QSTR + ch*8)*2,
             qh2 + (size_t)(b*LMAX + l)*DMODEL + ch*8);
    }
    asm volatile("cp.async.commit_group;");

    // per-lane mma smem addresses
    unsigned aQ = sq + ((lane & 15)*QSTR + (lane >> 4)*8)*2;            // + mt*16*QSTR + h*64 + kk
    unsigned bK = sk + ((w*16 + ((lane >> 4) << 3) + (lane & 7))*KVSTR
                        + ((lane >> 3) & 1)*8)*2;                       // + kk
    int mtw = w & 3, ng = w >> 2;   // PV: m-tile mtw, d-cols [16ng, 16ng+16)
    unsigned aP = spb + ((mtw*16 + (lane & 15))*PSTR2 + (lane >> 4)*8)*2;  // + kk
    unsigned bV = sv + (((lane & 7) + ((lane >> 3) & 1)*8)*KVSTR
                        + ng*16 + (lane >> 4)*8)*2;                     // + kk*KVSTR

    float avacc[4][8];
    #pragma unroll
    for (int rr = 0; rr < 4; rr++)
        #pragma unroll
        for (int jj = 0; jj < 8; jj++) avacc[rr][jj] = 0.f;

    for (int h = 0; h < NH; h++) {
        __syncthreads();   // prev head PV reads done; K/V/P writable (h=0: mask)
        // K,V per head via cp.async
        {
            const __half* kg = kh2 + (size_t)b*SEQ*DMODEL + h*DH;
            const __half* vg = vh2 + (size_t)b*SEQ*DMODEL + h*DH;
            #pragma unroll
            for (int i = 0; i < 4; i++) {
                int c = tid + 512*i;
                int s = c >> 3, ch = c & 7;
                CP16(sk + (s*KVSTR + ch*8)*2, kg + (size_t)s*DMODEL + ch*8);
                CP16(sv + (s*KVSTR + ch*8)*2, vg + (size_t)s*DMODEL + ch*8);
            }
        }
        asm volatile("cp.async.commit_group;");
        asm volatile("cp.async.wait_group 0;");
        __syncthreads();

        // ---- QK^T: warp w owns cols [16w,16w+16), 4 m-tiles ----
        float csc[2][4][4];
        #pragma unroll
        for (int j = 0; j < 2; j++)
            #pragma unroll
            for (int mt = 0; mt < 4; mt++)
                #pragma unroll
                for (int i = 0; i < 4; i++) csc[j][mt][i] = 0.f;
        #pragma unroll
        for (int ks = 0; ks < 4; ks++) {
            int kk = ks*16;
            unsigned bfr[4];
            LDSM4(bfr, bK + kk*2);
            #pragma unroll
            for (int mt = 0; mt < 4; mt++) {
                unsigned afr[4];
                LDSM4(afr, aQ + (mt*16*QSTR + h*DH + kk)*2);
                mma_f16(csc[0][mt], afr[0], afr[1], afr[2], afr[3], bfr[0], bfr[1]);
                mma_f16(csc[1][mt], afr[0], afr[1], afr[2], afr[3], bfr[2], bfr[3]);
            }
        }
        // write raw scores to sP (protected by top-of-loop sync)
        #pragma unroll
        for (int j = 0; j < 2; j++)
            #pragma unroll
            for (int mt = 0; mt < 4; mt++) {
                int row = mt*16 + p;
                int col = (2*w + j)*8 + 2*q;
                *(__half2*)&sP[row*PSTR2 + col]     = __floats2half2_rn(csc[j][mt][0], csc[j][mt][1]);
                *(__half2*)&sP[(row+8)*PSTR2 + col] = __floats2half2_rn(csc[j][mt][2], csc[j][mt][3]);
            }
        __syncthreads();
        // ---- softmax: warp w owns rows [4w,4w+4) ----
        #pragma unroll
        for (int rr = 0; rr < 4; rr++) {
            int row = 4*w + rr;
            float v[8];
            float m = -1e30f;
            #pragma unroll
            for (int jj = 0; jj < 8; jj++) {
                int s = lane + 32*jj;
                float x = sMask[s] ? -1e30f : __half2float(sP[row*PSTR2 + s])*0.125f;
                v[jj] = x;
                m = fmaxf(m, x);
            }
            #pragma unroll
            for (int o = 16; o > 0; o >>= 1) m = fmaxf(m, __shfl_xor_sync(0xffffffffu, m, o));
            float sum = 0.f;
            #pragma unroll
            for (int jj = 0; jj < 8; jj++) { v[jj] = __expf(v[jj] - m); sum += v[jj]; }
            #pragma unroll
            for (int o = 16; o > 0; o >>= 1) sum += __shfl_xor_sync(0xffffffffu, sum, o);
            float inv = 1.f/sum;
            #pragma unroll
            for (int jj = 0; jj < 8; jj++) {
                float pp = v[jj]*inv;
                avacc[rr][jj] += pp;
                sP[row*PSTR2 + lane + 32*jj] = __float2half_rn(pp);
            }
        }
        __syncthreads();
        // ---- P@V: warp w -> m-tile mtw, d-cols [16ng, 16ng+16) ----
        float cct[2][4];
        #pragma unroll
        for (int j = 0; j < 2; j++)
            #pragma unroll
            for (int i = 0; i < 4; i++) cct[j][i] = 0.f;
        #pragma unroll 4
        for (int ks = 0; ks < 16; ks++) {
            int kk = ks*16;
            unsigned afr[4], bfr[4];
            LDSM4(afr, aP + kk*2);
            LDSM4T(bfr, bV + kk*KVSTR*2);
            mma_f16(cct[0], afr[0], afr[1], afr[2], afr[3], bfr[0], bfr[1]);
            mma_f16(cct[1], afr[0], afr[1], afr[2], afr[3], bfr[2], bfr[3]);
        }
        #pragma unroll
        for (int j = 0; j < 2; j++) {
            int dc = h*DH + ng*16 + j*8 + 2*q;
            int l0 = lt*TB + mtw*16 + p;
            if (l0 < LMAX)
                *(__half2*)&ctx[((size_t)(b*LMAX) + l0)*DMODEL + dc] =
                    __floats2half2_rn(cct[j][0], cct[j][1]);
            int l1 = l0 + 8;
            if (l1 < LMAX)
                *(__half2*)&ctx[((size_t)(b*LMAX) + l1)*DMODEL + dc] =
                    __floats2half2_rn(cct[j][2], cct[j][3]);
        }
    }

    // ---- head-averaged attention ----
    #pragma unroll
    for (int rr = 0; rr < 4; rr++) {
        int l = lt*TB + 4*w + rr;
        if (l < LMAX) {
            #pragma unroll
            for (int jj = 0; jj < 8; jj++)
                av_out[((size_t)(b*LMAX) + l)*SEQ + lane + 32*jj] = avacc[rr][jj]*0.125f;
        }
    }
}

// ---------------- LN1: fp32 residual + half operand ----------
__global__ __launch_bounds__(128) void ln_dual(
    const float* __restrict__ x, const float* __restrict__ g,
    const float* __restrict__ bb, float* __restrict__ yf, __half* __restrict__ yh)
{
    __shared__ float ws[4], wss[4];
    int r = blockIdx.x;
    int tid = threadIdx.x;
    const float4* xr = (const float4*)(x + (size_t)r*DMODEL);
    float4 v = xr[tid];
    float s  = v.x + v.y + v.z + v.w;
    float ss = v.x*v.x + v.y*v.y + v.z*v.z + v.w*v.w;
    #pragma unroll
    for (int o = 16; o > 0; o >>= 1) {
        s  += __shfl_xor_sync(0xffffffffu, s,  o);
        ss += __shfl_xor_sync(0xffffffffu, ss, o);
    }
    int warp = tid >> 5, lane = tid & 31;
    if (lane == 0) { ws[warp] = s; wss[warp] = ss; }
    __syncthreads();
    float S  = ws[0] + ws[1] + ws[2] + ws[3];
    float SS = wss[0] + wss[1] + wss[2] + wss[3];
    float mean = S * (1.f/DMODEL);
    float var  = SS * (1.f/DMODEL) - mean*mean;
    float rstd = rsqrtf(var + 1e-5f);
    float4 gg = ((const float4*)g)[tid];
    float4 b4 = ((const float4*)bb)[tid];
    float4 o4;
    o4.x = (v.x - mean)*rstd*gg.x + b4.x;
    o4.y = (v.y - mean)*rstd*gg.y + b4.y;
    o4.z = (v.z - mean)*rstd*gg.z + b4.z;
    o4.w = (v.w - mean)*rstd*gg.w + b4.w;
    ((float4*)(yf + (size_t)r*DMODEL))[tid] = o4;
    __half2* yhp = (__half2*)(yh + (size_t)r*DMODEL);
    yhp[tid*2]   = __floats2half2_rn(o4.x, o4.y);
    yhp[tid*2+1] = __floats2half2_rn(o4.z, o4.w);
}

// ---------------- fused LN2 + ragged gather ----------
__global__ __launch_bounds__(128) void ln_gather(
    const float* __restrict__ x, const int* __restrict__ gb,
    const float* __restrict__ g, const float* __restrict__ bb,
    float* __restrict__ out)
{
    __shared__ float ws[4], wss[4];
    int i = blockIdx.x;
    int b = gb[i];
    int pp = i - lower_bound_gb(gb, b);
    size_t row = (size_t)b*LMAX + pp;
    int tid = threadIdx.x;
    float4 v = ((const float4*)(x + row*DMODEL))[tid];
    float s  = v.x + v.y + v.z + v.w;
    float ss = v.x*v.x + v.y*v.y + v.z*v.z + v.w*v.w;
    #pragma unroll
    for (int o = 16; o > 0; o >>= 1) {
        s  += __shfl_xor_sync(0xffffffffu, s,  o);
        ss += __shfl_xor_sync(0xffffffffu, ss, o);
    }
    int warp = tid >> 5, lane = tid & 31;
    if (lane == 0) { ws[warp] = s; wss[warp] = ss; }
    __syncthreads();
    float S  = ws[0] + ws[1] + ws[2] + ws[3];
    float SS = wss[0] + wss[1] + wss[2] + wss[3];
    float mean = S * (1.f/DMODEL);
    float var  = SS * (1.f/DMODEL) - mean*mean;
    float rstd = rsqrtf(var + 1e-5f);
    float4 gg = ((const float4*)g)[tid];
    float4 b4 = ((const float4*)bb)[tid];
    float4 o4;
    o4.x = (v.x - mean)*rstd*gg.x + b4.x;
    o4.y = (v.y - mean)*rstd*gg.y + b4.y;
    o4.z = (v.z - mean)*rstd*gg.z + b4.z;
    o4.w = (v.w - mean)*rstd*gg.w + b4.w;
    ((float4*)(out + (size_t)i*DMODEL))[tid] = o4;
}

// ---------------- launch ----------------
extern "C" void kernel_launch(void* const* d_in, const int* in_sizes, int n_in,
                              void* d_out, int out_size)
{
    int off = (n_in >= 22) ? 0 : 2;
    const float* nodes  = (const float*)d_in[0];
    const int*   gb     = (const int*)  d_in[1];
    const float* cond   = (const float*)d_in[2];
    const int*   maskp  = (const int*)  d_in[3];
    const float* Wq     = (const float*)d_in[6-off];
    const float* bq     = (const float*)d_in[7-off];
    const float* Wk     = (const float*)d_in[8-off];
    const float* bk     = (const float*)d_in[9-off];
    const float* Wv     = (const float*)d_in[10-off];
    const float* bv     = (const float*)d_in[11-off];
    const float* in_w   = (const float*)d_in[12-off];
    const float* in_b   = (const float*)d_in[13-off];
    const float* Wo     = (const float*)d_in[14-off];
    const float* bo     = (const float*)d_in[15-off];
    const float* ln1g   = (const float*)d_in[16-off];
    const float* ln1b   = (const float*)d_in[17-off];
    const float* W1     = (const float*)d_in[18-off];
    const float* b1     = (const float*)d_in[19-off];
    const float* ln2g   = (const float*)d_in[20-off];
    const float* ln2b   = (const float*)d_in[21-off];
    float* out = (float*)d_out;
    float* av_out = out + (size_t)NN*DMODEL;

    float *p_dense_f, *p_y, *p_x1f, *p_h, *p_bq2, *p_bk2, *p_bv2;
    __half *p_dense_h, *p_qh2, *p_kh2, *p_vh2, *p_ctx, *p_x1h;
    __half *p_WqT, *p_WkT, *p_WvT, *p_WoT, *p_W1T, *p_cond;
    cudaGetSymbolAddress((void**)&p_dense_f, g_dense_f);
    cudaGetSymbolAddress((void**)&p_dense_h, g_dense_h);
    cudaGetSymbolAddress((void**)&p_qh2, g_qh2);
    cudaGetSymbolAddress((void**)&p_kh2, g_kh2);
    cudaGetSymbolAddress((void**)&p_vh2, g_vh2);
    cudaGetSymbolAddress((void**)&p_ctx, g_ctx);
    cudaGetSymbolAddress((void**)&p_y, g_y);
    cudaGetSymbolAddress((void**)&p_x1f, g_x1f);
    cudaGetSymbolAddress((void**)&p_x1h, g_x1h);
    cudaGetSymbolAddress((void**)&p_h, g_h);
    cudaGetSymbolAddress((void**)&p_WqT, g_WqT);
    cudaGetSymbolAddress((void**)&p_WkT, g_WkT);
    cudaGetSymbolAddress((void**)&p_WvT, g_WvT);
    cudaGetSymbolAddress((void**)&p_WoT, g_WoT);
    cudaGetSymbolAddress((void**)&p_W1T, g_W1T);
    cudaGetSymbolAddress((void**)&p_cond, g_cond);
    cudaGetSymbolAddress((void**)&p_bq2, g_bq2);
    cudaGetSymbolAddress((void**)&p_bk2, g_bk2);
    cudaGetSymbolAddress((void**)&p_bv2, g_bv2);

    cudaFuncSetAttribute(gemm_one<1>, cudaFuncAttributeMaxDynamicSharedMemorySize, GEMM_SMEM);
    cudaFuncSetAttribute(gemm_one<2>, cudaFuncAttributeMaxDynamicSharedMemorySize, GEMM_SMEM);
    cudaFuncSetAttribute(gemm_all,    cudaFuncAttributeMaxDynamicSharedMemorySize, GEMM_SMEM);
    cudaFuncSetAttribute(attn_f16,    cudaFuncAttributeMaxDynamicSharedMemorySize, ATT_SMEM);

    // 1) mega prologue
    prologue_misc<<<PM_BIAS, 128>>>(nodes, gb, cond, Wo, W1, bq, bk, bv, in_w, in_b,
                                    p_dense_f, p_dense_h, p_cond, p_WoT, p_W1T,
                                    p_bq2, p_bk2, p_bv2);
    // 2) fold projection weights
    fold3_gemm<<<dim3(4,6,3), 256>>>(Wq, Wk, Wv, in_w, p_WqT, p_WkT, p_WvT);
    // 3) Q + K + V projections
    gemm_all<<<dim3(4,124,3), 256, GEMM_SMEM>>>(p_dense_h, p_cond, p_WqT, p_WkT, p_WvT,
                                                p_bq2, p_bk2, p_bv2, p_qh2, p_kh2, p_vh2);
    // 4) fp16 attention v2  <-- profiled launch
    attn_f16<<<dim3(16, BGR), 512, ATT_SMEM>>>(p_qh2, p_kh2, p_vh2, maskp, p_ctx, av_out);
    // 5) out proj + residual
    gemm_one<1><<<dim3(4,124), 256, GEMM_SMEM>>>(p_ctx, p_WoT, bo, p_dense_f, p_y, DMODEL, DMODEL);
    // 6) LN1
    ln_dual<<<ROWS_Q, 128>>>(p_y, ln1g, ln1b, p_x1f, p_x1h);
    // 7) FFN + leaky + residual
    gemm_one<2><<<dim3(4,124), 256, GEMM_SMEM>>>(p_x1h, p_W1T, b1, p_x1f, p_h, DMODEL, DMODEL);
    // 8) LN2 + ragged gather
    ln_gather<<<NN, 128>>>(p_h, gb, ln2g, ln2b, out);
}

// round 11
// speedup vs baseline: 6.6289x; 1.1172x over previous
#include <cuda_runtime.h>
#include <cuda_fp16.h>
#include <cuda_bf16.h>
#include <math.h>

// ---------------- problem constants ----------------
#define NN    12032
#define DMODEL 512
#define BGR   16
#define SEQ   256
#define NH    8
#define DH    64
#define LMAX  992
#define LATD  768
#define ROWS_Q  (BGR*LMAX)   // 15872
#define ROWS_KV (BGR*SEQ)    // 4096

// ---------------- scratch ----------
__device__ float  g_dense_f[ROWS_Q*DMODEL];
__device__ __half g_dense_h[ROWS_Q*DMODEL];
__device__ __half g_qh2 [ROWS_Q*DMODEL];
__device__ __half g_kh2 [ROWS_KV*DMODEL];
__device__ __half g_vh2 [ROWS_KV*DMODEL];
__device__ __half g_ctx [ROWS_Q*DMODEL];
__device__ float  g_y   [ROWS_Q*DMODEL];
__device__ float  g_x1f [ROWS_Q*DMODEL];
__device__ __half g_x1h [ROWS_Q*DMODEL];
__device__ float  g_h   [ROWS_Q*DMODEL];
__device__ __half g_WqT [DMODEL*DMODEL];
__device__ __half g_WkT [LATD*DMODEL];
__device__ __half g_WvT [LATD*DMODEL];
__device__ __half g_WoT [DMODEL*DMODEL];
__device__ __half g_W1T [DMODEL*DMODEL];
__device__ __half g_cond[BGR*SEQ*LATD];
__device__ __half g_Wqh [DMODEL*DMODEL];       // raw weights as half
__device__ __half g_Wkh [LATD*DMODEL];
__device__ __half g_Wvh [LATD*DMODEL];
__device__ __half g_inwT[3*DMODEL*DMODEL];     // in_w transposed, half
__device__ float  g_bq2 [DMODEL];
__device__ float  g_bk2 [DMODEL];
__device__ float  g_bv2 [DMODEL];

// ---------------- helpers ----------------
__device__ __forceinline__ void mma_f16(float c[4],
    unsigned a0, unsigned a1, unsigned a2, unsigned a3,
    unsigned b0, unsigned b1)
{
    asm volatile(
        "mma.sync.aligned.m16n8k16.row.col.f32.f16.f16.f32 "
        "{%0,%1,%2,%3}, {%4,%5,%6,%7}, {%8,%9}, {%0,%1,%2,%3};"
        : "+f"(c[0]), "+f"(c[1]), "+f"(c[2]), "+f"(c[3])
        : "r"(a0), "r"(a1), "r"(a2), "r"(a3), "r"(b0), "r"(b1));
}

#define CP16(dst, src) asm volatile("cp.async.cg.shared.global [%0], [%1], 16;" :: "r"(dst), "l"(src))
#define LDSM4(r, addr) asm volatile( \
    "ldmatrix.sync.aligned.m8n8.x4.shared.b16 {%0,%1,%2,%3}, [%4];" \
    : "=r"((r)[0]), "=r"((r)[1]), "=r"((r)[2]), "=r"((r)[3]) : "r"(addr))
#define LDSM4T(r, addr) asm volatile( \
    "ldmatrix.sync.aligned.m8n8.x4.trans.shared.b16 {%0,%1,%2,%3}, [%4];" \
    : "=r"((r)[0]), "=r"((r)[1]), "=r"((r)[2]), "=r"((r)[3]) : "r"(addr))

__device__ __forceinline__ int lower_bound_gb(const int* __restrict__ gb, int b) {
    int lo = 0, hi = NN;
    while (lo < hi) { int mid = (lo + hi) >> 1; if (gb[mid] < b) lo = mid + 1; else hi = mid; }
    return lo;
}

// ---------------- mega-prologue ----------
#define PM_PAD   ROWS_Q             // 15872
#define PM_COND  (PM_PAD + 2048)    // 17920
#define PM_HT    (PM_COND + 512)    // 18432
#define PM_BIAS  (PM_HT + 48)       // 18480
#define PM_CONVW (PM_BIAS + 512)    // 18992
#define PM_TINW  (PM_CONVW + 768)   // 19760 (grid size)

__global__ __launch_bounds__(128) void prologue_misc(
    const float* __restrict__ nodes, const int* __restrict__ gb,
    const float* __restrict__ cond,  const float* __restrict__ Wo,
    const float* __restrict__ W1,
    const float* __restrict__ Wq, const float* __restrict__ Wk,
    const float* __restrict__ Wv,
    const float* __restrict__ bq, const float* __restrict__ bk,
    const float* __restrict__ bv, const float* __restrict__ inw,
    const float* __restrict__ inb,
    float* __restrict__ dense_f, __half* __restrict__ dense_h,
    __half* __restrict__ cond_h, __half* __restrict__ WoT, __half* __restrict__ W1T,
    __half* __restrict__ Wqh, __half* __restrict__ Wkh, __half* __restrict__ Wvh,
    __half* __restrict__ inwT,
    float* __restrict__ bq2, float* __restrict__ bk2, float* __restrict__ bv2)
{
    __shared__ float sh[32*33];
    int bid = blockIdx.x, tid = threadIdx.x;
    if (bid < PM_PAD) {
        int r = bid;
        int b = r / LMAX, pp = r - b*LMAX;
        int start = lower_bound_gb(gb, b);
        int i = start + pp;
        float4 v = make_float4(0.f, 0.f, 0.f, 0.f);
        if (i < NN && gb[i] == b)
            v = ((const float4*)(nodes + (size_t)i*DMODEL))[tid];
        ((float4*)(dense_f + (size_t)r*DMODEL))[tid] = v;
        __half2* dh = (__half2*)(dense_h + (size_t)r*DMODEL);
        dh[tid*2]   = __floats2half2_rn(v.x, v.y);
        dh[tid*2+1] = __floats2half2_rn(v.z, v.w);
    } else if (bid < PM_COND) {
        int j = bid - PM_PAD;
        int n4 = (BGR*SEQ*LATD) >> 2;
        for (int i = j*128 + tid; i < n4; i += 2048*128) {
            float4 v = ((const float4*)cond)[i];
            __half2* d = (__half2*)cond_h;
            d[i*2]   = __floats2half2_rn(v.x, v.y);
            d[i*2+1] = __floats2half2_rn(v.z, v.w);
        }
    } else if (bid < PM_HT) {
        int t = bid - PM_COND;
        int z = t >> 8, rem = t & 255;
        const float* s = z ? W1 : Wo;
        __half* d = z ? W1T : WoT;
        int bx = (rem & 15)*32, by = (rem >> 4)*32;
        int x = tid & 31, y0 = tid >> 5;
        #pragma unroll
        for (int i = 0; i < 32; i += 4)
            sh[(y0+i)*33 + x] = s[(size_t)(by + y0 + i)*DMODEL + bx + x];
        __syncthreads();
        #pragma unroll
        for (int i = 0; i < 32; i += 4)
            d[(size_t)(bx + y0 + i)*DMODEL + by + x] = __float2half_rn(sh[x*33 + y0+i]);
    } else if (bid < PM_BIAS) {
        int t = bid - PM_HT;
        int z = t >> 4, blk = t & 15;
        const float* bin = (z==0) ? bq : (z==1) ? bk : bv;
        const float* W = inw + (size_t)z*DMODEL*DMODEL;
        const float* ab = inb + z*DMODEL;
        float* outp = (z==0) ? bq2 : (z==1) ? bk2 : bv2;
        int jj = tid & 31;
        int r = tid >> 5;
        int j = blk*32 + jj;
        float a = 0.f;
        #pragma unroll 8
        for (int i = r*128; i < r*128 + 128; i++)
            a += bin[i]*W[(size_t)i*DMODEL + j];
        sh[r*32 + jj] = a;
        __syncthreads();
        if (r == 0) {
            float s = ab[j];
            #pragma unroll
            for (int k = 0; k < 4; k++) s += sh[k*32 + jj];
            outp[j] = s;
        }
    } else if (bid < PM_CONVW) {
        // straight convert Wq/Wk/Wv -> half.  262144 float4 total, 512 f4/block
        int t = bid - PM_BIAS;
        #pragma unroll
        for (int i = 0; i < 4; i++) {
            int idx = t*512 + i*128 + tid;
            const float* src; __half* dst; int loc;
            if (idx < 65536)       { src = Wq; dst = Wqh; loc = idx; }
            else if (idx < 163840) { src = Wk; dst = Wkh; loc = idx - 65536; }
            else                   { src = Wv; dst = Wvh; loc = idx - 163840; }
            float4 v = ((const float4*)src)[loc];
            ((__half2*)dst)[loc*2]   = __floats2half2_rn(v.x, v.y);
            ((__half2*)dst)[loc*2+1] = __floats2half2_rn(v.z, v.w);
        }
    } else {
        // transpose-convert in_w[z] (512x512) -> inwT half
        int t = bid - PM_CONVW;
        int z = t >> 8, rem = t & 255;
        const float* s = inw + (size_t)z*DMODEL*DMODEL;
        __half* d = inwT + (size_t)z*DMODEL*DMODEL;
        int bx = (rem & 15)*32, by = (rem >> 4)*32;
        int x = tid & 31, y0 = tid >> 5;
        #pragma unroll
        for (int i = 0; i < 32; i += 4)
            sh[(y0+i)*33 + x] = s[(size_t)(by + y0 + i)*DMODEL + bx + x];
        __syncthreads();
        #pragma unroll
        for (int i = 0; i < 32; i += 4)
            d[(size_t)(bx + y0 + i)*DMODEL + by + x] = __float2half_rn(sh[x*33 + y0+i]);
    }
}

// ---------------- 3-stage cp.async FP16 GEMM ----------------
// MODE 1: C(fp32) = A@B + bias + Dm ; MODE 2: leaky then += Dm
// MODE 3: C(half) = A@B + bias ; MODE 4: C(half, transposed CT[n*Mstr+m])
#define TSTRH 40
#define STG_B (128*TSTRH*2)
#define GEMM_SMEM (3*2*STG_B)

template<int MODE>
__device__ __forceinline__ void gemm_body(
    const __half* __restrict__ A, const __half* __restrict__ Bt,
    const float* __restrict__ bias, const float* __restrict__ Dm,
    void* __restrict__ Cv, int N, int K, char* smem, int Mstr)
{
    char* As = smem;
    char* Bs = smem + 3*STG_B;

    int tid = threadIdx.x;
    int warp = tid >> 5, lane = tid & 31;
    int warp_m = warp & 3, warp_n = warp >> 2;
    int p = lane >> 2, q = lane & 3;
    int blockM = blockIdx.y * 128;
    int blockN = blockIdx.x * 128;

    int c0 = tid*2, c1 = c0 + 1;
    int r0c = c0 >> 2, k0c = (c0 & 3)*8;
    int r1c = c1 >> 2, k1c = (c1 & 3)*8;

    const __half* gA0 = A  + (size_t)(blockM + r0c)*K + k0c;
    const __half* gA1 = A  + (size_t)(blockM + r1c)*K + k1c;
    const __half* gB0 = Bt + (size_t)(blockN + r0c)*K + k0c;
    const __half* gB1 = Bt + (size_t)(blockN + r1c)*K + k1c;

    unsigned sa = (unsigned)__cvta_generic_to_shared(As);
    unsigned sb = (unsigned)__cvta_generic_to_shared(Bs);
    unsigned dA0[3], dA1[3], dB0[3], dB1[3];
    #pragma unroll
    for (int s = 0; s < 3; s++) {
        dA0[s] = sa + s*STG_B + (r0c*TSTRH + k0c)*2;
        dA1[s] = sa + s*STG_B + (r1c*TSTRH + k1c)*2;
        dB0[s] = sb + s*STG_B + (r0c*TSTRH + k0c)*2;
        dB1[s] = sb + s*STG_B + (r1c*TSTRH + k1c)*2;
    }

    unsigned aBase = sa + ((warp_m*32 + (lane & 15))*TSTRH + (lane >> 4)*8)*2;
    unsigned bBase = sb + ((warp_n*64 + ((lane >> 4) << 3) + (lane & 7))*TSTRH
                           + ((lane >> 3) & 1)*8)*2;

    float acc[2][8][4];
    #pragma unroll
    for (int mt = 0; mt < 2; mt++)
        #pragma unroll
        for (int nt = 0; nt < 8; nt++)
            #pragma unroll
            for (int i = 0; i < 4; i++) acc[mt][nt][i] = 0.f;

    CP16(dA0[0], gA0); CP16(dA1[0], gA1);
    CP16(dB0[0], gB0); CP16(dB1[0], gB1);
    asm volatile("cp.async.commit_group;");
    CP16(dA0[1], gA0 + 32); CP16(dA1[1], gA1 + 32);
    CP16(dB0[1], gB0 + 32); CP16(dB1[1], gB1 + 32);
    asm volatile("cp.async.commit_group;");

    int nk = K >> 5;
    int sc = 0, sp = 2;
    for (int t = 0; t < nk; t++) {
        asm volatile("cp.async.wait_group 1;");
        __syncthreads();
        if (t + 2 < nk) {
            int kt = (t + 2) << 5;
            CP16(dA0[sp], gA0 + kt); CP16(dA1[sp], gA1 + kt);
            CP16(dB0[sp], gB0 + kt); CP16(dB1[sp], gB1 + kt);
        }
        asm volatile("cp.async.commit_group;");
        unsigned ao = aBase + sc*STG_B;
        unsigned bo = bBase + sc*STG_B;
        #pragma unroll
        for (int kk = 0; kk < 32; kk += 16) {
            unsigned afr[2][4];
            LDSM4(afr[0], ao + kk*2);
            LDSM4(afr[1], ao + (16*TSTRH + kk)*2);
            unsigned bfr[4][4];
            #pragma unroll
            for (int j = 0; j < 4; j++)
                LDSM4(bfr[j], bo + (j*16*TSTRH + kk)*2);
            #pragma unroll
            for (int mt = 0; mt < 2; mt++)
                #pragma unroll
                for (int nt = 0; nt < 8; nt++)
                    mma_f16(acc[mt][nt],
                            afr[mt][0], afr[mt][1], afr[mt][2], afr[mt][3],
                            bfr[nt >> 1][(nt & 1)*2], bfr[nt >> 1][(nt & 1)*2 + 1]);
        }
        sc++; if (sc == 3) sc = 0;
        sp++; if (sp == 3) sp = 0;
    }

    #pragma unroll
    for (int mt = 0; mt < 2; mt++) {
        int r0 = blockM + warp_m*32 + mt*16 + p;
        #pragma unroll
        for (int nt = 0; nt < 8; nt++) {
            int c0c = blockN + warp_n*64 + nt*8 + 2*q;
            float b0 = 0.f, b1 = 0.f;
            if (bias) { b0 = bias[c0c]; b1 = bias[c0c+1]; }
            float v0 = acc[mt][nt][0] + b0;
            float v1 = acc[mt][nt][1] + b1;
            float v2 = acc[mt][nt][2] + b0;
            float v3 = acc[mt][nt][3] + b1;
            if (MODE == 4) {
                __half* Ch = (__half*)Cv;
                Ch[(size_t)(c0c  )*Mstr + r0    ] = __float2half_rn(v0);
                Ch[(size_t)(c0c+1)*Mstr + r0    ] = __float2half_rn(v1);
                Ch[(size_t)(c0c  )*Mstr + r0 + 8] = __float2half_rn(v2);
                Ch[(size_t)(c0c+1)*Mstr + r0 + 8] = __float2half_rn(v3);
            } else {
                size_t o0 = (size_t)r0*N + c0c;
                size_t o1 = (size_t)(r0+8)*N + c0c;
                if (MODE == 3) {
                    __half* Ch = (__half*)Cv;
                    *(__half2*)&Ch[o0] = __floats2half2_rn(v0, v1);
                    *(__half2*)&Ch[o1] = __floats2half2_rn(v2, v3);
                } else {
                    float* C = (float*)Cv;
                    if (MODE == 1) {
                        float2 d0 = *(const float2*)(Dm + o0);
                        float2 d1 = *(const float2*)(Dm + o1);
                        v0 += d0.x; v1 += d0.y; v2 += d1.x; v3 += d1.y;
                    }
                    if (MODE == 2) {
                        v0 = (v0 > 0.f) ? v0 : 0.01f*v0;
                        v1 = (v1 > 0.f) ? v1 : 0.01f*v1;
                        v2 = (v2 > 0.f) ? v2 : 0.01f*v2;
                        v3 = (v3 > 0.f) ? v3 : 0.01f*v3;
                        float2 d0 = *(const float2*)(Dm + o0);
                        float2 d1 = *(const float2*)(Dm + o1);
                        v0 += d0.x; v1 += d0.y; v2 += d1.x; v3 += d1.y;
                    }
                    *(float2*)(C + o0) = make_float2(v0, v1);
                    *(float2*)(C + o1) = make_float2(v2, v3);
                }
            }
        }
    }
}

template<int MODE>
__global__ __launch_bounds__(256, 2) void gemm_one(
    const __half* __restrict__ A, const __half* __restrict__ Bt,
    const float* __restrict__ bias, const float* __restrict__ Dm,
    float* __restrict__ C, int N, int K)
{
    extern __shared__ char smem[];
    gemm_body<MODE>(A, Bt, bias, Dm, C, N, K, smem, 0);
}

// weight fold: z=0 Wq (M=512), z=1 Wk (M=768), z=2 Wv (M=768); writes CT half
__global__ __launch_bounds__(256, 2) void gemm_fold(
    const __half* __restrict__ Wqh, const __half* __restrict__ Wkh,
    const __half* __restrict__ Wvh, const __half* __restrict__ inwT,
    __half* __restrict__ WqT, __half* __restrict__ WkT, __half* __restrict__ WvT)
{
    extern __shared__ char smem[];
    int z = blockIdx.z;
    int M = (z == 0) ? DMODEL : LATD;
    if ((int)blockIdx.y*128 >= M) return;
    const __half* A = (z==0) ? Wqh : (z==1) ? Wkh : Wvh;
    const __half* Bt = inwT + (size_t)z*DMODEL*DMODEL;
    __half* C = (z==0) ? WqT : (z==1) ? WkT : WvT;
    gemm_body<4>(A, Bt, nullptr, nullptr, C, DMODEL, DMODEL, smem, M);
}

__global__ __launch_bounds__(256, 2) void gemm_all(
    const __half* __restrict__ dense_h, const __half* __restrict__ cond_h,
    const __half* __restrict__ WqT, const __half* __restrict__ WkT,
    const __half* __restrict__ WvT,
    const float* __restrict__ bq2, const float* __restrict__ bk2,
    const float* __restrict__ bv2,
    __half* __restrict__ qh2, __half* __restrict__ kh2, __half* __restrict__ vh2)
{
    extern __shared__ char smem[];
    int z = blockIdx.z;
    if (z < 2) {
        if (blockIdx.y >= 32) return;
        gemm_body<3>(cond_h, z ? WvT : WkT, z ? bv2 : bk2, nullptr,
                     z ? (void*)vh2 : (void*)kh2, DMODEL, LATD, smem, 0);
    } else {
        gemm_body<3>(dense_h, WqT, bq2, nullptr, (void*)qh2, DMODEL, DMODEL, smem, 0);
    }
}

// ---------------- fp16 attention v3: double-buffered K/V/Q across heads ----
#define TB    64
#define QSTR  72
#define KVSTR 72
#define PSTR2 264
#define AK_BYTES (SEQ*KVSTR*2)     // 36864
#define AQ_BYTES (TB*QSTR*2)       // 9216
#define SM_K  0
#define SM_V  (2*AK_BYTES)         // 73728
#define SM_Q  (SM_V + 2*AK_BYTES)  // 147456
#define SM_P  (SM_Q + 2*AQ_BYTES)  // 165888
#define SM_MASK (SM_P + TB*PSTR2*2)// 199680
#define ATT_SMEM (SM_MASK + SEQ*4) // 200704

__global__ __launch_bounds__(512, 1) void attn_f16(
    const __half* __restrict__ qh2, const __half* __restrict__ kh2,
    const __half* __restrict__ vh2, const int* __restrict__ maskp,
    __half* __restrict__ ctx, float* __restrict__ av_out)
{
    extern __shared__ char smc[];
    __half* sP  = (__half*)(smc + SM_P);
    int* sMask  = (int*)(smc + SM_MASK);

    int b = blockIdx.y, lt = blockIdx.x;
    int tid = threadIdx.x;
    int w = tid >> 5, lane = tid & 31;
    int p = lane >> 2, q = lane & 3;

    unsigned sk = (unsigned)__cvta_generic_to_shared(smc + SM_K);
    unsigned sv = (unsigned)__cvta_generic_to_shared(smc + SM_V);
    unsigned sq = (unsigned)__cvta_generic_to_shared(smc + SM_Q);
    unsigned spb = (unsigned)__cvta_generic_to_shared(sP);

    if (tid < SEQ) sMask[tid] = maskp[b*SEQ + tid];

    // per-lane mma smem bases (add buf offsets at use)
    unsigned aQ = sq + ((lane & 15)*QSTR + (lane >> 4)*8)*2;
    unsigned bK = sk + ((w*16 + ((lane >> 4) << 3) + (lane & 7))*KVSTR
                        + ((lane >> 3) & 1)*8)*2;
    int mtw = w & 3, ng = w >> 2;
    unsigned aP = spb + ((mtw*16 + (lane & 15))*PSTR2 + (lane >> 4)*8)*2;
    unsigned bV = sv + (((lane & 7) + ((lane >> 3) & 1)*8)*KVSTR
                        + ng*16 + (lane >> 4)*8)*2;

    // Q row/chunk for this thread's cp.async
    int qrow = tid >> 3, qch = tid & 7;
    int ql = lt*TB + qrow; if (ql > LMAX-1) ql = LMAX-1;

    // ---- prologue: issue head 0 into buf 0 ----
    {
        const __half* kg = kh2 + (size_t)b*SEQ*DMODEL;
        const __half* vg = vh2 + (size_t)b*SEQ*DMODEL;
        #pragma unroll
        for (int i = 0; i < 4; i++) {
            int c = tid + 512*i;
            int s = c >> 3, ch = c & 7;
            CP16(sk + (s*KVSTR + ch*8)*2, kg + (size_t)s*DMODEL + ch*8);
            CP16(sv + (s*KVSTR + ch*8)*2, vg + (size_t)s*DMODEL + ch*8);
        }
        CP16(sq + (qrow*QSTR + qch*8)*2,
             qh2 + (size_t)(b*LMAX + ql)*DMODEL + qch*8);
    }
    asm volatile("cp.async.commit_group;");

    float avacc[4][8];
    #pragma unroll
    for (int rr = 0; rr < 4; rr++)
        #pragma unroll
        for (int jj = 0; jj < 8; jj++) avacc[rr][jj] = 0.f;

    for (int h = 0; h < NH; h++) {
        int buf = h & 1;
        __syncthreads();   // prev head PV done -> other buffer free; mask visible
        if (h + 1 < NH) {
            int hh = h + 1, ob = buf ^ 1;
            const __half* kg = kh2 + (size_t)b*SEQ*DMODEL + hh*DH;
            const __half* vg = vh2 + (size_t)b*SEQ*DMODEL + hh*DH;
            #pragma unroll
            for (int i = 0; i < 4; i++) {
                int c = tid + 512*i;
                int s = c >> 3, ch = c & 7;
                CP16(sk + ob*AK_BYTES + (s*KVSTR + ch*8)*2, kg + (size_t)s*DMODEL + ch*8);
                CP16(sv + ob*AK_BYTES + (s*KVSTR + ch*8)*2, vg + (size_t)s*DMODEL + ch*8);
            }
            CP16(sq + ob*AQ_BYTES + (qrow*QSTR + qch*8)*2,
                 qh2 + (size_t)(b*LMAX + ql)*DMODEL + hh*DH + qch*8);
        }
        asm volatile("cp.async.commit_group;");
        asm volatile("cp.async.wait_group 1;");
        __syncthreads();

        unsigned aQb = aQ + buf*AQ_BYTES;
        unsigned bKb = bK + buf*AK_BYTES;
        unsigned bVb = bV + buf*AK_BYTES;

        // ---- QK^T: warp w owns cols [16w,16w+16), 4 m-tiles ----
        float csc[2][4][4];
        #pragma unroll
        for (int j = 0; j < 2; j++)
            #pragma unroll
            for (int mt = 0; mt < 4; mt++)
                #pragma unroll
                for (int i = 0; i < 4; i++) csc[j][mt][i] = 0.f;
        #pragma unroll
        for (int ks = 0; ks < 4; ks++) {
            int kk = ks*16;
            unsigned bfr[4];
            LDSM4(bfr, bKb + kk*2);
            #pragma unroll
            for (int mt = 0; mt < 4; mt++) {
                unsigned afr[4];
                LDSM4(afr, aQb + (mt*16*QSTR + kk)*2);
                mma_f16(csc[0][mt], afr[0], afr[1], afr[2], afr[3], bfr[0], bfr[1]);
                mma_f16(csc[1][mt], afr[0], afr[1], afr[2], afr[3], bfr[2], bfr[3]);
            }
        }
        // write raw scores to sP
        #pragma unroll
        for (int j = 0; j < 2; j++)
            #pragma unroll
            for (int mt = 0; mt < 4; mt++) {
                int row = mt*16 + p;
                int col = (2*w + j)*8 + 2*q;
                *(__half2*)&sP[row*PSTR2 + col]     = __floats2half2_rn(csc[j][mt][0], csc[j][mt][1]);
                *(__half2*)&sP[(row+8)*PSTR2 + col] = __floats2half2_rn(csc[j][mt][2], csc[j][mt][3]);
            }
        __syncthreads();
        // ---- softmax: warp w owns rows [4w,4w+4) ----
        #pragma unroll
        for (int rr = 0; rr < 4; rr++) {
            int row = 4*w + rr;
            float v[8];
            float m = -1e30f;
            #pragma unroll
            for (int jj = 0; jj < 8; jj++) {
                int s = lane + 32*jj;
                float x = sMask[s] ? -1e30f : __half2float(sP[row*PSTR2 + s])*0.125f;
                v[jj] = x;
                m = fmaxf(m, x);
            }
            #pragma unroll
            for (int o = 16; o > 0; o >>= 1) m = fmaxf(m, __shfl_xor_sync(0xffffffffu, m, o));
            float sum = 0.f;
            #pragma unroll
            for (int jj = 0; jj < 8; jj++) { v[jj] = __expf(v[jj] - m); sum += v[jj]; }
            #pragma unroll
            for (int o = 16; o > 0; o >>= 1) sum += __shfl_xor_sync(0xffffffffu, sum, o);
            float inv = 1.f/sum;
            #pragma unroll
            for (int jj = 0; jj < 8; jj++) {
                float pp = v[jj]*inv;
                avacc[rr][jj] += pp;
                sP[row*PSTR2 + lane + 32*jj] = __float2half_rn(pp);
            }
        }
        __syncthreads();
        // ---- P@V: warp w -> m-tile mtw, d-cols [16ng, 16ng+16) ----
        float cct[2][4];
        #pragma unroll
        for (int j = 0; j < 2; j++)
            #pragma unroll
            for (int i = 0; i < 4; i++) cct[j][i] = 0.f;
        #pragma unroll 4
        for (int ks = 0; ks < 16; ks++) {
            int kk = ks*16;
            unsigned afr[4], bfr[4];
            LDSM4(afr, aP + kk*2);
            LDSM4T(bfr, bVb + kk*KVSTR*2);
            mma_f16(cct[0], afr[0], afr[1], afr[2], afr[3], bfr[0], bfr[1]);
            mma_f16(cct[1], afr[0], afr[1], afr[2], afr[3], bfr[2], bfr[3]);
        }
        #pragma unroll
        for (int j = 0; j < 2; j++) {
            int dc = h*DH + ng*16 + j*8 + 2*q;
            int l0 = lt*TB + mtw*16 + p;
            if (l0 < LMAX)
                *(__half2*)&ctx[((size_t)(b*LMAX) + l0)*DMODEL + dc] =
                    __floats2half2_rn(cct[j][0], cct[j][1]);
            int l1 = l0 + 8;
            if (l1 < LMAX)
                *(__half2*)&ctx[((size_t)(b*LMAX) + l1)*DMODEL + dc] =
                    __floats2half2_rn(cct[j][2], cct[j][3]);
        }
    }

    // ---- head-averaged attention ----
    #pragma unroll
    for (int rr = 0; rr < 4; rr++) {
        int l = lt*TB + 4*w + rr;
        if (l < LMAX) {
            #pragma unroll
            for (int jj = 0; jj < 8; jj++)
                av_out[((size_t)(b*LMAX) + l)*SEQ + lane + 32*jj] = avacc[rr][jj]*0.125f;
        }
    }
}

// ---------------- LN1: fp32 residual + half operand ----------
__global__ __launch_bounds__(128) void ln_dual(
    const float* __restrict__ x, const float* __restrict__ g,
    const float* __restrict__ bb, float* __restrict__ yf, __half* __restrict__ yh)
{
    __shared__ float ws[4], wss[4];
    int r = blockIdx.x;
    int tid = threadIdx.x;
    const float4* xr = (const float4*)(x + (size_t)r*DMODEL);
    float4 v = xr[tid];
    float s  = v.x + v.y + v.z + v.w;
    float ss = v.x*v.x + v.y*v.y + v.z*v.z + v.w*v.w;
    #pragma unroll
    for (int o = 16; o > 0; o >>= 1) {
        s  += __shfl_xor_sync(0xffffffffu, s,  o);
        ss += __shfl_xor_sync(0xffffffffu, ss, o);
    }
    int warp = tid >> 5, lane = tid & 31;
    if (lane == 0) { ws[warp] = s; wss[warp] = ss; }
    __syncthreads();
    float S  = ws[0] + ws[1] + ws[2] + ws[3];
    float SS = wss[0] + wss[1] + wss[2] + wss[3];
    float mean = S * (1.f/DMODEL);
    float var  = SS * (1.f/DMODEL) - mean*mean;
    float rstd = rsqrtf(var + 1e-5f);
    float4 gg = ((const float4*)g)[tid];
    float4 b4 = ((const float4*)bb)[tid];
    float4 o4;
    o4.x = (v.x - mean)*rstd*gg.x + b4.x;
    o4.y = (v.y - mean)*rstd*gg.y + b4.y;
    o4.z = (v.z - mean)*rstd*gg.z + b4.z;
    o4.w = (v.w - mean)*rstd*gg.w + b4.w;
    ((float4*)(yf + (size_t)r*DMODEL))[tid] = o4;
    __half2* yhp = (__half2*)(yh + (size_t)r*DMODEL);
    yhp[tid*2]   = __floats2half2_rn(o4.x, o4.y);
    yhp[tid*2+1] = __floats2half2_rn(o4.z, o4.w);
}

// ---------------- fused LN2 + ragged gather ----------
__global__ __launch_bounds__(128) void ln_gather(
    const float* __restrict__ x, const int* __restrict__ gb,
    const float* __restrict__ g, const float* __restrict__ bb,
    float* __restrict__ out)
{
    __shared__ float ws[4], wss[4];
    int i = blockIdx.x;
    int b = gb[i];
    int pp = i - lower_bound_gb(gb, b);
    size_t row = (size_t)b*LMAX + pp;
    int tid = threadIdx.x;
    float4 v = ((const float4*)(x + row*DMODEL))[tid];
    float s  = v.x + v.y + v.z + v.w;
    float ss = v.x*v.x + v.y*v.y + v.z*v.z + v.w*v.w;
    #pragma unroll
    for (int o = 16; o > 0; o >>= 1) {
        s  += __shfl_xor_sync(0xffffffffu, s,  o);
        ss += __shfl_xor_sync(0xffffffffu, ss, o);
    }
    int warp = tid >> 5, lane = tid & 31;
    if (lane == 0) { ws[warp] = s; wss[warp] = ss; }
    __syncthreads();
    float S  = ws[0] + ws[1] + ws[2] + ws[3];
    float SS = wss[0] + wss[1] + wss[2] + wss[3];
    float mean = S * (1.f/DMODEL);
    float var  = SS * (1.f/DMODEL) - mean*mean;
    float rstd = rsqrtf(var + 1e-5f);
    float4 gg = ((const float4*)g)[tid];
    float4 b4 = ((const float4*)bb)[tid];
    float4 o4;
    o4.x = (v.x - mean)*rstd*gg.x + b4.x;
    o4.y = (v.y - mean)*rstd*gg.y + b4.y;
    o4.z = (v.z - mean)*rstd*gg.z + b4.z;
    o4.w = (v.w - mean)*rstd*gg.w + b4.w;
    ((float4*)(out + (size_t)i*DMODEL))[tid] = o4;
}

// ---------------- launch ----------------
extern "C" void kernel_launch(void* const* d_in, const int* in_sizes, int n_in,
                              void* d_out, int out_size)
{
    int off = (n_in >= 22) ? 0 : 2;
    const float* nodes  = (const float*)d_in[0];
    const int*   gb     = (const int*)  d_in[1];
    const float* cond   = (const float*)d_in[2];
    const int*   maskp  = (const int*)  d_in[3];
    const float* Wq     = (const float*)d_in[6-off];
    const float* bq     = (const float*)d_in[7-off];
    const float* Wk     = (const float*)d_in[8-off];
    const float* bk     = (const float*)d_in[9-off];
    const float* Wv     = (const float*)d_in[10-off];
    const float* bv     = (const float*)d_in[11-off];
    const float* in_w   = (const float*)d_in[12-off];
    const float* in_b   = (const float*)d_in[13-off];
    const float* Wo     = (const float*)d_in[14-off];
    const float* bo     = (const float*)d_in[15-off];
    const float* ln1g   = (const float*)d_in[16-off];
    const float* ln1b   = (const float*)d_in[17-off];
    const float* W1     = (const float*)d_in[18-off];
    const float* b1     = (const float*)d_in[19-off];
    const float* ln2g   = (const float*)d_in[20-off];
    const float* ln2b   = (const float*)d_in[21-off];
    float* out = (float*)d_out;
    float* av_out = out + (size_t)NN*DMODEL;

    float *p_dense_f, *p_y, *p_x1f, *p_h, *p_bq2, *p_bk2, *p_bv2;
    __half *p_dense_h, *p_qh2, *p_kh2, *p_vh2, *p_ctx, *p_x1h;
    __half *p_WqT, *p_WkT, *p_WvT, *p_WoT, *p_W1T, *p_cond;
    __half *p_Wqh, *p_Wkh, *p_Wvh, *p_inwT;
    cudaGetSymbolAddress((void**)&p_dense_f, g_dense_f);
    cudaGetSymbolAddress((void**)&p_dense_h, g_dense_h);
    cudaGetSymbolAddress((void**)&p_qh2, g_qh2);
    cudaGetSymbolAddress((void**)&p_kh2, g_kh2);
    cudaGetSymbolAddress((void**)&p_vh2, g_vh2);
    cudaGetSymbolAddress((void**)&p_ctx, g_ctx);
    cudaGetSymbolAddress((void**)&p_y, g_y);
    cudaGetSymbolAddress((void**)&p_x1f, g_x1f);
    cudaGetSymbolAddress((void**)&p_x1h, g_x1h);
    cudaGetSymbolAddress((void**)&p_h, g_h);
    cudaGetSymbolAddress((void**)&p_WqT, g_WqT);
    cudaGetSymbolAddress((void**)&p_WkT, g_WkT);
    cudaGetSymbolAddress((void**)&p_WvT, g_WvT);
    cudaGetSymbolAddress((void**)&p_WoT, g_WoT);
    cudaGetSymbolAddress((void**)&p_W1T, g_W1T);
    cudaGetSymbolAddress((void**)&p_cond, g_cond);
    cudaGetSymbolAddress((void**)&p_Wqh, g_Wqh);
    cudaGetSymbolAddress((void**)&p_Wkh, g_Wkh);
    cudaGetSymbolAddress((void**)&p_Wvh, g_Wvh);
    cudaGetSymbolAddress((void**)&p_inwT, g_inwT);
    cudaGetSymbolAddress((void**)&p_bq2, g_bq2);
    cudaGetSymbolAddress((void**)&p_bk2, g_bk2);
    cudaGetSymbolAddress((void**)&p_bv2, g_bv2);

    cudaFuncSetAttribute(gemm_one<1>, cudaFuncAttributeMaxDynamicSharedMemorySize, GEMM_SMEM);
    cudaFuncSetAttribute(gemm_one<2>, cudaFuncAttributeMaxDynamicSharedMemorySize, GEMM_SMEM);
    cudaFuncSetAttribute(gemm_all,    cudaFuncAttributeMaxDynamicSharedMemorySize, GEMM_SMEM);
    cudaFuncSetAttribute(gemm_fold,   cudaFuncAttributeMaxDynamicSharedMemorySize, GEMM_SMEM);
    cudaFuncSetAttribute(attn_f16,    cudaFuncAttributeMaxDynamicSharedMemorySize, ATT_SMEM);

    // 1) mega prologue: pad + cond/W converts + Wo/W1 + in_w transposes + biases
    prologue_misc<<<PM_TINW, 128>>>(nodes, gb, cond, Wo, W1, Wq, Wk, Wv,
                                    bq, bk, bv, in_w, in_b,
                                    p_dense_f, p_dense_h, p_cond, p_WoT, p_W1T,
                                    p_Wqh, p_Wkh, p_Wvh, p_inwT,
                                    p_bq2, p_bk2, p_bv2);
    // 2) fold projection weights (fp16 pipelined GEMM, transposed half output)
    gemm_fold<<<dim3(4,6,3), 256, GEMM_SMEM>>>(p_Wqh, p_Wkh, p_Wvh, p_inwT,
                                               p_WqT, p_WkT, p_WvT);
    // 3) Q + K + V projections
    gemm_all<<<dim3(4,124,3), 256, GEMM_SMEM>>>(p_dense_h, p_cond, p_WqT, p_WkT, p_WvT,
                                                p_bq2, p_bk2, p_bv2, p_qh2, p_kh2, p_vh2);
    // 4) fp16 attention v3  <-- profiled launch
    attn_f16<<<dim3(16, BGR), 512, ATT_SMEM>>>(p_qh2, p_kh2, p_vh2, maskp, p_ctx, av_out);
    // 5) out proj + residual
    gemm_one<1><<<dim3(4,124), 256, GEMM_SMEM>>>(p_ctx, p_WoT, bo, p_dense_f, p_y, DMODEL, DMODEL);
    // 6) LN1
    ln_dual<<<ROWS_Q, 128>>>(p_y, ln1g, ln1b, p_x1f, p_x1h);
    // 7) FFN + leaky + residual
    gemm_one<2><<<dim3(4,124), 256, GEMM_SMEM>>>(p_x1h, p_W1T, b1, p_x1f, p_h, DMODEL, DMODEL);
    // 8) LN2 + ragged gather
    ln_gather<<<NN, 128>>>(p_h, gb, ln2g, ln2b, out);
}

// round 12
// speedup vs baseline: 6.7019x; 1.0110x over previous
#include <cuda_runtime.h>
#include <cuda_fp16.h>
#include <cuda_bf16.h>
#include <math.h>

// ---------------- problem constants ----------------
#define NN    12032
#define DMODEL 512
#define BGR   16
#define SEQ   256
#define NH    8
#define DH    64
#define LMAX  992
#define LATD  768
#define ROWS_Q  (BGR*LMAX)   // 15872
#define ROWS_KV (BGR*SEQ)    // 4096

// ---------------- scratch ----------
__device__ __half g_dense_h[ROWS_Q*DMODEL];
__device__ __half g_qh2 [ROWS_Q*DMODEL];
__device__ __half g_kh2 [ROWS_KV*DMODEL];
__device__ __half g_vh2 [ROWS_KV*DMODEL];
__device__ __half g_ctx [ROWS_Q*DMODEL];
__device__ float  g_y   [ROWS_Q*DMODEL];
__device__ __half g_x1h [ROWS_Q*DMODEL];
__device__ float  g_h   [ROWS_Q*DMODEL];
__device__ __half g_WqT [DMODEL*DMODEL];
__device__ __half g_WkT [LATD*DMODEL];
__device__ __half g_WvT [LATD*DMODEL];
__device__ __half g_WoT [DMODEL*DMODEL];
__device__ __half g_W1T [DMODEL*DMODEL];
__device__ __half g_cond[BGR*SEQ*LATD];
__device__ __half g_Wqh [DMODEL*DMODEL];
__device__ __half g_Wkh [LATD*DMODEL];
__device__ __half g_Wvh [LATD*DMODEL];
__device__ __half g_inwT[3*DMODEL*DMODEL];
__device__ float  g_bq2 [DMODEL];
__device__ float  g_bk2 [DMODEL];
__device__ float  g_bv2 [DMODEL];

// ---------------- helpers ----------------
__device__ __forceinline__ void mma_f16(float c[4],
    unsigned a0, unsigned a1, unsigned a2, unsigned a3,
    unsigned b0, unsigned b1)
{
    asm volatile(
        "mma.sync.aligned.m16n8k16.row.col.f32.f16.f16.f32 "
        "{%0,%1,%2,%3}, {%4,%5,%6,%7}, {%8,%9}, {%0,%1,%2,%3};"
        : "+f"(c[0]), "+f"(c[1]), "+f"(c[2]), "+f"(c[3])
        : "r"(a0), "r"(a1), "r"(a2), "r"(a3), "r"(b0), "r"(b1));
}

#define CP16(dst, src) asm volatile("cp.async.cg.shared.global [%0], [%1], 16;" :: "r"(dst), "l"(src))
#define LDSM4(r, addr) asm volatile( \
    "ldmatrix.sync.aligned.m8n8.x4.shared.b16 {%0,%1,%2,%3}, [%4];" \
    : "=r"((r)[0]), "=r"((r)[1]), "=r"((r)[2]), "=r"((r)[3]) : "r"(addr))
#define LDSM4T(r, addr) asm volatile( \
    "ldmatrix.sync.aligned.m8n8.x4.trans.shared.b16 {%0,%1,%2,%3}, [%4];" \
    : "=r"((r)[0]), "=r"((r)[1]), "=r"((r)[2]), "=r"((r)[3]) : "r"(addr))

__device__ __forceinline__ int lower_bound_gb(const int* __restrict__ gb, int b) {
    int lo = 0, hi = NN;
    while (lo < hi) { int mid = (lo + hi) >> 1; if (gb[mid] < b) lo = mid + 1; else hi = mid; }
    return lo;
}

// ---------------- mega-prologue ----------
#define PM_PAD   ROWS_Q             // 15872
#define PM_COND  (PM_PAD + 2048)    // 17920
#define PM_HT    (PM_COND + 512)    // 18432
#define PM_BIAS  (PM_HT + 48)       // 18480
#define PM_CONVW (PM_BIAS + 512)    // 18992
#define PM_TINW  (PM_CONVW + 768)   // 19760 (grid size)

__global__ __launch_bounds__(128) void prologue_misc(
    const float* __restrict__ nodes, const int* __restrict__ gb,
    const float* __restrict__ cond,  const float* __restrict__ Wo,
    const float* __restrict__ W1,
    const float* __restrict__ Wq, const float* __restrict__ Wk,
    const float* __restrict__ Wv,
    const float* __restrict__ bq, const float* __restrict__ bk,
    const float* __restrict__ bv, const float* __restrict__ inw,
    const float* __restrict__ inb,
    __half* __restrict__ dense_h,
    __half* __restrict__ cond_h, __half* __restrict__ WoT, __half* __restrict__ W1T,
    __half* __restrict__ Wqh, __half* __restrict__ Wkh, __half* __restrict__ Wvh,
    __half* __restrict__ inwT,
    float* __restrict__ bq2, float* __restrict__ bk2, float* __restrict__ bv2)
{
    __shared__ float sh[32*33];
    int bid = blockIdx.x, tid = threadIdx.x;
    if (bid < PM_PAD) {
        int r = bid;
        int b = r / LMAX, pp = r - b*LMAX;
        int start = lower_bound_gb(gb, b);
        int i = start + pp;
        float4 v = make_float4(0.f, 0.f, 0.f, 0.f);
        if (i < NN && gb[i] == b)
            v = ((const float4*)(nodes + (size_t)i*DMODEL))[tid];
        __half2* dh = (__half2*)(dense_h + (size_t)r*DMODEL);
        dh[tid*2]   = __floats2half2_rn(v.x, v.y);
        dh[tid*2+1] = __floats2half2_rn(v.z, v.w);
    } else if (bid < PM_COND) {
        int j = bid - PM_PAD;
        int n4 = (BGR*SEQ*LATD) >> 2;
        for (int i = j*128 + tid; i < n4; i += 2048*128) {
            float4 v = ((const float4*)cond)[i];
            __half2* d = (__half2*)cond_h;
            d[i*2]   = __floats2half2_rn(v.x, v.y);
            d[i*2+1] = __floats2half2_rn(v.z, v.w);
        }
    } else if (bid < PM_HT) {
        int t = bid - PM_COND;
        int z = t >> 8, rem = t & 255;
        const float* s = z ? W1 : Wo;
        __half* d = z ? W1T : WoT;
        int bx = (rem & 15)*32, by = (rem >> 4)*32;
        int x = tid & 31, y0 = tid >> 5;
        #pragma unroll
        for (int i = 0; i < 32; i += 4)
            sh[(y0+i)*33 + x] = s[(size_t)(by + y0 + i)*DMODEL + bx + x];
        __syncthreads();
        #pragma unroll
        for (int i = 0; i < 32; i += 4)
            d[(size_t)(bx + y0 + i)*DMODEL + by + x] = __float2half_rn(sh[x*33 + y0+i]);
    } else if (bid < PM_BIAS) {
        int t = bid - PM_HT;
        int z = t >> 4, blk = t & 15;
        const float* bin = (z==0) ? bq : (z==1) ? bk : bv;
        const float* W = inw + (size_t)z*DMODEL*DMODEL;
        const float* ab = inb + z*DMODEL;
        float* outp = (z==0) ? bq2 : (z==1) ? bk2 : bv2;
        int jj = tid & 31;
        int r = tid >> 5;
        int j = blk*32 + jj;
        float a = 0.f;
        #pragma unroll 8
        for (int i = r*128; i < r*128 + 128; i++)
            a += bin[i]*W[(size_t)i*DMODEL + j];
        sh[r*32 + jj] = a;
        __syncthreads();
        if (r == 0) {
            float s = ab[j];
            #pragma unroll
            for (int k = 0; k < 4; k++) s += sh[k*32 + jj];
            outp[j] = s;
        }
    } else if (bid < PM_CONVW) {
        int t = bid - PM_BIAS;
        #pragma unroll
        for (int i = 0; i < 4; i++) {
            int idx = t*512 + i*128 + tid;
            const float* src; __half* dst; int loc;
            if (idx < 65536)       { src = Wq; dst = Wqh; loc = idx; }
            else if (idx < 163840) { src = Wk; dst = Wkh; loc = idx - 65536; }
            else                   { src = Wv; dst = Wvh; loc = idx - 163840; }
            float4 v = ((const float4*)src)[loc];
            ((__half2*)dst)[loc*2]   = __floats2half2_rn(v.x, v.y);
            ((__half2*)dst)[loc*2+1] = __floats2half2_rn(v.z, v.w);
        }
    } else {
        int t = bid - PM_CONVW;
        int z = t >> 8, rem = t & 255;
        const float* s = inw + (size_t)z*DMODEL*DMODEL;
        __half* d = inwT + (size_t)z*DMODEL*DMODEL;
        int bx = (rem & 15)*32, by = (rem >> 4)*32;
        int x = tid & 31, y0 = tid >> 5;
        #pragma unroll
        for (int i = 0; i < 32; i += 4)
            sh[(y0+i)*33 + x] = s[(size_t)(by + y0 + i)*DMODEL + bx + x];
        __syncthreads();
        #pragma unroll
        for (int i = 0; i < 32; i += 4)
            d[(size_t)(bx + y0 + i)*DMODEL + by + x] = __float2half_rn(sh[x*33 + y0+i]);
    }
}

// ---------------- 3-stage cp.async FP16 GEMM ----------------
// MODE 1: C(fp32) = A@B + bias + DmH(half) ; MODE 2: leaky then += DmH
// MODE 3: C(half) = A@B + bias ; MODE 4: C(half, transposed CT[n*Mstr+m])
#define TSTRH 40
#define STG_B (128*TSTRH*2)
#define GEMM_SMEM (3*2*STG_B)

template<int MODE>
__device__ __forceinline__ void gemm_body(
    const __half* __restrict__ A, const __half* __restrict__ Bt,
    const float* __restrict__ bias, const __half* __restrict__ DmH,
    void* __restrict__ Cv, int N, int K, char* smem, int Mstr, int by)
{
    char* As = smem;
    char* Bs = smem + 3*STG_B;

    int tid = threadIdx.x;
    int warp = tid >> 5, lane = tid & 31;
    int warp_m = warp & 3, warp_n = warp >> 2;
    int p = lane >> 2, q = lane & 3;
    int blockM = by * 128;
    int blockN = blockIdx.x * 128;

    int c0 = tid*2, c1 = c0 + 1;
    int r0c = c0 >> 2, k0c = (c0 & 3)*8;
    int r1c = c1 >> 2, k1c = (c1 & 3)*8;

    const __half* gA0 = A  + (size_t)(blockM + r0c)*K + k0c;
    const __half* gA1 = A  + (size_t)(blockM + r1c)*K + k1c;
    const __half* gB0 = Bt + (size_t)(blockN + r0c)*K + k0c;
    const __half* gB1 = Bt + (size_t)(blockN + r1c)*K + k1c;

    unsigned sa = (unsigned)__cvta_generic_to_shared(As);
    unsigned sb = (unsigned)__cvta_generic_to_shared(Bs);
    unsigned dA0[3], dA1[3], dB0[3], dB1[3];
    #pragma unroll
    for (int s = 0; s < 3; s++) {
        dA0[s] = sa + s*STG_B + (r0c*TSTRH + k0c)*2;
        dA1[s] = sa + s*STG_B + (r1c*TSTRH + k1c)*2;
        dB0[s] = sb + s*STG_B + (r0c*TSTRH + k0c)*2;
        dB1[s] = sb + s*STG_B + (r1c*TSTRH + k1c)*2;
    }

    unsigned aBase = sa + ((warp_m*32 + (lane & 15))*TSTRH + (lane >> 4)*8)*2;
    unsigned bBase = sb + ((warp_n*64 + ((lane >> 4) << 3) + (lane & 7))*TSTRH
                           + ((lane >> 3) & 1)*8)*2;

    float acc[2][8][4];
    #pragma unroll
    for (int mt = 0; mt < 2; mt++)
        #pragma unroll
        for (int nt = 0; nt < 8; nt++)
            #pragma unroll
            for (int i = 0; i < 4; i++) acc[mt][nt][i] = 0.f;

    CP16(dA0[0], gA0); CP16(dA1[0], gA1);
    CP16(dB0[0], gB0); CP16(dB1[0], gB1);
    asm volatile("cp.async.commit_group;");
    CP16(dA0[1], gA0 + 32); CP16(dA1[1], gA1 + 32);
    CP16(dB0[1], gB0 + 32); CP16(dB1[1], gB1 + 32);
    asm volatile("cp.async.commit_group;");

    int nk = K >> 5;
    int sc = 0, sp = 2;
    for (int t = 0; t < nk; t++) {
        asm volatile("cp.async.wait_group 1;");
        __syncthreads();
        if (t + 2 < nk) {
            int kt = (t + 2) << 5;
            CP16(dA0[sp], gA0 + kt); CP16(dA1[sp], gA1 + kt);
            CP16(dB0[sp], gB0 + kt); CP16(dB1[sp], gB1 + kt);
        }
        asm volatile("cp.async.commit_group;");
        unsigned ao = aBase + sc*STG_B;
        unsigned bo = bBase + sc*STG_B;
        #pragma unroll
        for (int kk = 0; kk < 32; kk += 16) {
            unsigned afr[2][4];
            LDSM4(afr[0], ao + kk*2);
            LDSM4(afr[1], ao + (16*TSTRH + kk)*2);
            unsigned bfr[4][4];
            #pragma unroll
            for (int j = 0; j < 4; j++)
                LDSM4(bfr[j], bo + (j*16*TSTRH + kk)*2);
            #pragma unroll
            for (int mt = 0; mt < 2; mt++)
                #pragma unroll
                for (int nt = 0; nt < 8; nt++)
                    mma_f16(acc[mt][nt],
                            afr[mt][0], afr[mt][1], afr[mt][2], afr[mt][3],
                            bfr[nt >> 1][(nt & 1)*2], bfr[nt >> 1][(nt & 1)*2 + 1]);
        }
        sc++; if (sc == 3) sc = 0;
        sp++; if (sp == 3) sp = 0;
    }

    #pragma unroll
    for (int mt = 0; mt < 2; mt++) {
        int r0 = blockM + warp_m*32 + mt*16 + p;
        #pragma unroll
        for (int nt = 0; nt < 8; nt++) {
            int c0c = blockN + warp_n*64 + nt*8 + 2*q;
            float b0 = 0.f, b1 = 0.f;
            if (bias) { b0 = bias[c0c]; b1 = bias[c0c+1]; }
            float v0 = acc[mt][nt][0] + b0;
            float v1 = acc[mt][nt][1] + b1;
            float v2 = acc[mt][nt][2] + b0;
            float v3 = acc[mt][nt][3] + b1;
            if (MODE == 4) {
                __half* Ch = (__half*)Cv;
                Ch[(size_t)(c0c  )*Mstr + r0    ] = __float2half_rn(v0);
                Ch[(size_t)(c0c+1)*Mstr + r0    ] = __float2half_rn(v1);
                Ch[(size_t)(c0c  )*Mstr + r0 + 8] = __float2half_rn(v2);
                Ch[(size_t)(c0c+1)*Mstr + r0 + 8] = __float2half_rn(v3);
            } else {
                size_t o0 = (size_t)r0*N + c0c;
                size_t o1 = (size_t)(r0+8)*N + c0c;
                if (MODE == 3) {
                    __half* Ch = (__half*)Cv;
                    *(__half2*)&Ch[o0] = __floats2half2_rn(v0, v1);
                    *(__half2*)&Ch[o1] = __floats2half2_rn(v2, v3);
                } else {
                    float* C = (float*)Cv;
                    if (MODE == 2) {
                        v0 = (v0 > 0.f) ? v0 : 0.01f*v0;
                        v1 = (v1 > 0.f) ? v1 : 0.01f*v1;
                        v2 = (v2 > 0.f) ? v2 : 0.01f*v2;
                        v3 = (v3 > 0.f) ? v3 : 0.01f*v3;
                    }
                    float2 f0 = __half22float2(*(const __half2*)(DmH + o0));
                    float2 f1 = __half22float2(*(const __half2*)(DmH + o1));
                    v0 += f0.x; v1 += f0.y; v2 += f1.x; v3 += f1.y;
                    *(float2*)(C + o0) = make_float2(v0, v1);
                    *(float2*)(C + o1) = make_float2(v2, v3);
                }
            }
        }
    }
}

template<int MODE>
__global__ __launch_bounds__(256, 2) void gemm_one(
    const __half* __restrict__ A, const __half* __restrict__ Bt,
    const float* __restrict__ bias, const __half* __restrict__ DmH,
    float* __restrict__ C, int N, int K)
{
    extern __shared__ char smem[];
    gemm_body<MODE>(A, Bt, bias, DmH, C, N, K, smem, 0, blockIdx.y);
}

// weight fold: z=0 Wq (M=512), z=1 Wk (M=768), z=2 Wv (M=768); writes CT half
__global__ __launch_bounds__(256, 2) void gemm_fold(
    const __half* __restrict__ Wqh, const __half* __restrict__ Wkh,
    const __half* __restrict__ Wvh, const __half* __restrict__ inwT,
    __half* __restrict__ WqT, __half* __restrict__ WkT, __half* __restrict__ WvT)
{
    extern __shared__ char smem[];
    int z = blockIdx.z;
    int M = (z == 0) ? DMODEL : LATD;
    if ((int)blockIdx.y*128 >= M) return;
    const __half* A = (z==0) ? Wqh : (z==1) ? Wkh : Wvh;
    const __half* Bt = inwT + (size_t)z*DMODEL*DMODEL;
    __half* C = (z==0) ? WqT : (z==1) ? WkT : WvT;
    gemm_body<4>(A, Bt, nullptr, nullptr, C, DMODEL, DMODEL, smem, M, blockIdx.y);
}

// Q + K + V projections in one flattened launch: y 0..123 Q, 124..155 K, 156..187 V
__global__ __launch_bounds__(256, 2) void gemm_all(
    const __half* __restrict__ dense_h, const __half* __restrict__ cond_h,
    const __half* __restrict__ WqT, const __half* __restrict__ WkT,
    const __half* __restrict__ WvT,
    const float* __restrict__ bq2, const float* __restrict__ bk2,
    const float* __restrict__ bv2,
    __half* __restrict__ qh2, __half* __restrict__ kh2, __half* __restrict__ vh2)
{
    extern __shared__ char smem[];
    int y = blockIdx.y;
    if (y < 124)
        gemm_body<3>(dense_h, WqT, bq2, nullptr, (void*)qh2, DMODEL, DMODEL, smem, 0, y);
    else if (y < 156)
        gemm_body<3>(cond_h, WkT, bk2, nullptr, (void*)kh2, DMODEL, LATD, smem, 0, y - 124);
    else
        gemm_body<3>(cond_h, WvT, bv2, nullptr, (void*)vh2, DMODEL, LATD, smem, 0, y - 156);
}

// ---------------- fp16 attention v3: double-buffered K/V/Q across heads ----
#define TB    64
#define QSTR  72
#define KVSTR 72
#define PSTR2 264
#define AK_BYTES (SEQ*KVSTR*2)     // 36864
#define AQ_BYTES (TB*QSTR*2)       // 9216
#define SM_K  0
#define SM_V  (2*AK_BYTES)         // 73728
#define SM_Q  (SM_V + 2*AK_BYTES)  // 147456
#define SM_P  (SM_Q + 2*AQ_BYTES)  // 165888
#define SM_MASK (SM_P + TB*PSTR2*2)// 199680
#define ATT_SMEM (SM_MASK + SEQ*4) // 200704

__global__ __launch_bounds__(512, 1) void attn_f16(
    const __half* __restrict__ qh2, const __half* __restrict__ kh2,
    const __half* __restrict__ vh2, const int* __restrict__ maskp,
    __half* __restrict__ ctx, float* __restrict__ av_out)
{
    extern __shared__ char smc[];
    __half* sP  = (__half*)(smc + SM_P);
    int* sMask  = (int*)(smc + SM_MASK);

    int b = blockIdx.y, lt = blockIdx.x;
    int tid = threadIdx.x;
    int w = tid >> 5, lane = tid & 31;
    int p = lane >> 2, q = lane & 3;

    unsigned sk = (unsigned)__cvta_generic_to_shared(smc + SM_K);
    unsigned sv = (unsigned)__cvta_generic_to_shared(smc + SM_V);
    unsigned sq = (unsigned)__cvta_generic_to_shared(smc + SM_Q);
    unsigned spb = (unsigned)__cvta_generic_to_shared(sP);

    if (tid < SEQ) sMask[tid] = maskp[b*SEQ + tid];

    unsigned aQ = sq + ((lane & 15)*QSTR + (lane >> 4)*8)*2;
    unsigned bK = sk + ((w*16 + ((lane >> 4) << 3) + (lane & 7))*KVSTR
                        + ((lane >> 3) & 1)*8)*2;
    int mtw = w & 3, ng = w >> 2;
    unsigned aP = spb + ((mtw*16 + (lane & 15))*PSTR2 + (lane >> 4)*8)*2;
    unsigned bV = sv + (((lane & 7) + ((lane >> 3) & 1)*8)*KVSTR
                        + ng*16 + (lane >> 4)*8)*2;

    int qrow = tid >> 3, qch = tid & 7;
    int ql = lt*TB + qrow; if (ql > LMAX-1) ql = LMAX-1;

    // ---- prologue: issue head 0 into buf 0 ----
    {
        const __half* kg = kh2 + (size_t)b*SEQ*DMODEL;
        const __half* vg = vh2 + (size_t)b*SEQ*DMODEL;
        #pragma unroll
        for (int i = 0; i < 4; i++) {
            int c = tid + 512*i;
            int s = c >> 3, ch = c & 7;
            CP16(sk + (s*KVSTR + ch*8)*2, kg + (size_t)s*DMODEL + ch*8);
            CP16(sv + (s*KVSTR + ch*8)*2, vg + (size_t)s*DMODEL + ch*8);
        }
        CP16(sq + (qrow*QSTR + qch*8)*2,
             qh2 + (size_t)(b*LMAX + ql)*DMODEL + qch*8);
    }
    asm volatile("cp.async.commit_group;");

    float avacc[4][8];
    #pragma unroll
    for (int rr = 0; rr < 4; rr++)
        #pragma unroll
        for (int jj = 0; jj < 8; jj++) avacc[rr][jj] = 0.f;

    for (int h = 0; h < NH; h++) {
        int buf = h & 1;
        __syncthreads();
        if (h + 1 < NH) {
            int hh = h + 1, ob = buf ^ 1;
            const __half* kg = kh2 + (size_t)b*SEQ*DMODEL + hh*DH;
            const __half* vg = vh2 + (size_t)b*SEQ*DMODEL + hh*DH;
            #pragma unroll
            for (int i = 0; i < 4; i++) {
                int c = tid + 512*i;
                int s = c >> 3, ch = c & 7;
                CP16(sk + ob*AK_BYTES + (s*KVSTR + ch*8)*2, kg + (size_t)s*DMODEL + ch*8);
                CP16(sv + ob*AK_BYTES + (s*KVSTR + ch*8)*2, vg + (size_t)s*DMODEL + ch*8);
            }
            CP16(sq + ob*AQ_BYTES + (qrow*QSTR + qch*8)*2,
                 qh2 + (size_t)(b*LMAX + ql)*DMODEL + hh*DH + qch*8);
        }
        asm volatile("cp.async.commit_group;");
        asm volatile("cp.async.wait_group 1;");
        __syncthreads();

        unsigned aQb = aQ + buf*AQ_BYTES;
        unsigned bKb = bK + buf*AK_BYTES;
        unsigned bVb = bV + buf*AK_BYTES;

        // ---- QK^T ----
        float csc[2][4][4];
        #pragma unroll
        for (int j = 0; j < 2; j++)
            #pragma unroll
            for (int mt = 0; mt < 4; mt++)
                #pragma unroll
                for (int i = 0; i < 4; i++) csc[j][mt][i] = 0.f;
        #pragma unroll
        for (int ks = 0; ks < 4; ks++) {
            int kk = ks*16;
            unsigned bfr[4];
            LDSM4(bfr, bKb + kk*2);
            #pragma unroll
            for (int mt = 0; mt < 4; mt++) {
                unsigned afr[4];
                LDSM4(afr, aQb + (mt*16*QSTR + kk)*2);
                mma_f16(csc[0][mt], afr[0], afr[1], afr[2], afr[3], bfr[0], bfr[1]);
                mma_f16(csc[1][mt], afr[0], afr[1], afr[2], afr[3], bfr[2], bfr[3]);
            }
        }
        #pragma unroll
        for (int j = 0; j < 2; j++)
            #pragma unroll
            for (int mt = 0; mt < 4; mt++) {
                int row = mt*16 + p;
                int col = (2*w + j)*8 + 2*q;
                *(__half2*)&sP[row*PSTR2 + col]     = __floats2half2_rn(csc[j][mt][0], csc[j][mt][1]);
                *(__half2*)&sP[(row+8)*PSTR2 + col] = __floats2half2_rn(csc[j][mt][2], csc[j][mt][3]);
            }
        __syncthreads();
        // ---- softmax ----
        #pragma unroll
        for (int rr = 0; rr < 4; rr++) {
            int row = 4*w + rr;
            float v[8];
            float m = -1e30f;
            #pragma unroll
            for (int jj = 0; jj < 8; jj++) {
                int s = lane + 32*jj;
                float x = sMask[s] ? -1e30f : __half2float(sP[row*PSTR2 + s])*0.125f;
                v[jj] = x;
                m = fmaxf(m, x);
            }
            #pragma unroll
            for (int o = 16; o > 0; o >>= 1) m = fmaxf(m, __shfl_xor_sync(0xffffffffu, m, o));
            float sum = 0.f;
            #pragma unroll
            for (int jj = 0; jj < 8; jj++) { v[jj] = __expf(v[jj] - m); sum += v[jj]; }
            #pragma unroll
            for (int o = 16; o > 0; o >>= 1) sum += __shfl_xor_sync(0xffffffffu, sum, o);
            float inv = 1.f/sum;
            #pragma unroll
            for (int jj = 0; jj < 8; jj++) {
                float pp = v[jj]*inv;
                avacc[rr][jj] += pp;
                sP[row*PSTR2 + lane + 32*jj] = __float2half_rn(pp);
            }
        }
        __syncthreads();
        // ---- P@V ----
        float cct[2][4];
        #pragma unroll
        for (int j = 0; j < 2; j++)
            #pragma unroll
            for (int i = 0; i < 4; i++) cct[j][i] = 0.f;
        #pragma unroll 4
        for (int ks = 0; ks < 16; ks++) {
            int kk = ks*16;
            unsigned afr[4], bfr[4];
            LDSM4(afr, aP + kk*2);
            LDSM4T(bfr, bVb + kk*KVSTR*2);
            mma_f16(cct[0], afr[0], afr[1], afr[2], afr[3], bfr[0], bfr[1]);
            mma_f16(cct[1], afr[0], afr[1], afr[2], afr[3], bfr[2], bfr[3]);
        }
        #pragma unroll
        for (int j = 0; j < 2; j++) {
            int dc = h*DH + ng*16 + j*8 + 2*q;
            int l0 = lt*TB + mtw*16 + p;
            if (l0 < LMAX)
                *(__half2*)&ctx[((size_t)(b*LMAX) + l0)*DMODEL + dc] =
                    __floats2half2_rn(cct[j][0], cct[j][1]);
            int l1 = l0 + 8;
            if (l1 < LMAX)
                *(__half2*)&ctx[((size_t)(b*LMAX) + l1)*DMODEL + dc] =
                    __floats2half2_rn(cct[j][2], cct[j][3]);
        }
    }

    // ---- head-averaged attention ----
    #pragma unroll
    for (int rr = 0; rr < 4; rr++) {
        int l = lt*TB + 4*w + rr;
        if (l < LMAX) {
            #pragma unroll
            for (int jj = 0; jj < 8; jj++)
                av_out[((size_t)(b*LMAX) + l)*SEQ + lane + 32*jj] = avacc[rr][jj]*0.125f;
        }
    }
}

// ---------------- LN1: half operand only ----------
__global__ __launch_bounds__(128) void ln_half(
    const float* __restrict__ x, const float* __restrict__ g,
    const float* __restrict__ bb, __half* __restrict__ yh)
{
    __shared__ float ws[4], wss[4];
    int r = blockIdx.x;
    int tid = threadIdx.x;
    const float4* xr = (const float4*)(x + (size_t)r*DMODEL);
    float4 v = xr[tid];
    float s  = v.x + v.y + v.z + v.w;
    float ss = v.x*v.x + v.y*v.y + v.z*v.z + v.w*v.w;
    #pragma unroll
    for (int o = 16; o > 0; o >>= 1) {
        s  += __shfl_xor_sync(0xffffffffu, s,  o);
        ss += __shfl_xor_sync(0xffffffffu, ss, o);
    }
    int warp = tid >> 5, lane = tid & 31;
    if (lane == 0) { ws[warp] = s; wss[warp] = ss; }
    __syncthreads();
    float S  = ws[0] + ws[1] + ws[2] + ws[3];
    float SS = wss[0] + wss[1] + wss[2] + wss[3];
    float mean = S * (1.f/DMODEL);
    float var  = SS * (1.f/DMODEL) - mean*mean;
    float rstd = rsqrtf(var + 1e-5f);
    float4 gg = ((const float4*)g)[tid];
    float4 b4 = ((const float4*)bb)[tid];
    float4 o4;
    o4.x = (v.x - mean)*rstd*gg.x + b4.x;
    o4.y = (v.y - mean)*rstd*gg.y + b4.y;
    o4.z = (v.z - mean)*rstd*gg.z + b4.z;
    o4.w = (v.w - mean)*rstd*gg.w + b4.w;
    __half2* yhp = (__half2*)(yh + (size_t)r*DMODEL);
    yhp[tid*2]   = __floats2half2_rn(o4.x, o4.y);
    yhp[tid*2+1] = __floats2half2_rn(o4.z, o4.w);
}

// ---------------- fused LN2 + ragged gather ----------
__global__ __launch_bounds__(128) void ln_gather(
    const float* __restrict__ x, const int* __restrict__ gb,
    const float* __restrict__ g, const float* __restrict__ bb,
    float* __restrict__ out)
{
    __shared__ float ws[4], wss[4];
    int i = blockIdx.x;
    int b = gb[i];
    int pp = i - lower_bound_gb(gb, b);
    size_t row = (size_t)b*LMAX + pp;
    int tid = threadIdx.x;
    float4 v = ((const float4*)(x + row*DMODEL))[tid];
    float s  = v.x + v.y + v.z + v.w;
    float ss = v.x*v.x + v.y*v.y + v.z*v.z + v.w*v.w;
    #pragma unroll
    for (int o = 16; o > 0; o >>= 1) {
        s  += __shfl_xor_sync(0xffffffffu, s,  o);
        ss += __shfl_xor_sync(0xffffffffu, ss, o);
    }
    int warp = tid >> 5, lane = tid & 31;
    if (lane == 0) { ws[warp] = s; wss[warp] = ss; }
    __syncthreads();
    float S  = ws[0] + ws[1] + ws[2] + ws[3];
    float SS = wss[0] + wss[1] + wss[2] + wss[3];
    float mean = S * (1.f/DMODEL);
    float var  = SS * (1.f/DMODEL) - mean*mean;
    float rstd = rsqrtf(var + 1e-5f);
    float4 gg = ((const float4*)g)[tid];
    float4 b4 = ((const float4*)bb)[tid];
    float4 o4;
    o4.x = (v.x - mean)*rstd*gg.x + b4.x;
    o4.y = (v.y - mean)*rstd*gg.y + b4.y;
    o4.z = (v.z - mean)*rstd*gg.z + b4.z;
    o4.w = (v.w - mean)*rstd*gg.w + b4.w;
    ((float4*)(out + (size_t)i*DMODEL))[tid] = o4;
}

// ---------------- launch ----------------
extern "C" void kernel_launch(void* const* d_in, const int* in_sizes, int n_in,
                              void* d_out, int out_size)
{
    int off = (n_in >= 22) ? 0 : 2;
    const float* nodes  = (const float*)d_in[0];
    const int*   gb     = (const int*)  d_in[1];
    const float* cond   = (const float*)d_in[2];
    const int*   maskp  = (const int*)  d_in[3];
    const float* Wq     = (const float*)d_in[6-off];
    const float* bq     = (const float*)d_in[7-off];
    const float* Wk     = (const float*)d_in[8-off];
    const float* bk     = (const float*)d_in[9-off];
    const float* Wv     = (const float*)d_in[10-off];
    const float* bv     = (const float*)d_in[11-off];
    const float* in_w   = (const float*)d_in[12-off];
    const float* in_b   = (const float*)d_in[13-off];
    const float* Wo     = (const float*)d_in[14-off];
    const float* bo     = (const float*)d_in[15-off];
    const float* ln1g   = (const float*)d_in[16-off];
    const float* ln1b   = (const float*)d_in[17-off];
    const float* W1     = (const float*)d_in[18-off];
    const float* b1     = (const float*)d_in[19-off];
    const float* ln2g   = (const float*)d_in[20-off];
    const float* ln2b   = (const float*)d_in[21-off];
    float* out = (float*)d_out;
    float* av_out = out + (size_t)NN*DMODEL;

    float *p_y, *p_h, *p_bq2, *p_bk2, *p_bv2;
    __half *p_dense_h, *p_qh2, *p_kh2, *p_vh2, *p_ctx, *p_x1h;
    __half *p_WqT, *p_WkT, *p_WvT, *p_WoT, *p_W1T, *p_cond;
    __half *p_Wqh, *p_Wkh, *p_Wvh, *p_inwT;
    cudaGetSymbolAddress((void**)&p_dense_h, g_dense_h);
    cudaGetSymbolAddress((void**)&p_qh2, g_qh2);
    cudaGetSymbolAddress((void**)&p_kh2, g_kh2);
    cudaGetSymbolAddress((void**)&p_vh2, g_vh2);
    cudaGetSymbolAddress((void**)&p_ctx, g_ctx);
    cudaGetSymbolAddress((void**)&p_y, g_y);
    cudaGetSymbolAddress((void**)&p_x1h, g_x1h);
    cudaGetSymbolAddress((void**)&p_h, g_h);
    cudaGetSymbolAddress((void**)&p_WqT, g_WqT);
    cudaGetSymbolAddress((void**)&p_WkT, g_WkT);
    cudaGetSymbolAddress((void**)&p_WvT, g_WvT);
    cudaGetSymbolAddress((void**)&p_WoT, g_WoT);
    cudaGetSymbolAddress((void**)&p_W1T, g_W1T);
    cudaGetSymbolAddress((void**)&p_cond, g_cond);
    cudaGetSymbolAddress((void**)&p_Wqh, g_Wqh);
    cudaGetSymbolAddress((void**)&p_Wkh, g_Wkh);
    cudaGetSymbolAddress((void**)&p_Wvh, g_Wvh);
    cudaGetSymbolAddress((void**)&p_inwT, g_inwT);
    cudaGetSymbolAddress((void**)&p_bq2, g_bq2);
    cudaGetSymbolAddress((void**)&p_bk2, g_bk2);
    cudaGetSymbolAddress((void**)&p_bv2, g_bv2);

    cudaFuncSetAttribute(gemm_one<1>, cudaFuncAttributeMaxDynamicSharedMemorySize, GEMM_SMEM);
    cudaFuncSetAttribute(gemm_one<2>, cudaFuncAttributeMaxDynamicSharedMemorySize, GEMM_SMEM);
    cudaFuncSetAttribute(gemm_all,    cudaFuncAttributeMaxDynamicSharedMemorySize, GEMM_SMEM);
    cudaFuncSetAttribute(gemm_fold,   cudaFuncAttributeMaxDynamicSharedMemorySize, GEMM_SMEM);
    cudaFuncSetAttribute(attn_f16,    cudaFuncAttributeMaxDynamicSharedMemorySize, ATT_SMEM);

    // 1) mega prologue
    prologue_misc<<<PM_TINW, 128>>>(nodes, gb, cond, Wo, W1, Wq, Wk, Wv,
                                    bq, bk, bv, in_w, in_b,
                                    p_dense_h, p_cond, p_WoT, p_W1T,
                                    p_Wqh, p_Wkh, p_Wvh, p_inwT,
                                    p_bq2, p_bk2, p_bv2);
    // 2) fold projection weights
    gemm_fold<<<dim3(4,6,3), 256, GEMM_SMEM>>>(p_Wqh, p_Wkh, p_Wvh, p_inwT,
                                               p_WqT, p_WkT, p_WvT);
    // 3) Q + K + V projections (flattened grid)
    gemm_all<<<dim3(4,188), 256, GEMM_SMEM>>>(p_dense_h, p_cond, p_WqT, p_WkT, p_WvT,
                                              p_bq2, p_bk2, p_bv2, p_qh2, p_kh2, p_vh2);
    // 4) fp16 attention v3  <-- profiled launch
    attn_f16<<<dim3(16, BGR), 512, ATT_SMEM>>>(p_qh2, p_kh2, p_vh2, maskp, p_ctx, av_out);
    // 5) out proj + residual (half residual)
    gemm_one<1><<<dim3(4,124), 256, GEMM_SMEM>>>(p_ctx, p_WoT, bo, p_dense_h, p_y, DMODEL, DMODEL);
    // 6) LN1 -> half operand/residual
    ln_half<<<ROWS_Q, 128>>>(p_y, ln1g, ln1b, p_x1h);
    // 7) FFN + leaky + residual (half residual)
    gemm_one<2><<<dim3(4,124), 256, GEMM_SMEM>>>(p_x1h, p_W1T, b1, p_x1h, p_h, DMODEL, DMODEL);
    // 8) LN2 + ragged gather
    ln_gather<<<NN, 128>>>(p_h, gb, ln2g, ln2b, out);
}